// round 2
// baseline (speedup 1.0000x reference)
#include <cuda_runtime.h>

#define B_  4
#define L_  1024
#define D_  1024
#define H_  16
#define HD  64
#define NBH (B_ * H_)   // 64

// Scratch (static device globals — no allocation allowed)
__device__ float g_q[NBH * L_ * HD];
__device__ float g_k[NBH * L_ * HD];
__device__ float g_v[NBH * L_ * HD];
__device__ float g_att[B_ * L_ * D_];

// ---------------------------------------------------------------------------
// GEMM NT: C[M,N] = A[M,K] * W[N,K]^T   (both operands K-major / row-major)
// MODE 0: A = x, W = w_qkv, scatter epilogue into g_q/g_k/g_v ([B,H,L,64])
// MODE 1: A = g_att (internal), W = w_out, plain epilogue to C ([4096,1024])
// Tile 64x64, BK=16, 256 threads, 4x4 microtile.
// ---------------------------------------------------------------------------
template <int MODE>
__global__ void __launch_bounds__(256) gemm_nt(const float* __restrict__ Ain,
                                               const float* __restrict__ W,
                                               float* __restrict__ C,
                                               int K) {
    __shared__ float As[16][68];
    __shared__ float Bs[16][68];

    const float* A = (MODE == 1) ? (const float*)g_att : Ain;

    int t  = threadIdx.x;
    int tx = t & 15, ty = t >> 4;
    int m0 = blockIdx.y * 64;
    int n0 = blockIdx.x * 64;
    int lr = t >> 2;            // 0..63 (tile row for loading)
    int lq = (t & 3) << 2;      // 0,4,8,12 (k quad)

    const float* aptr = A + (size_t)(m0 + lr) * K + lq;
    const float* wptr = W + (size_t)(n0 + lr) * K + lq;

    float acc[4][4];
#pragma unroll
    for (int r = 0; r < 4; r++)
#pragma unroll
        for (int c = 0; c < 4; c++) acc[r][c] = 0.f;

    for (int k0 = 0; k0 < K; k0 += 16) {
        float4 av = *(const float4*)(aptr + k0);
        float4 bv = *(const float4*)(wptr + k0);
        __syncthreads();
        As[lq + 0][lr] = av.x; As[lq + 1][lr] = av.y;
        As[lq + 2][lr] = av.z; As[lq + 3][lr] = av.w;
        Bs[lq + 0][lr] = bv.x; Bs[lq + 1][lr] = bv.y;
        Bs[lq + 2][lr] = bv.z; Bs[lq + 3][lr] = bv.w;
        __syncthreads();
#pragma unroll
        for (int kk = 0; kk < 16; kk++) {
            float4 a = *(const float4*)&As[kk][ty * 4];
            float4 b = *(const float4*)&Bs[kk][tx * 4];
            acc[0][0] += a.x * b.x; acc[0][1] += a.x * b.y;
            acc[0][2] += a.x * b.z; acc[0][3] += a.x * b.w;
            acc[1][0] += a.y * b.x; acc[1][1] += a.y * b.y;
            acc[1][2] += a.y * b.z; acc[1][3] += a.y * b.w;
            acc[2][0] += a.z * b.x; acc[2][1] += a.z * b.y;
            acc[2][2] += a.z * b.z; acc[2][3] += a.z * b.w;
            acc[3][0] += a.w * b.x; acc[3][1] += a.w * b.y;
            acc[3][2] += a.w * b.z; acc[3][3] += a.w * b.w;
        }
    }

    if (MODE == 0) {
        // n0 is a multiple of 64 -> whole tile shares s (q/k/v) and head h
        int s = n0 >> 10;
        int h = (n0 >> 6) & 15;
        float* dst = (s == 0) ? g_q : (s == 1) ? g_k : g_v;
#pragma unroll
        for (int r = 0; r < 4; r++) {
            int n = m0 + ty * 4 + r;          // row of x = b*L + l
            int b = n >> 10, l = n & 1023;
            float4 v = make_float4(acc[r][0], acc[r][1], acc[r][2], acc[r][3]);
            *(float4*)&dst[((size_t)(b * H_ + h) * L_ + l) * HD + tx * 4] = v;
        }
    } else {
#pragma unroll
        for (int r = 0; r < 4; r++) {
            float4 v = make_float4(acc[r][0], acc[r][1], acc[r][2], acc[r][3]);
            *(float4*)&C[(size_t)(m0 + ty * 4 + r) * 1024 + n0 + tx * 4] = v;
        }
    }
}

// ---------------------------------------------------------------------------
// Attention: one block = one (b,h) and a 64-query tile.
// Keys live in [qt0-256, qt0+63] -> 5 aligned key blocks of 64.
// smem: Qs[d][qi] 64x68 | KV[..] 64x68 (Rs / Ks / Vs reused) |
//       qE[qi][r] 64x68 (r in 0..64) | S[qi][col] 64x324 (320 used)
// ---------------------------------------------------------------------------
#define SW 324
#define SMEM_FLOATS (4352 * 3 + 64 * SW)   // 33792 floats = 135168 bytes

__global__ void __launch_bounds__(256) attn_kernel(const float* __restrict__ rel_emb) {
    extern __shared__ float sm[];
    float* Qs = sm;            // [64][68], d-major
    float* KV = sm + 4352;     // [64][68]
    float* qE = sm + 8704;     // [64][68], qi-major
    float* S  = sm + 13056;    // [64][SW]

    int t  = threadIdx.x;
    int tx = t & 15, ty = t >> 4;
    int qt0 = blockIdx.x * 64;
    int bh  = blockIdx.y;      // b*16 + h
    const float* qb = g_q + (size_t)bh * L_ * HD;
    const float* kb = g_k + (size_t)bh * L_ * HD;
    const float* vb = g_v + (size_t)bh * L_ * HD;
    int lr = t >> 2, lq = (t & 3) << 2;

    // Load Q tile transposed: Qs[d][qi]  (FULL 64x64: 4 d-quads per thread)
#pragma unroll
    for (int dq = lq; dq < 64; dq += 16) {
        float4 v = *(const float4*)&qb[(qt0 + lr) * HD + dq];
        Qs[(dq + 0) * 68 + lr] = v.x; Qs[(dq + 1) * 68 + lr] = v.y;
        Qs[(dq + 2) * 68 + lr] = v.z; Qs[(dq + 3) * 68 + lr] = v.w;
    }
    // Load rel_emb rows 0..64 transposed into KV: Rs[d][r]
    for (int idx = t; idx < 65 * 16; idx += 256) {
        int r = idx >> 4, quad = (idx & 15) << 2;
        float4 v = *(const float4*)&rel_emb[r * HD + quad];
        KV[(quad + 0) * 68 + r] = v.x; KV[(quad + 1) * 68 + r] = v.y;
        KV[(quad + 2) * 68 + r] = v.z; KV[(quad + 3) * 68 + r] = v.w;
    }
    __syncthreads();

    // qE[qi][r] = sum_d Qs[d][qi] * Rs[d][r],  r in [0,64]
    {
        int qi = t & 63;
        int rq = (t >> 6) << 2;           // 0,4,8,12
#pragma unroll
        for (int pass = 0; pass < 5; pass++) {
            int r0 = pass * 16 + rq;
            if (r0 < 65) {
                float a0 = 0, a1 = 0, a2 = 0, a3 = 0;
#pragma unroll 8
                for (int d = 0; d < 64; d++) {
                    float  qv = Qs[d * 68 + qi];
                    float4 rv = *(const float4*)&KV[d * 68 + r0];
                    a0 += qv * rv.x; a1 += qv * rv.y;
                    a2 += qv * rv.z; a3 += qv * rv.w;
                }
                qE[qi * 68 + r0] = a0;
                if (r0 + 1 < 65) qE[qi * 68 + r0 + 1] = a1;
                if (r0 + 2 < 65) qE[qi * 68 + r0 + 2] = a2;
                if (r0 + 3 < 65) qE[qi * 68 + r0 + 3] = a3;
            }
        }
    }

    // Scores: 5 key blocks
    for (int kbk = 0; kbk < 5; kbk++) {
        int kb0 = qt0 - 256 + kbk * 64;
        if (kb0 >= 0) {
            __syncthreads();   // previous KV consumers done (uniform branch)
#pragma unroll
            for (int dq = lq; dq < 64; dq += 16) {
                float4 v = *(const float4*)&kb[(kb0 + lr) * HD + dq];
                KV[(dq + 0) * 68 + lr] = v.x; KV[(dq + 1) * 68 + lr] = v.y;
                KV[(dq + 2) * 68 + lr] = v.z; KV[(dq + 3) * 68 + lr] = v.w;
            }
            __syncthreads();
            float s4[4][4];
#pragma unroll
            for (int r = 0; r < 4; r++)
#pragma unroll
                for (int c = 0; c < 4; c++) s4[r][c] = 0.f;
#pragma unroll 16
            for (int d = 0; d < 64; d++) {
                float4 a = *(const float4*)&Qs[d * 68 + ty * 4];
                float4 b = *(const float4*)&KV[d * 68 + tx * 4];
                s4[0][0] += a.x * b.x; s4[0][1] += a.x * b.y;
                s4[0][2] += a.x * b.z; s4[0][3] += a.x * b.w;
                s4[1][0] += a.y * b.x; s4[1][1] += a.y * b.y;
                s4[1][2] += a.y * b.z; s4[1][3] += a.y * b.w;
                s4[2][0] += a.z * b.x; s4[2][1] += a.z * b.y;
                s4[2][2] += a.z * b.z; s4[2][3] += a.z * b.w;
                s4[3][0] += a.w * b.x; s4[3][1] += a.w * b.y;
                s4[3][2] += a.w * b.z; s4[3][3] += a.w * b.w;
            }
#pragma unroll
            for (int r = 0; r < 4; r++)
#pragma unroll
                for (int c = 0; c < 4; c++) {
                    int i = qt0 + ty * 4 + r;
                    int j = kb0 + tx * 4 + c;
                    float val;
                    if (j > i || (i - j) >= 256) {
                        val = -1e30f;
                    } else {
                        int rel = j - i + 64;      // in [-192, 64]
                        if (rel < 0) rel = 0;      // clip to 0..64
                        val = (s4[r][c] + qE[(ty * 4 + r) * 68 + rel]) * 0.125f;
                    }
                    S[(ty * 4 + r) * SW + kbk * 64 + tx * 4 + c] = val;
                }
        } else {
#pragma unroll
            for (int r = 0; r < 4; r++)
#pragma unroll
                for (int c = 0; c < 4; c++)
                    S[(ty * 4 + r) * SW + kbk * 64 + tx * 4 + c] = -1e30f;
        }
    }
    __syncthreads();

    // Row softmax over 320 cols; warp handles 8 rows
    {
        int warp = t >> 5, lane = t & 31;
        for (int r = warp * 8; r < warp * 8 + 8; r++) {
            float mx = -1e30f;
            for (int c = lane; c < 320; c += 32) mx = fmaxf(mx, S[r * SW + c]);
#pragma unroll
            for (int o = 16; o > 0; o >>= 1)
                mx = fmaxf(mx, __shfl_xor_sync(0xffffffffu, mx, o));
            float sum = 0.f;
            for (int c = lane; c < 320; c += 32) {
                float p = __expf(S[r * SW + c] - mx);
                S[r * SW + c] = p;
                sum += p;
            }
#pragma unroll
            for (int o = 16; o > 0; o >>= 1)
                sum += __shfl_xor_sync(0xffffffffu, sum, o);
            float inv = 1.f / sum;
            for (int c = lane; c < 320; c += 32) S[r * SW + c] *= inv;
        }
    }
    __syncthreads();

    // AV: out[qi][d] = sum_j P[qi][j] * V[j][d]
    float o4[4][4];
#pragma unroll
    for (int r = 0; r < 4; r++)
#pragma unroll
        for (int c = 0; c < 4; c++) o4[r][c] = 0.f;

    for (int kbk = 0; kbk < 5; kbk++) {
        int kb0 = qt0 - 256 + kbk * 64;
        if (kb0 < 0) continue;           // uniform across block
        __syncthreads();
#pragma unroll
        for (int dq = lq; dq < 64; dq += 16) {
            float4 v = *(const float4*)&vb[(kb0 + lr) * HD + dq];
            *(float4*)&KV[lr * 68 + dq] = v;   // Vs[j][d], natural layout
        }
        __syncthreads();
#pragma unroll 8
        for (int j = 0; j < 64; j++) {
            float4 vv = *(const float4*)&KV[j * 68 + tx * 4];
            float p0 = S[(ty * 4 + 0) * SW + kbk * 64 + j];
            float p1 = S[(ty * 4 + 1) * SW + kbk * 64 + j];
            float p2 = S[(ty * 4 + 2) * SW + kbk * 64 + j];
            float p3 = S[(ty * 4 + 3) * SW + kbk * 64 + j];
            o4[0][0] += p0 * vv.x; o4[0][1] += p0 * vv.y;
            o4[0][2] += p0 * vv.z; o4[0][3] += p0 * vv.w;
            o4[1][0] += p1 * vv.x; o4[1][1] += p1 * vv.y;
            o4[1][2] += p1 * vv.z; o4[1][3] += p1 * vv.w;
            o4[2][0] += p2 * vv.x; o4[2][1] += p2 * vv.y;
            o4[2][2] += p2 * vv.z; o4[2][3] += p2 * vv.w;
            o4[3][0] += p3 * vv.x; o4[3][1] += p3 * vv.y;
            o4[3][2] += p3 * vv.z; o4[3][3] += p3 * vv.w;
        }
    }

    // Write attention output in [B, L, H*hd] layout for the final GEMM
    int b = bh >> 4, h = bh & 15;
#pragma unroll
    for (int r = 0; r < 4; r++) {
        int i = qt0 + ty * 4 + r;
        float4 v = make_float4(o4[r][0], o4[r][1], o4[r][2], o4[r][3]);
        *(float4*)&g_att[((size_t)(b * L_ + i) * H_ + h) * HD + tx * 4] = v;
    }
}

// ---------------------------------------------------------------------------
extern "C" void kernel_launch(void* const* d_in, const int* in_sizes, int n_in,
                              void* d_out, int out_size) {
    const float* x       = (const float*)d_in[0];   // [4,1024,1024]
    const float* w_qkv   = (const float*)d_in[1];   // [3072,1024]
    const float* w_out   = (const float*)d_in[2];   // [1024,1024]
    const float* rel_emb = (const float*)d_in[3];   // [129,64]
    float* out = (float*)d_out;                     // [4,1024,1024]

    (void)in_sizes; (void)n_in; (void)out_size;

    const int smem_bytes = SMEM_FLOATS * (int)sizeof(float);   // 135168
    cudaFuncSetAttribute(attn_kernel,
                         cudaFuncAttributeMaxDynamicSharedMemorySize, smem_bytes);

    // 1) QKV projection (scatter into [B,H,L,64] q/k/v)
    gemm_nt<0><<<dim3(3072 / 64, 4096 / 64), 256>>>(x, w_qkv, nullptr, 1024);

    // 2) Relative attention
    attn_kernel<<<dim3(L_ / 64, NBH), 256, smem_bytes>>>(rel_emb);

    // 3) Output projection
    gemm_nt<1><<<dim3(1024 / 64, 4096 / 64), 256>>>(nullptr, w_out, out, 1024);
}

// round 4
// speedup vs baseline: 2.2397x; 2.2397x over previous
#include <cuda_runtime.h>
#include <cuda_bf16.h>
#include <cstdint>

#define B_  4
#define L_  1024
#define D_  1024
#define H_  16
#define HD  64
#define NBH (B_ * H_)   // 64

// ---------------------------------------------------------------------------
// Static device scratch (no allocation allowed)
// ---------------------------------------------------------------------------
__device__ float g_q[NBH * L_ * HD];
__device__ float g_k[NBH * L_ * HD];
__device__ float g_v[NBH * L_ * HD];
__device__ float g_att[B_ * L_ * D_];

__device__ __nv_bfloat16 g_x_hi[B_ * L_ * D_];
__device__ __nv_bfloat16 g_x_lo[B_ * L_ * D_];
__device__ __nv_bfloat16 g_wqkv_hi[3 * D_ * D_];
__device__ __nv_bfloat16 g_wqkv_lo[3 * D_ * D_];
__device__ __nv_bfloat16 g_wout_hi[D_ * D_];
__device__ __nv_bfloat16 g_wout_lo[D_ * D_];
__device__ __nv_bfloat16 g_att_hi[B_ * L_ * D_];
__device__ __nv_bfloat16 g_att_lo[B_ * L_ * D_];

// ---------------------------------------------------------------------------
// PTX helpers (base ISA only — NO sm_100a features)
// ---------------------------------------------------------------------------
__device__ __forceinline__ uint32_t smem_u32(const void* p) {
    uint32_t a;
    asm("{ .reg .u64 t; cvta.to.shared.u64 t, %1; cvt.u32.u64 %0, t; }" : "=r"(a) : "l"(p));
    return a;
}

#define CP_ASYNC16(dst, src) \
    asm volatile("cp.async.cg.shared.global [%0], [%1], 16;" :: "r"(dst), "l"(src))
#define CP_COMMIT() asm volatile("cp.async.commit_group;" ::: "memory")
#define CP_WAIT2()  asm volatile("cp.async.wait_group 2;" ::: "memory")

__device__ __forceinline__ void ldsm_x4(uint32_t& r0, uint32_t& r1, uint32_t& r2,
                                        uint32_t& r3, uint32_t addr) {
    asm volatile("ldmatrix.sync.aligned.m8n8.x4.shared.b16 {%0,%1,%2,%3}, [%4];"
                 : "=r"(r0), "=r"(r1), "=r"(r2), "=r"(r3) : "r"(addr));
}

__device__ __forceinline__ void mma_bf16(float* d, const uint32_t* a,
                                         uint32_t b0, uint32_t b1) {
    asm volatile(
        "mma.sync.aligned.m16n8k16.row.col.f32.bf16.bf16.f32 "
        "{%0,%1,%2,%3}, {%4,%5,%6,%7}, {%8,%9}, {%0,%1,%2,%3};"
        : "+f"(d[0]), "+f"(d[1]), "+f"(d[2]), "+f"(d[3])
        : "r"(a[0]), "r"(a[1]), "r"(a[2]), "r"(a[3]), "r"(b0), "r"(b1));
}

// ---------------------------------------------------------------------------
// fp32 -> bf16 hi/lo split conversion.  W: 0=x, 1=wqkv, 2=wout, 3=att
// ---------------------------------------------------------------------------
template <int W>
__global__ void __launch_bounds__(256) cvt_split(const float* __restrict__ src_in, int n4) {
    __nv_bfloat16* hi = (W == 0) ? g_x_hi : (W == 1) ? g_wqkv_hi : (W == 2) ? g_wout_hi : g_att_hi;
    __nv_bfloat16* lo = (W == 0) ? g_x_lo : (W == 1) ? g_wqkv_lo : (W == 2) ? g_wout_lo : g_att_lo;
    const float* src = (W == 3) ? (const float*)g_att : src_in;

    int i = blockIdx.x * 256 + threadIdx.x;
    if (i >= n4) return;
    float4 v = ((const float4*)src)[i];
    __nv_bfloat16 h0 = __float2bfloat16(v.x), h1 = __float2bfloat16(v.y);
    __nv_bfloat16 h2 = __float2bfloat16(v.z), h3 = __float2bfloat16(v.w);
    __nv_bfloat16 l0 = __float2bfloat16(v.x - __bfloat162float(h0));
    __nv_bfloat16 l1 = __float2bfloat16(v.y - __bfloat162float(h1));
    __nv_bfloat16 l2 = __float2bfloat16(v.z - __bfloat162float(h2));
    __nv_bfloat16 l3 = __float2bfloat16(v.w - __bfloat162float(h3));
    ((__nv_bfloat162*)hi)[2 * i]     = __nv_bfloat162(h0, h1);
    ((__nv_bfloat162*)hi)[2 * i + 1] = __nv_bfloat162(h2, h3);
    ((__nv_bfloat162*)lo)[2 * i]     = __nv_bfloat162(l0, l1);
    ((__nv_bfloat162*)lo)[2 * i + 1] = __nv_bfloat162(l2, l3);
}

// ---------------------------------------------------------------------------
// Warp-mma split-bf16 GEMM NT: C[M,N] = A[M,K]*B[N,K]^T, fp32-accurate.
// CTA tile 128x128, K staged by 64, 3-stage cp.async pipeline.
// 8 warps: 2(m) x 4(n); warp tile 64x32; mma.sync m16n8k16 bf16.
// smem tiles per stage: Ah | Al | Bh | Bl, each 128x64 bf16 (16KB), SW128.
// MODE 0: A=x, B=w_qkv -> scatter g_q/g_k/g_v.  MODE 1: A=att, B=w_out -> C.
// ---------------------------------------------------------------------------
#define TILE_B  16384
#define STAGE_B (4 * TILE_B)     // 64 KB
#define NSTAGE  3
#define TC_SMEM (NSTAGE * STAGE_B)   // 192 KB

template <int MODE>
__global__ void __launch_bounds__(256, 1) tc_gemm(float* __restrict__ C) {
    extern __shared__ char smc[];
    uint32_t sb = smem_u32(smc);

    const __nv_bfloat16* Ah = (MODE == 0) ? g_x_hi : g_att_hi;
    const __nv_bfloat16* Al = (MODE == 0) ? g_x_lo : g_att_lo;
    const __nv_bfloat16* Bhp = (MODE == 0) ? g_wqkv_hi : g_wout_hi;
    const __nv_bfloat16* Blp = (MODE == 0) ? g_wqkv_lo : g_wout_lo;

    const int t = threadIdx.x, lane = t & 31, warp = t >> 5;
    const int wm = warp & 1, wn = warp >> 1;
    const int m0 = blockIdx.y * 128, n0 = blockIdx.x * 128;

    // --- global->smem load mapping (4 x 16B chunks per thread per tile) ---
    uint32_t ld_sm[4];
    size_t   ld_ga[4], ld_gb[4];
#pragma unroll
    for (int j = 0; j < 4; j++) {
        int c = t + 256 * j;
        int row = c >> 3, ch = c & 7;
        ld_sm[j] = (uint32_t)(row * 128 + ((ch ^ (row & 7)) << 4));
        ld_ga[j] = (size_t)(m0 + row) * 1024 + ch * 8;
        ld_gb[j] = (size_t)(n0 + row) * 1024 + ch * 8;
    }

    float acc[4][4][4];
#pragma unroll
    for (int mi = 0; mi < 4; mi++)
#pragma unroll
        for (int ni = 0; ni < 4; ni++)
#pragma unroll
            for (int q = 0; q < 4; q++) acc[mi][ni][q] = 0.f;

    // ldmatrix address components
    const int a_rb = wm * 64 + (lane & 15);
    const int a_cb = (lane >> 4);             // +kk*2
    const int b_rb = wn * 32 + ((lane >> 4) * 8) + (lane & 7);
    const int b_cb = (lane >> 3) & 1;         // +kk*2

#define LOAD_STAGE(it, s) do {                                                  \
    uint32_t base = sb + (s) * STAGE_B;                                         \
    int k0 = (it) * 64;                                                         \
    _Pragma("unroll")                                                           \
    for (int j = 0; j < 4; j++) {                                               \
        CP_ASYNC16(base + 0 * TILE_B + ld_sm[j], Ah  + ld_ga[j] + k0);          \
        CP_ASYNC16(base + 1 * TILE_B + ld_sm[j], Al  + ld_ga[j] + k0);          \
        CP_ASYNC16(base + 2 * TILE_B + ld_sm[j], Bhp + ld_gb[j] + k0);          \
        CP_ASYNC16(base + 3 * TILE_B + ld_sm[j], Blp + ld_gb[j] + k0);          \
    }                                                                           \
    CP_COMMIT();                                                                \
} while (0)

    LOAD_STAGE(0, 0);
    LOAD_STAGE(1, 1);
    LOAD_STAGE(2, 2);

    int s = 0;
    for (int it = 0; it < 16; it++) {
        CP_WAIT2();
        __syncthreads();
        uint32_t base = sb + s * STAGE_B;

#pragma unroll
        for (int kk = 0; kk < 4; kk++) {
            uint32_t ah[4][4], al[4][4];
#pragma unroll
            for (int mi = 0; mi < 4; mi++) {
                int r = a_rb + mi * 16;
                int c = kk * 2 + a_cb;
                uint32_t addr = base + (uint32_t)(r * 128 + ((c ^ (r & 7)) << 4));
                ldsm_x4(ah[mi][0], ah[mi][1], ah[mi][2], ah[mi][3], addr);
                ldsm_x4(al[mi][0], al[mi][1], al[mi][2], al[mi][3], addr + TILE_B);
            }
            uint32_t bh[2][4], bl[2][4];
#pragma unroll
            for (int nh = 0; nh < 2; nh++) {
                int r = b_rb + nh * 16;
                int c = kk * 2 + b_cb;
                uint32_t addr = base + 2 * TILE_B + (uint32_t)(r * 128 + ((c ^ (r & 7)) << 4));
                ldsm_x4(bh[nh][0], bh[nh][1], bh[nh][2], bh[nh][3], addr);
                ldsm_x4(bl[nh][0], bl[nh][1], bl[nh][2], bl[nh][3], addr + TILE_B);
            }
#pragma unroll
            for (int mi = 0; mi < 4; mi++)
#pragma unroll
                for (int nh = 0; nh < 2; nh++)
#pragma unroll
                    for (int q = 0; q < 2; q++) {
                        float* d = acc[mi][nh * 2 + q];
                        mma_bf16(d, ah[mi], bh[nh][q * 2], bh[nh][q * 2 + 1]);
                        mma_bf16(d, ah[mi], bl[nh][q * 2], bl[nh][q * 2 + 1]);
                        mma_bf16(d, al[mi], bh[nh][q * 2], bh[nh][q * 2 + 1]);
                    }
        }
        __syncthreads();
        if (it + 3 < 16) LOAD_STAGE(it + 3, s);
        s = (s == 2) ? 0 : s + 1;
    }

    // ---------------- epilogue: registers -> global (fused scatter) --------
    const int wnb = n0 + wn * 32;                 // warp n base (global)
    if (MODE == 0) {
        const int sIdx = wnb >> 10;
        const int h    = (wnb >> 6) & 15;
        const int dby  = (wnb & 63);
        float* dst = (sIdx == 0) ? g_q : (sIdx == 1) ? g_k : g_v;
#pragma unroll
        for (int mi = 0; mi < 4; mi++)
#pragma unroll
            for (int half = 0; half < 2; half++) {
                int row = m0 + wm * 64 + mi * 16 + (lane >> 2) + half * 8;
                int b = row >> 10, l = row & 1023;
                float* rp = &dst[((size_t)(b * H_ + h) * L_ + l) * HD];
#pragma unroll
                for (int ni = 0; ni < 4; ni++) {
                    int d = dby + ni * 8 + (lane & 3) * 2;
                    *(float2*)&rp[d] = make_float2(acc[mi][ni][half * 2],
                                                   acc[mi][ni][half * 2 + 1]);
                }
            }
    } else {
#pragma unroll
        for (int mi = 0; mi < 4; mi++)
#pragma unroll
            for (int half = 0; half < 2; half++) {
                int row = m0 + wm * 64 + mi * 16 + (lane >> 2) + half * 8;
#pragma unroll
                for (int ni = 0; ni < 4; ni++) {
                    int n = wnb + ni * 8 + (lane & 3) * 2;
                    *(float2*)&C[(size_t)row * 1024 + n] =
                        make_float2(acc[mi][ni][half * 2], acc[mi][ni][half * 2 + 1]);
                }
            }
    }
#undef LOAD_STAGE
}

// ---------------------------------------------------------------------------
// Attention (unchanged): one block = (b,h) x 64-query tile
// ---------------------------------------------------------------------------
#define SW 324
#define SMEM_FLOATS (4352 * 3 + 64 * SW)   // 135168 bytes

__global__ void __launch_bounds__(256) attn_kernel(const float* __restrict__ rel_emb) {
    extern __shared__ float sm[];
    float* Qs = sm;            // [64][68], d-major
    float* KV = sm + 4352;     // [64][68]
    float* qE = sm + 8704;     // [64][68], qi-major
    float* S  = sm + 13056;    // [64][SW]

    int t  = threadIdx.x;
    int tx = t & 15, ty = t >> 4;
    int qt0 = blockIdx.x * 64;
    int bh  = blockIdx.y;
    const float* qb = g_q + (size_t)bh * L_ * HD;
    const float* kb = g_k + (size_t)bh * L_ * HD;
    const float* vb = g_v + (size_t)bh * L_ * HD;
    int lr = t >> 2, lq = (t & 3) << 2;

#pragma unroll
    for (int dq = lq; dq < 64; dq += 16) {
        float4 v = *(const float4*)&qb[(qt0 + lr) * HD + dq];
        Qs[(dq + 0) * 68 + lr] = v.x; Qs[(dq + 1) * 68 + lr] = v.y;
        Qs[(dq + 2) * 68 + lr] = v.z; Qs[(dq + 3) * 68 + lr] = v.w;
    }
    for (int idx = t; idx < 65 * 16; idx += 256) {
        int r = idx >> 4, quad = (idx & 15) << 2;
        float4 v = *(const float4*)&rel_emb[r * HD + quad];
        KV[(quad + 0) * 68 + r] = v.x; KV[(quad + 1) * 68 + r] = v.y;
        KV[(quad + 2) * 68 + r] = v.z; KV[(quad + 3) * 68 + r] = v.w;
    }
    __syncthreads();

    {
        int qi = t & 63;
        int rq = (t >> 6) << 2;
#pragma unroll
        for (int pass = 0; pass < 5; pass++) {
            int r0 = pass * 16 + rq;
            if (r0 < 65) {
                float a0 = 0, a1 = 0, a2 = 0, a3 = 0;
#pragma unroll 8
                for (int d = 0; d < 64; d++) {
                    float  qv = Qs[d * 68 + qi];
                    float4 rv = *(const float4*)&KV[d * 68 + r0];
                    a0 += qv * rv.x; a1 += qv * rv.y;
                    a2 += qv * rv.z; a3 += qv * rv.w;
                }
                qE[qi * 68 + r0] = a0;
                if (r0 + 1 < 65) qE[qi * 68 + r0 + 1] = a1;
                if (r0 + 2 < 65) qE[qi * 68 + r0 + 2] = a2;
                if (r0 + 3 < 65) qE[qi * 68 + r0 + 3] = a3;
            }
        }
    }

    for (int kbk = 0; kbk < 5; kbk++) {
        int kb0 = qt0 - 256 + kbk * 64;
        if (kb0 >= 0) {
            __syncthreads();
#pragma unroll
            for (int dq = lq; dq < 64; dq += 16) {
                float4 v = *(const float4*)&kb[(kb0 + lr) * HD + dq];
                KV[(dq + 0) * 68 + lr] = v.x; KV[(dq + 1) * 68 + lr] = v.y;
                KV[(dq + 2) * 68 + lr] = v.z; KV[(dq + 3) * 68 + lr] = v.w;
            }
            __syncthreads();
            float s4[4][4];
#pragma unroll
            for (int r = 0; r < 4; r++)
#pragma unroll
                for (int c = 0; c < 4; c++) s4[r][c] = 0.f;
#pragma unroll 16
            for (int d = 0; d < 64; d++) {
                float4 a = *(const float4*)&Qs[d * 68 + ty * 4];
                float4 b = *(const float4*)&KV[d * 68 + tx * 4];
                s4[0][0] += a.x * b.x; s4[0][1] += a.x * b.y;
                s4[0][2] += a.x * b.z; s4[0][3] += a.x * b.w;
                s4[1][0] += a.y * b.x; s4[1][1] += a.y * b.y;
                s4[1][2] += a.y * b.z; s4[1][3] += a.y * b.w;
                s4[2][0] += a.z * b.x; s4[2][1] += a.z * b.y;
                s4[2][2] += a.z * b.z; s4[2][3] += a.z * b.w;
                s4[3][0] += a.w * b.x; s4[3][1] += a.w * b.y;
                s4[3][2] += a.w * b.z; s4[3][3] += a.w * b.w;
            }
#pragma unroll
            for (int r = 0; r < 4; r++)
#pragma unroll
                for (int c = 0; c < 4; c++) {
                    int i = qt0 + ty * 4 + r;
                    int j = kb0 + tx * 4 + c;
                    float val;
                    if (j > i || (i - j) >= 256) {
                        val = -1e30f;
                    } else {
                        int rel = j - i + 64;
                        if (rel < 0) rel = 0;
                        val = (s4[r][c] + qE[(ty * 4 + r) * 68 + rel]) * 0.125f;
                    }
                    S[(ty * 4 + r) * SW + kbk * 64 + tx * 4 + c] = val;
                }
        } else {
#pragma unroll
            for (int r = 0; r < 4; r++)
#pragma unroll
                for (int c = 0; c < 4; c++)
                    S[(ty * 4 + r) * SW + kbk * 64 + tx * 4 + c] = -1e30f;
        }
    }
    __syncthreads();

    {
        int warp = t >> 5, lane = t & 31;
        for (int r = warp * 8; r < warp * 8 + 8; r++) {
            float mx = -1e30f;
            for (int c = lane; c < 320; c += 32) mx = fmaxf(mx, S[r * SW + c]);
#pragma unroll
            for (int o = 16; o > 0; o >>= 1)
                mx = fmaxf(mx, __shfl_xor_sync(0xffffffffu, mx, o));
            float sum = 0.f;
            for (int c = lane; c < 320; c += 32) {
                float p = __expf(S[r * SW + c] - mx);
                S[r * SW + c] = p;
                sum += p;
            }
#pragma unroll
            for (int o = 16; o > 0; o >>= 1)
                sum += __shfl_xor_sync(0xffffffffu, sum, o);
            float inv = 1.f / sum;
            for (int c = lane; c < 320; c += 32) S[r * SW + c] *= inv;
        }
    }
    __syncthreads();

    float o4[4][4];
#pragma unroll
    for (int r = 0; r < 4; r++)
#pragma unroll
        for (int c = 0; c < 4; c++) o4[r][c] = 0.f;

    for (int kbk = 0; kbk < 5; kbk++) {
        int kb0 = qt0 - 256 + kbk * 64;
        if (kb0 < 0) continue;
        __syncthreads();
#pragma unroll
        for (int dq = lq; dq < 64; dq += 16) {
            float4 v = *(const float4*)&vb[(kb0 + lr) * HD + dq];
            *(float4*)&KV[lr * 68 + dq] = v;
        }
        __syncthreads();
#pragma unroll 8
        for (int j = 0; j < 64; j++) {
            float4 vv = *(const float4*)&KV[j * 68 + tx * 4];
            float p0 = S[(ty * 4 + 0) * SW + kbk * 64 + j];
            float p1 = S[(ty * 4 + 1) * SW + kbk * 64 + j];
            float p2 = S[(ty * 4 + 2) * SW + kbk * 64 + j];
            float p3 = S[(ty * 4 + 3) * SW + kbk * 64 + j];
            o4[0][0] += p0 * vv.x; o4[0][1] += p0 * vv.y;
            o4[0][2] += p0 * vv.z; o4[0][3] += p0 * vv.w;
            o4[1][0] += p1 * vv.x; o4[1][1] += p1 * vv.y;
            o4[1][2] += p1 * vv.z; o4[1][3] += p1 * vv.w;
            o4[2][0] += p2 * vv.x; o4[2][1] += p2 * vv.y;
            o4[2][2] += p2 * vv.z; o4[2][3] += p2 * vv.w;
            o4[3][0] += p3 * vv.x; o4[3][1] += p3 * vv.y;
            o4[3][2] += p3 * vv.z; o4[3][3] += p3 * vv.w;
        }
    }

    int b = bh >> 4, h = bh & 15;
#pragma unroll
    for (int r = 0; r < 4; r++) {
        int i = qt0 + ty * 4 + r;
        float4 v = make_float4(o4[r][0], o4[r][1], o4[r][2], o4[r][3]);
        *(float4*)&g_att[((size_t)(b * L_ + i) * H_ + h) * HD + tx * 4] = v;
    }
}

// ---------------------------------------------------------------------------
extern "C" void kernel_launch(void* const* d_in, const int* in_sizes, int n_in,
                              void* d_out, int out_size) {
    const float* x       = (const float*)d_in[0];   // [4,1024,1024]
    const float* w_qkv   = (const float*)d_in[1];   // [3072,1024]
    const float* w_out   = (const float*)d_in[2];   // [1024,1024]
    const float* rel_emb = (const float*)d_in[3];   // [129,64]
    float* out = (float*)d_out;                     // [4,1024,1024]

    (void)in_sizes; (void)n_in; (void)out_size;

    const int attn_smem = SMEM_FLOATS * (int)sizeof(float);   // 135168
    cudaFuncSetAttribute(attn_kernel,
                         cudaFuncAttributeMaxDynamicSharedMemorySize, attn_smem);
    cudaFuncSetAttribute(tc_gemm<0>,
                         cudaFuncAttributeMaxDynamicSharedMemorySize, TC_SMEM);
    cudaFuncSetAttribute(tc_gemm<1>,
                         cudaFuncAttributeMaxDynamicSharedMemorySize, TC_SMEM);

    // 1) Split-precision conversions
    cvt_split<0><<<(B_ * L_ * D_ / 4 + 255) / 256, 256>>>(x,    B_ * L_ * D_ / 4);
    cvt_split<1><<<(3 * D_ * D_ / 4 + 255) / 256, 256>>>(w_qkv, 3 * D_ * D_ / 4);
    cvt_split<2><<<(D_ * D_ / 4 + 255) / 256, 256>>>(w_out,     D_ * D_ / 4);

    // 2) QKV projection (mma.sync tensor cores, scatter to g_q/g_k/g_v)
    tc_gemm<0><<<dim3(3072 / 128, 4096 / 128), 256, TC_SMEM>>>(nullptr);

    // 3) Relative attention
    attn_kernel<<<dim3(L_ / 64, NBH), 256, attn_smem>>>(rel_emb);

    // 4) Convert attention output, then output projection
    cvt_split<3><<<(B_ * L_ * D_ / 4 + 255) / 256, 256>>>(nullptr, B_ * L_ * D_ / 4);
    tc_gemm<1><<<dim3(1024 / 128, 4096 / 128), 256, TC_SMEM>>>(out);
}

// round 6
// speedup vs baseline: 2.5713x; 1.1481x over previous
#include <cuda_runtime.h>
#include <cuda_bf16.h>
#include <cstdint>

#define B_  4
#define L_  1024
#define D_  1024
#define H_  16
#define HD  64
#define NBH (B_ * H_)   // 64

// ---------------------------------------------------------------------------
// Static device scratch (no allocation allowed)
// ---------------------------------------------------------------------------
__device__ float g_q[NBH * L_ * HD];
__device__ float g_k[NBH * L_ * HD];
__device__ float g_v[NBH * L_ * HD];

__device__ __nv_bfloat16 g_x_hi[B_ * L_ * D_];
__device__ __nv_bfloat16 g_x_lo[B_ * L_ * D_];
__device__ __nv_bfloat16 g_wqkv_hi[3 * D_ * D_];
__device__ __nv_bfloat16 g_wqkv_lo[3 * D_ * D_];
__device__ __nv_bfloat16 g_wout_hi[D_ * D_];
__device__ __nv_bfloat16 g_wout_lo[D_ * D_];
__device__ __nv_bfloat16 g_att_hi[B_ * L_ * D_];
__device__ __nv_bfloat16 g_att_lo[B_ * L_ * D_];

// ---------------------------------------------------------------------------
// PTX helpers (base ISA only — NO sm_100a features)
// ---------------------------------------------------------------------------
__device__ __forceinline__ uint32_t smem_u32(const void* p) {
    uint32_t a;
    asm("{ .reg .u64 t; cvta.to.shared.u64 t, %1; cvt.u32.u64 %0, t; }" : "=r"(a) : "l"(p));
    return a;
}

#define CP_ASYNC16(dst, src) \
    asm volatile("cp.async.cg.shared.global [%0], [%1], 16;" :: "r"(dst), "l"(src))
#define CP_COMMIT() asm volatile("cp.async.commit_group;" ::: "memory")
#define CP_WAIT2()  asm volatile("cp.async.wait_group 2;" ::: "memory")

__device__ __forceinline__ void ldsm_x4(uint32_t& r0, uint32_t& r1, uint32_t& r2,
                                        uint32_t& r3, uint32_t addr) {
    asm volatile("ldmatrix.sync.aligned.m8n8.x4.shared.b16 {%0,%1,%2,%3}, [%4];"
                 : "=r"(r0), "=r"(r1), "=r"(r2), "=r"(r3) : "r"(addr));
}

__device__ __forceinline__ void mma_bf16(float* d, const uint32_t* a,
                                         uint32_t b0, uint32_t b1) {
    asm volatile(
        "mma.sync.aligned.m16n8k16.row.col.f32.bf16.bf16.f32 "
        "{%0,%1,%2,%3}, {%4,%5,%6,%7}, {%8,%9}, {%0,%1,%2,%3};"
        : "+f"(d[0]), "+f"(d[1]), "+f"(d[2]), "+f"(d[3])
        : "r"(a[0]), "r"(a[1]), "r"(a[2]), "r"(a[3]), "r"(b0), "r"(b1));
}

// split fp32x4 -> two packed bf16x4 (hi, lo)
__device__ __forceinline__ void split4(float4 v, uint2& h, uint2& l) {
    __nv_bfloat162 h01 = __floats2bfloat162_rn(v.x, v.y);
    __nv_bfloat162 h23 = __floats2bfloat162_rn(v.z, v.w);
    float2 f01 = __bfloat1622float2(h01);
    float2 f23 = __bfloat1622float2(h23);
    __nv_bfloat162 l01 = __floats2bfloat162_rn(v.x - f01.x, v.y - f01.y);
    __nv_bfloat162 l23 = __floats2bfloat162_rn(v.z - f23.x, v.w - f23.y);
    h = make_uint2(*(uint32_t*)&h01, *(uint32_t*)&h23);
    l = make_uint2(*(uint32_t*)&l01, *(uint32_t*)&l23);
}

// swizzled byte offset of float4-chunk c4 in a 128B-row bf16 tile
__device__ __forceinline__ uint32_t sw_off4(int row, int c4) {
    return (uint32_t)(row * 128 + ((((c4 >> 1) ^ (row & 7)) << 4) | ((c4 & 1) << 3)));
}

// ---------------------------------------------------------------------------
// fp32 -> bf16 hi/lo split conversion.  W: 0=x, 1=wqkv, 2=wout
// ---------------------------------------------------------------------------
template <int W>
__global__ void __launch_bounds__(256) cvt_split(const float* __restrict__ src, int n4) {
    __nv_bfloat16* hi = (W == 0) ? g_x_hi : (W == 1) ? g_wqkv_hi : g_wout_hi;
    __nv_bfloat16* lo = (W == 0) ? g_x_lo : (W == 1) ? g_wqkv_lo : g_wout_lo;

    int i = blockIdx.x * 256 + threadIdx.x;
    if (i >= n4) return;
    float4 v = ((const float4*)src)[i];
    uint2 h, l;
    split4(v, h, l);
    ((uint2*)hi)[i] = h;
    ((uint2*)lo)[i] = l;
}

// ---------------------------------------------------------------------------
// Warp-mma split-bf16 GEMM NT (validated in R4)
// ---------------------------------------------------------------------------
#define TILE_B  16384
#define STAGE_B (4 * TILE_B)
#define NSTAGE  3
#define TC_SMEM (NSTAGE * STAGE_B)   // 192 KB

template <int MODE>
__global__ void __launch_bounds__(256, 1) tc_gemm(float* __restrict__ C) {
    extern __shared__ char smc[];
    uint32_t sb = smem_u32(smc);

    const __nv_bfloat16* Ah = (MODE == 0) ? g_x_hi : g_att_hi;
    const __nv_bfloat16* Al = (MODE == 0) ? g_x_lo : g_att_lo;
    const __nv_bfloat16* Bhp = (MODE == 0) ? g_wqkv_hi : g_wout_hi;
    const __nv_bfloat16* Blp = (MODE == 0) ? g_wqkv_lo : g_wout_lo;

    const int t = threadIdx.x, lane = t & 31, warp = t >> 5;
    const int wm = warp & 1, wn = warp >> 1;
    const int m0 = blockIdx.y * 128, n0 = blockIdx.x * 128;

    uint32_t ld_sm[4];
    size_t   ld_ga[4], ld_gb[4];
#pragma unroll
    for (int j = 0; j < 4; j++) {
        int c = t + 256 * j;
        int row = c >> 3, ch = c & 7;
        ld_sm[j] = (uint32_t)(row * 128 + ((ch ^ (row & 7)) << 4));
        ld_ga[j] = (size_t)(m0 + row) * 1024 + ch * 8;
        ld_gb[j] = (size_t)(n0 + row) * 1024 + ch * 8;
    }

    float acc[4][4][4];
#pragma unroll
    for (int mi = 0; mi < 4; mi++)
#pragma unroll
        for (int ni = 0; ni < 4; ni++)
#pragma unroll
            for (int q = 0; q < 4; q++) acc[mi][ni][q] = 0.f;

    const int a_rb = wm * 64 + (lane & 15);
    const int a_cb = (lane >> 4);
    const int b_rb = wn * 32 + ((lane >> 4) * 8) + (lane & 7);
    const int b_cb = (lane >> 3) & 1;

#define LOAD_STAGE(it, s) do {                                                  \
    uint32_t base = sb + (s) * STAGE_B;                                         \
    int k0 = (it) * 64;                                                         \
    _Pragma("unroll")                                                           \
    for (int j = 0; j < 4; j++) {                                               \
        CP_ASYNC16(base + 0 * TILE_B + ld_sm[j], Ah  + ld_ga[j] + k0);          \
        CP_ASYNC16(base + 1 * TILE_B + ld_sm[j], Al  + ld_ga[j] + k0);          \
        CP_ASYNC16(base + 2 * TILE_B + ld_sm[j], Bhp + ld_gb[j] + k0);          \
        CP_ASYNC16(base + 3 * TILE_B + ld_sm[j], Blp + ld_gb[j] + k0);          \
    }                                                                           \
    CP_COMMIT();                                                                \
} while (0)

    LOAD_STAGE(0, 0);
    LOAD_STAGE(1, 1);
    LOAD_STAGE(2, 2);

    int s = 0;
    for (int it = 0; it < 16; it++) {
        CP_WAIT2();
        __syncthreads();
        uint32_t base = sb + s * STAGE_B;

#pragma unroll
        for (int kk = 0; kk < 4; kk++) {
            uint32_t ah[4][4], al[4][4];
#pragma unroll
            for (int mi = 0; mi < 4; mi++) {
                int r = a_rb + mi * 16;
                int c = kk * 2 + a_cb;
                uint32_t addr = base + (uint32_t)(r * 128 + ((c ^ (r & 7)) << 4));
                ldsm_x4(ah[mi][0], ah[mi][1], ah[mi][2], ah[mi][3], addr);
                ldsm_x4(al[mi][0], al[mi][1], al[mi][2], al[mi][3], addr + TILE_B);
            }
            uint32_t bh[2][4], bl[2][4];
#pragma unroll
            for (int nh = 0; nh < 2; nh++) {
                int r = b_rb + nh * 16;
                int c = kk * 2 + b_cb;
                uint32_t addr = base + 2 * TILE_B + (uint32_t)(r * 128 + ((c ^ (r & 7)) << 4));
                ldsm_x4(bh[nh][0], bh[nh][1], bh[nh][2], bh[nh][3], addr);
                ldsm_x4(bl[nh][0], bl[nh][1], bl[nh][2], bl[nh][3], addr + TILE_B);
            }
#pragma unroll
            for (int mi = 0; mi < 4; mi++)
#pragma unroll
                for (int nh = 0; nh < 2; nh++)
#pragma unroll
                    for (int q = 0; q < 2; q++) {
                        float* d = acc[mi][nh * 2 + q];
                        mma_bf16(d, ah[mi], bh[nh][q * 2], bh[nh][q * 2 + 1]);
                        mma_bf16(d, ah[mi], bl[nh][q * 2], bl[nh][q * 2 + 1]);
                        mma_bf16(d, al[mi], bh[nh][q * 2], bh[nh][q * 2 + 1]);
                    }
        }
        __syncthreads();
        if (it + 3 < 16) LOAD_STAGE(it + 3, s);
        s = (s == 2) ? 0 : s + 1;
    }

    const int wnb = n0 + wn * 32;
    if (MODE == 0) {
        const int sIdx = wnb >> 10;
        const int h    = (wnb >> 6) & 15;
        const int dby  = (wnb & 63);
        float* dst = (sIdx == 0) ? g_q : (sIdx == 1) ? g_k : g_v;
#pragma unroll
        for (int mi = 0; mi < 4; mi++)
#pragma unroll
            for (int half = 0; half < 2; half++) {
                int row = m0 + wm * 64 + mi * 16 + (lane >> 2) + half * 8;
                int b = row >> 10, l = row & 1023;
                float* rp = &dst[((size_t)(b * H_ + h) * L_ + l) * HD];
#pragma unroll
                for (int ni = 0; ni < 4; ni++) {
                    int d = dby + ni * 8 + (lane & 3) * 2;
                    *(float2*)&rp[d] = make_float2(acc[mi][ni][half * 2],
                                                   acc[mi][ni][half * 2 + 1]);
                }
            }
    } else {
#pragma unroll
        for (int mi = 0; mi < 4; mi++)
#pragma unroll
            for (int half = 0; half < 2; half++) {
                int row = m0 + wm * 64 + mi * 16 + (lane >> 2) + half * 8;
#pragma unroll
                for (int ni = 0; ni < 4; ni++) {
                    int n = wnb + ni * 8 + (lane & 3) * 2;
                    *(float2*)&C[(size_t)row * 1024 + n] =
                        make_float2(acc[mi][ni][half * 2], acc[mi][ni][half * 2 + 1]);
                }
            }
    }
#undef LOAD_STAGE
}

// ---------------------------------------------------------------------------
// Tensor-core attention: one block = (b,h) x 64-query tile, 256 threads.
// All GEMMs (qE, QK^T, PV) via mma.sync bf16 3-term split; softmax fp32.
// smem (bytes):
//   [0      ) Qh / Ph   8K   [ 8192) Ql / Pl   8K
//   [16384  ) Kh / Vth  8K   [24576) Kl / Vtl  8K
//   [32768  ) Rh 16K (128 rows)   [49152) Rl 16K
//   [65536  ) qE fp32 [64][80]  20K
//   [86016  ) S  fp32 [64][328] 82K        total 169984
// ---------------------------------------------------------------------------
#define OFF_QH  0
#define OFF_QL  8192
#define OFF_KH  16384
#define OFF_KL  24576
#define OFF_RH  32768
#define OFF_RL  49152
#define OFF_QE  65536
#define OFF_S   86016
#define ATT_SMEM 169984
#define SP 328    // S pitch (f32)
#define QEP 80    // qE pitch (f32)

__global__ void __launch_bounds__(256, 1) attn_mma(const float* __restrict__ rel_emb) {
    extern __shared__ char smc[];
    uint32_t sb = smem_u32(smc);
    float* Sf  = (float*)(smc + OFF_S);
    float* qEf = (float*)(smc + OFF_QE);

    const int t = threadIdx.x, lane = t & 31, warp = t >> 5;
    const int wm = warp & 1, wn = warp >> 1;
    const int qt0 = blockIdx.x * 64;
    const int bh  = blockIdx.y;
    const float* qb = g_q + (size_t)bh * L_ * HD;
    const float* kb = g_k + (size_t)bh * L_ * HD;
    const float* vb = g_v + (size_t)bh * L_ * HD;

    // fragment address components (identical pattern to tc_gemm)
    const int a_rb = wm * 32 + (lane & 15);       // + mi*16
    const int a_cb = (lane >> 4);                 // k chunk half
    const int b_rb16 = wn * 16 + ((lane >> 4) * 8) + (lane & 7);   // n-extent 16
    const int b_cb = (lane >> 3) & 1;

    // ---------- phase 0: zero R region, fill Q and R (hi/lo, swizzled) ------
    for (int i = t; i < 2048; i += 256)
        ((uint4*)(smc + OFF_RH))[i] = make_uint4(0, 0, 0, 0);
#pragma unroll
    for (int j = 0; j < 4; j++) {
        int c = t + 256 * j;                       // 0..1023 float4 chunks
        int row = c >> 4, c4 = c & 15;
        float4 v = *(const float4*)&qb[(qt0 + row) * HD + c4 * 4];
        uint2 h, l;
        split4(v, h, l);
        uint32_t o = sw_off4(row, c4);
        *(uint2*)(smc + OFF_QH + o) = h;
        *(uint2*)(smc + OFF_QL + o) = l;
    }
    for (int idx = t; idx < 65 * 16; idx += 256) {
        int r = idx >> 4, c4 = idx & 15;
        float4 v = *(const float4*)&rel_emb[r * HD + c4 * 4];
        uint2 h, l;
        split4(v, h, l);
        uint32_t o = sw_off4(r, c4);
        *(uint2*)(smc + OFF_RH + o) = h;
        *(uint2*)(smc + OFF_RL + o) = l;
    }
    __syncthreads();

    // ---------- phase 1: qE = Q * R^T  (M=64, N=128 padded, K=64) -----------
    {
        float qa[2][2][2][4];   // mi, nh, q
#pragma unroll
        for (int mi = 0; mi < 2; mi++)
#pragma unroll
            for (int nh = 0; nh < 2; nh++)
#pragma unroll
                for (int q = 0; q < 2; q++)
#pragma unroll
                    for (int e = 0; e < 4; e++) qa[mi][nh][q][e] = 0.f;

#pragma unroll
        for (int kk = 0; kk < 4; kk++) {
            uint32_t ah[2][4], al[2][4];
#pragma unroll
            for (int mi = 0; mi < 2; mi++) {
                int r = a_rb + mi * 16;
                int c = kk * 2 + a_cb;
                uint32_t addr = sb + (uint32_t)(r * 128 + ((c ^ (r & 7)) << 4));
                ldsm_x4(ah[mi][0], ah[mi][1], ah[mi][2], ah[mi][3], addr + OFF_QH);
                ldsm_x4(al[mi][0], al[mi][1], al[mi][2], al[mi][3], addr + OFF_QL);
            }
            uint32_t bh[2][4], bl[2][4];
#pragma unroll
            for (int nh = 0; nh < 2; nh++) {
                int r = wn * 32 + nh * 16 + ((lane >> 4) * 8) + (lane & 7);
                int c = kk * 2 + b_cb;
                uint32_t addr = sb + (uint32_t)(r * 128 + ((c ^ (r & 7)) << 4));
                ldsm_x4(bh[nh][0], bh[nh][1], bh[nh][2], bh[nh][3], addr + OFF_RH);
                ldsm_x4(bl[nh][0], bl[nh][1], bl[nh][2], bl[nh][3], addr + OFF_RL);
            }
#pragma unroll
            for (int mi = 0; mi < 2; mi++)
#pragma unroll
                for (int nh = 0; nh < 2; nh++)
#pragma unroll
                    for (int q = 0; q < 2; q++) {
                        float* d = qa[mi][nh][q];
                        mma_bf16(d, ah[mi], bh[nh][q * 2], bh[nh][q * 2 + 1]);
                        mma_bf16(d, ah[mi], bl[nh][q * 2], bl[nh][q * 2 + 1]);
                        mma_bf16(d, al[mi], bh[nh][q * 2], bh[nh][q * 2 + 1]);
                    }
        }
        // store qE cols < 72
#pragma unroll
        for (int mi = 0; mi < 2; mi++)
#pragma unroll
            for (int nh = 0; nh < 2; nh++)
#pragma unroll
                for (int q = 0; q < 2; q++)
#pragma unroll
                    for (int half = 0; half < 2; half++) {
                        int row = wm * 32 + mi * 16 + (lane >> 2) + half * 8;
                        int col = wn * 32 + nh * 16 + q * 8 + (lane & 3) * 2;
                        if (col < 72) {
                            qEf[row * QEP + col]     = qa[mi][nh][q][half * 2];
                            qEf[row * QEP + col + 1] = qa[mi][nh][q][half * 2 + 1];
                        }
                    }
    }

    // ---------- phase 2: scores for 5 key blocks ---------------------------
    for (int kbk = 0; kbk < 5; kbk++) {
        int kb0 = qt0 - 256 + kbk * 64;
        if (kb0 >= 0) {
            __syncthreads();   // prior KV consumers done; qE stores visible
#pragma unroll
            for (int j = 0; j < 4; j++) {
                int c = t + 256 * j;
                int row = c >> 4, c4 = c & 15;
                float4 v = *(const float4*)&kb[(kb0 + row) * HD + c4 * 4];
                uint2 h, l;
                split4(v, h, l);
                uint32_t o = sw_off4(row, c4);
                *(uint2*)(smc + OFF_KH + o) = h;
                *(uint2*)(smc + OFF_KL + o) = l;
            }
            __syncthreads();

            float sc[2][2][4];
#pragma unroll
            for (int mi = 0; mi < 2; mi++)
#pragma unroll
                for (int q = 0; q < 2; q++)
#pragma unroll
                    for (int e = 0; e < 4; e++) sc[mi][q][e] = 0.f;

#pragma unroll
            for (int kk = 0; kk < 4; kk++) {
                uint32_t ah[2][4], al[2][4];
#pragma unroll
                for (int mi = 0; mi < 2; mi++) {
                    int r = a_rb + mi * 16;
                    int c = kk * 2 + a_cb;
                    uint32_t addr = sb + (uint32_t)(r * 128 + ((c ^ (r & 7)) << 4));
                    ldsm_x4(ah[mi][0], ah[mi][1], ah[mi][2], ah[mi][3], addr + OFF_QH);
                    ldsm_x4(al[mi][0], al[mi][1], al[mi][2], al[mi][3], addr + OFF_QL);
                }
                uint32_t bh[4], bl[4];
                {
                    int r = b_rb16;
                    int c = kk * 2 + b_cb;
                    uint32_t addr = sb + (uint32_t)(r * 128 + ((c ^ (r & 7)) << 4));
                    ldsm_x4(bh[0], bh[1], bh[2], bh[3], addr + OFF_KH);
                    ldsm_x4(bl[0], bl[1], bl[2], bl[3], addr + OFF_KL);
                }
#pragma unroll
                for (int mi = 0; mi < 2; mi++)
#pragma unroll
                    for (int q = 0; q < 2; q++) {
                        float* d = sc[mi][q];
                        mma_bf16(d, ah[mi], bh[q * 2], bh[q * 2 + 1]);
                        mma_bf16(d, ah[mi], bl[q * 2], bl[q * 2 + 1]);
                        mma_bf16(d, al[mi], bh[q * 2], bh[q * 2 + 1]);
                    }
            }
            // epilogue: qE gather + mask + scale -> S
#pragma unroll
            for (int mi = 0; mi < 2; mi++)
#pragma unroll
                for (int q = 0; q < 2; q++)
#pragma unroll
                    for (int half = 0; half < 2; half++)
#pragma unroll
                        for (int dd = 0; dd < 2; dd++) {
                            int row = wm * 32 + mi * 16 + (lane >> 2) + half * 8;
                            int col = wn * 16 + q * 8 + (lane & 3) * 2 + dd;
                            int i = qt0 + row, j = kb0 + col;
                            float val;
                            if (j > i || (i - j) >= 256) {
                                val = -1e30f;
                            } else {
                                int rel = j - i + 64;
                                if (rel < 0) rel = 0;
                                val = (sc[mi][q][half * 2 + dd] + qEf[row * QEP + rel]) * 0.125f;
                            }
                            Sf[row * SP + kbk * 64 + col] = val;
                        }
        } else {
            for (int e = t; e < 4096; e += 256)
                Sf[(e >> 6) * SP + kbk * 64 + (e & 63)] = -1e30f;
        }
    }
    __syncthreads();

    // ---------- phase 3: row softmax (fp32, 320 cols) ----------------------
    {
        for (int r = warp * 8; r < warp * 8 + 8; r++) {
            float mx = -1e30f;
            for (int c = lane; c < 320; c += 32) mx = fmaxf(mx, Sf[r * SP + c]);
#pragma unroll
            for (int o = 16; o > 0; o >>= 1)
                mx = fmaxf(mx, __shfl_xor_sync(0xffffffffu, mx, o));
            float sum = 0.f;
            for (int c = lane; c < 320; c += 32) {
                float p = __expf(Sf[r * SP + c] - mx);
                Sf[r * SP + c] = p;
                sum += p;
            }
#pragma unroll
            for (int o = 16; o > 0; o >>= 1)
                sum += __shfl_xor_sync(0xffffffffu, sum, o);
            float inv = 1.f / sum;
            for (int c = lane; c < 320; c += 32) Sf[r * SP + c] *= inv;
        }
    }
    __syncthreads();

    // ---------- phase 4: out = P * V  (accumulate over key blocks) ---------
    float oac[2][2][4];
#pragma unroll
    for (int mi = 0; mi < 2; mi++)
#pragma unroll
        for (int q = 0; q < 2; q++)
#pragma unroll
            for (int e = 0; e < 4; e++) oac[mi][q][e] = 0.f;

    for (int kbk = 0; kbk < 5; kbk++) {
        int kb0 = qt0 - 256 + kbk * 64;
        if (kb0 < 0) continue;
        __syncthreads();   // prior P/Vt consumers done
        // P slice [64][64] hi/lo from S (reuses Q region)
        {
            int row = t >> 2;
            int cbq = (t & 3) * 4;   // float4 chunk base
#pragma unroll
            for (int q4 = 0; q4 < 4; q4++) {
                int c4 = cbq + q4;
                float4 v = *(const float4*)&Sf[row * SP + kbk * 64 + c4 * 4];
                uint2 h, l;
                split4(v, h, l);
                uint32_t o = sw_off4(row, c4);
                *(uint2*)(smc + OFF_QH + o) = h;
                *(uint2*)(smc + OFF_QL + o) = l;
            }
        }
        // V transposed [d][j] hi/lo (reuses K region)
#pragma unroll
        for (int j = 0; j < 4; j++) {
            int c = t + 256 * j;
            int jr = c >> 4, d4 = (c & 15) * 4;
            float4 v = *(const float4*)&vb[(kb0 + jr) * HD + d4];
            float vv[4] = {v.x, v.y, v.z, v.w};
#pragma unroll
            for (int e = 0; e < 4; e++) {
                int d = d4 + e;
                __nv_bfloat16 h = __float2bfloat16(vv[e]);
                __nv_bfloat16 lo = __float2bfloat16(vv[e] - __bfloat162float(h));
                uint32_t o = (uint32_t)(d * 128 + ((((jr >> 3) ^ (d & 7)) << 4) | ((jr & 7) * 2)));
                *(__nv_bfloat16*)(smc + OFF_KH + o) = h;
                *(__nv_bfloat16*)(smc + OFF_KL + o) = lo;
            }
        }
        __syncthreads();

#pragma unroll
        for (int kk = 0; kk < 4; kk++) {
            uint32_t ah[2][4], al[2][4];
#pragma unroll
            for (int mi = 0; mi < 2; mi++) {
                int r = a_rb + mi * 16;
                int c = kk * 2 + a_cb;
                uint32_t addr = sb + (uint32_t)(r * 128 + ((c ^ (r & 7)) << 4));
                ldsm_x4(ah[mi][0], ah[mi][1], ah[mi][2], ah[mi][3], addr + OFF_QH);
                ldsm_x4(al[mi][0], al[mi][1], al[mi][2], al[mi][3], addr + OFF_QL);
            }
            uint32_t bh[4], bl[4];
            {
                int r = b_rb16;
                int c = kk * 2 + b_cb;
                uint32_t addr = sb + (uint32_t)(r * 128 + ((c ^ (r & 7)) << 4));
                ldsm_x4(bh[0], bh[1], bh[2], bh[3], addr + OFF_KH);
                ldsm_x4(bl[0], bl[1], bl[2], bl[3], addr + OFF_KL);
            }
#pragma unroll
            for (int mi = 0; mi < 2; mi++)
#pragma unroll
                for (int q = 0; q < 2; q++) {
                    float* d = oac[mi][q];
                    mma_bf16(d, ah[mi], bh[q * 2], bh[q * 2 + 1]);
                    mma_bf16(d, ah[mi], bl[q * 2], bl[q * 2 + 1]);
                    mma_bf16(d, al[mi], bh[q * 2], bh[q * 2 + 1]);
                }
        }
    }

    // ---------- epilogue: write att hi/lo in [B,L,H*hd] --------------------
    {
        int b = bh >> 4, h = bh & 15;
#pragma unroll
        for (int mi = 0; mi < 2; mi++)
#pragma unroll
            for (int q = 0; q < 2; q++)
#pragma unroll
                for (int half = 0; half < 2; half++) {
                    int row = wm * 32 + mi * 16 + (lane >> 2) + half * 8;
                    int i = qt0 + row;
                    int d = wn * 16 + q * 8 + (lane & 3) * 2;
                    float v0 = oac[mi][q][half * 2], v1 = oac[mi][q][half * 2 + 1];
                    __nv_bfloat162 hh = __floats2bfloat162_rn(v0, v1);
                    float2 hf = __bfloat1622float2(hh);
                    __nv_bfloat162 ll = __floats2bfloat162_rn(v0 - hf.x, v1 - hf.y);
                    size_t off = ((size_t)(b * L_ + i) * H_ + h) * HD + d;
                    *(__nv_bfloat162*)&g_att_hi[off] = hh;
                    *(__nv_bfloat162*)&g_att_lo[off] = ll;
                }
    }
}

// ---------------------------------------------------------------------------
extern "C" void kernel_launch(void* const* d_in, const int* in_sizes, int n_in,
                              void* d_out, int out_size) {
    const float* x       = (const float*)d_in[0];   // [4,1024,1024]
    const float* w_qkv   = (const float*)d_in[1];   // [3072,1024]
    const float* w_out   = (const float*)d_in[2];   // [1024,1024]
    const float* rel_emb = (const float*)d_in[3];   // [129,64]
    float* out = (float*)d_out;                     // [4,1024,1024]

    (void)in_sizes; (void)n_in; (void)out_size;

    cudaFuncSetAttribute(attn_mma,
                         cudaFuncAttributeMaxDynamicSharedMemorySize, ATT_SMEM);
    cudaFuncSetAttribute(tc_gemm<0>,
                         cudaFuncAttributeMaxDynamicSharedMemorySize, TC_SMEM);
    cudaFuncSetAttribute(tc_gemm<1>,
                         cudaFuncAttributeMaxDynamicSharedMemorySize, TC_SMEM);

    // 1) Split-precision conversions
    cvt_split<0><<<(B_ * L_ * D_ / 4 + 255) / 256, 256>>>(x,    B_ * L_ * D_ / 4);
    cvt_split<1><<<(3 * D_ * D_ / 4 + 255) / 256, 256>>>(w_qkv, 3 * D_ * D_ / 4);
    cvt_split<2><<<(D_ * D_ / 4 + 255) / 256, 256>>>(w_out,     D_ * D_ / 4);

    // 2) QKV projection (scatter to g_q/g_k/g_v fp32)
    tc_gemm<0><<<dim3(3072 / 128, 4096 / 128), 256, TC_SMEM>>>(nullptr);

    // 3) Tensor-core relative attention (writes g_att_hi/lo directly)
    attn_mma<<<dim3(L_ / 64, NBH), 256, ATT_SMEM>>>(rel_emb);

    // 4) Output projection
    tc_gemm<1><<<dim3(1024 / 128, 4096 / 128), 256, TC_SMEM>>>(out);
}

// round 7
// speedup vs baseline: 2.8232x; 1.0980x over previous
#include <cuda_runtime.h>
#include <cuda_bf16.h>
#include <cstdint>

#define B_  4
#define L_  1024
#define D_  1024
#define H_  16
#define HD  64
#define NBH (B_ * H_)   // 64

// ---------------------------------------------------------------------------
// Static device scratch (no allocation allowed)
// ---------------------------------------------------------------------------
__device__ __nv_bfloat16 g_q_hi[NBH * L_ * HD];
__device__ __nv_bfloat16 g_q_lo[NBH * L_ * HD];
__device__ __nv_bfloat16 g_k_hi[NBH * L_ * HD];
__device__ __nv_bfloat16 g_k_lo[NBH * L_ * HD];
__device__ __nv_bfloat16 g_v_hi[NBH * L_ * HD];
__device__ __nv_bfloat16 g_v_lo[NBH * L_ * HD];

__device__ __nv_bfloat16 g_x_hi[B_ * L_ * D_];
__device__ __nv_bfloat16 g_x_lo[B_ * L_ * D_];
__device__ __nv_bfloat16 g_wqkv_hi[3 * D_ * D_];
__device__ __nv_bfloat16 g_wqkv_lo[3 * D_ * D_];
__device__ __nv_bfloat16 g_wout_hi[D_ * D_];
__device__ __nv_bfloat16 g_wout_lo[D_ * D_];
__device__ __nv_bfloat16 g_att_hi[B_ * L_ * D_];
__device__ __nv_bfloat16 g_att_lo[B_ * L_ * D_];

// ---------------------------------------------------------------------------
// PTX helpers (base ISA only)
// ---------------------------------------------------------------------------
__device__ __forceinline__ uint32_t smem_u32(const void* p) {
    uint32_t a;
    asm("{ .reg .u64 t; cvta.to.shared.u64 t, %1; cvt.u32.u64 %0, t; }" : "=r"(a) : "l"(p));
    return a;
}

#define CP_ASYNC16(dst, src) \
    asm volatile("cp.async.cg.shared.global [%0], [%1], 16;" :: "r"(dst), "l"(src))
#define CP_COMMIT() asm volatile("cp.async.commit_group;" ::: "memory")
#define CP_WAIT0()  asm volatile("cp.async.wait_group 0;" ::: "memory")
#define CP_WAIT1()  asm volatile("cp.async.wait_group 1;" ::: "memory")
#define CP_WAIT2()  asm volatile("cp.async.wait_group 2;" ::: "memory")

__device__ __forceinline__ void ldsm_x4(uint32_t& r0, uint32_t& r1, uint32_t& r2,
                                        uint32_t& r3, uint32_t addr) {
    asm volatile("ldmatrix.sync.aligned.m8n8.x4.shared.b16 {%0,%1,%2,%3}, [%4];"
                 : "=r"(r0), "=r"(r1), "=r"(r2), "=r"(r3) : "r"(addr));
}
__device__ __forceinline__ void ldsm_x4_t(uint32_t& r0, uint32_t& r1, uint32_t& r2,
                                          uint32_t& r3, uint32_t addr) {
    asm volatile("ldmatrix.sync.aligned.m8n8.x4.trans.shared.b16 {%0,%1,%2,%3}, [%4];"
                 : "=r"(r0), "=r"(r1), "=r"(r2), "=r"(r3) : "r"(addr));
}

__device__ __forceinline__ void mma_bf16(float* d, const uint32_t* a,
                                         uint32_t b0, uint32_t b1) {
    asm volatile(
        "mma.sync.aligned.m16n8k16.row.col.f32.bf16.bf16.f32 "
        "{%0,%1,%2,%3}, {%4,%5,%6,%7}, {%8,%9}, {%0,%1,%2,%3};"
        : "+f"(d[0]), "+f"(d[1]), "+f"(d[2]), "+f"(d[3])
        : "r"(a[0]), "r"(a[1]), "r"(a[2]), "r"(a[3]), "r"(b0), "r"(b1));
}

// split fp32x4 -> two packed bf16x4 (hi, lo)
__device__ __forceinline__ void split4(float4 v, uint2& h, uint2& l) {
    __nv_bfloat162 h01 = __floats2bfloat162_rn(v.x, v.y);
    __nv_bfloat162 h23 = __floats2bfloat162_rn(v.z, v.w);
    float2 f01 = __bfloat1622float2(h01);
    float2 f23 = __bfloat1622float2(h23);
    __nv_bfloat162 l01 = __floats2bfloat162_rn(v.x - f01.x, v.y - f01.y);
    __nv_bfloat162 l23 = __floats2bfloat162_rn(v.z - f23.x, v.w - f23.y);
    h = make_uint2(*(uint32_t*)&h01, *(uint32_t*)&h23);
    l = make_uint2(*(uint32_t*)&l01, *(uint32_t*)&l23);
}

// swizzled byte offset of float4-chunk c4 in a 128B-row bf16 tile
__device__ __forceinline__ uint32_t sw_off4(int row, int c4) {
    return (uint32_t)(row * 128 + ((((c4 >> 1) ^ (row & 7)) << 4) | ((c4 & 1) << 3)));
}

// ---------------------------------------------------------------------------
// fp32 -> bf16 hi/lo split conversion.  W: 0=x, 1=wqkv, 2=wout
// ---------------------------------------------------------------------------
template <int W>
__global__ void __launch_bounds__(256) cvt_split(const float* __restrict__ src, int n4) {
    __nv_bfloat16* hi = (W == 0) ? g_x_hi : (W == 1) ? g_wqkv_hi : g_wout_hi;
    __nv_bfloat16* lo = (W == 0) ? g_x_lo : (W == 1) ? g_wqkv_lo : g_wout_lo;

    int i = blockIdx.x * 256 + threadIdx.x;
    if (i >= n4) return;
    float4 v = ((const float4*)src)[i];
    uint2 h, l;
    split4(v, h, l);
    ((uint2*)hi)[i] = h;
    ((uint2*)lo)[i] = l;
}

// ---------------------------------------------------------------------------
// Warp-mma split-bf16 GEMM NT (validated R4).  MODE 0 epilogue now writes
// q/k/v directly as bf16 hi/lo (split-at-production).
// ---------------------------------------------------------------------------
#define TILE_B  16384
#define STAGE_B (4 * TILE_B)
#define NSTAGE  3
#define TC_SMEM (NSTAGE * STAGE_B)   // 192 KB

template <int MODE>
__global__ void __launch_bounds__(256, 1) tc_gemm(float* __restrict__ C) {
    extern __shared__ char smc[];
    uint32_t sb = smem_u32(smc);

    const __nv_bfloat16* Ah = (MODE == 0) ? g_x_hi : g_att_hi;
    const __nv_bfloat16* Al = (MODE == 0) ? g_x_lo : g_att_lo;
    const __nv_bfloat16* Bhp = (MODE == 0) ? g_wqkv_hi : g_wout_hi;
    const __nv_bfloat16* Blp = (MODE == 0) ? g_wqkv_lo : g_wout_lo;

    const int t = threadIdx.x, lane = t & 31, warp = t >> 5;
    const int wm = warp & 1, wn = warp >> 1;
    const int m0 = blockIdx.y * 128, n0 = blockIdx.x * 128;

    uint32_t ld_sm[4];
    size_t   ld_ga[4], ld_gb[4];
#pragma unroll
    for (int j = 0; j < 4; j++) {
        int c = t + 256 * j;
        int row = c >> 3, ch = c & 7;
        ld_sm[j] = (uint32_t)(row * 128 + ((ch ^ (row & 7)) << 4));
        ld_ga[j] = (size_t)(m0 + row) * 1024 + ch * 8;
        ld_gb[j] = (size_t)(n0 + row) * 1024 + ch * 8;
    }

    float acc[4][4][4];
#pragma unroll
    for (int mi = 0; mi < 4; mi++)
#pragma unroll
        for (int ni = 0; ni < 4; ni++)
#pragma unroll
            for (int q = 0; q < 4; q++) acc[mi][ni][q] = 0.f;

    const int a_rb = wm * 64 + (lane & 15);
    const int a_cb = (lane >> 4);
    const int b_rb = wn * 32 + ((lane >> 4) * 8) + (lane & 7);
    const int b_cb = (lane >> 3) & 1;

#define LOAD_STAGE(it, s) do {                                                  \
    uint32_t base = sb + (s) * STAGE_B;                                         \
    int k0 = (it) * 64;                                                         \
    _Pragma("unroll")                                                           \
    for (int j = 0; j < 4; j++) {                                               \
        CP_ASYNC16(base + 0 * TILE_B + ld_sm[j], Ah  + ld_ga[j] + k0);          \
        CP_ASYNC16(base + 1 * TILE_B + ld_sm[j], Al  + ld_ga[j] + k0);          \
        CP_ASYNC16(base + 2 * TILE_B + ld_sm[j], Bhp + ld_gb[j] + k0);          \
        CP_ASYNC16(base + 3 * TILE_B + ld_sm[j], Blp + ld_gb[j] + k0);          \
    }                                                                           \
    CP_COMMIT();                                                                \
} while (0)

    LOAD_STAGE(0, 0);
    LOAD_STAGE(1, 1);
    LOAD_STAGE(2, 2);

    int s = 0;
    for (int it = 0; it < 16; it++) {
        CP_WAIT2();
        __syncthreads();
        uint32_t base = sb + s * STAGE_B;

#pragma unroll
        for (int kk = 0; kk < 4; kk++) {
            uint32_t ah[4][4], al[4][4];
#pragma unroll
            for (int mi = 0; mi < 4; mi++) {
                int r = a_rb + mi * 16;
                int c = kk * 2 + a_cb;
                uint32_t addr = base + (uint32_t)(r * 128 + ((c ^ (r & 7)) << 4));
                ldsm_x4(ah[mi][0], ah[mi][1], ah[mi][2], ah[mi][3], addr);
                ldsm_x4(al[mi][0], al[mi][1], al[mi][2], al[mi][3], addr + TILE_B);
            }
            uint32_t bh[2][4], bl[2][4];
#pragma unroll
            for (int nh = 0; nh < 2; nh++) {
                int r = b_rb + nh * 16;
                int c = kk * 2 + b_cb;
                uint32_t addr = base + 2 * TILE_B + (uint32_t)(r * 128 + ((c ^ (r & 7)) << 4));
                ldsm_x4(bh[nh][0], bh[nh][1], bh[nh][2], bh[nh][3], addr);
                ldsm_x4(bl[nh][0], bl[nh][1], bl[nh][2], bl[nh][3], addr + TILE_B);
            }
#pragma unroll
            for (int mi = 0; mi < 4; mi++)
#pragma unroll
                for (int nh = 0; nh < 2; nh++)
#pragma unroll
                    for (int q = 0; q < 2; q++) {
                        float* d = acc[mi][nh * 2 + q];
                        mma_bf16(d, ah[mi], bh[nh][q * 2], bh[nh][q * 2 + 1]);
                        mma_bf16(d, ah[mi], bl[nh][q * 2], bl[nh][q * 2 + 1]);
                        mma_bf16(d, al[mi], bh[nh][q * 2], bh[nh][q * 2 + 1]);
                    }
        }
        __syncthreads();
        if (it + 3 < 16) LOAD_STAGE(it + 3, s);
        s = (s == 2) ? 0 : s + 1;
    }

    const int wnb = n0 + wn * 32;
    if (MODE == 0) {
        const int sIdx = wnb >> 10;
        const int h    = (wnb >> 6) & 15;
        const int dby  = (wnb & 63);
        __nv_bfloat16 *dh, *dl;
        if (sIdx == 0)      { dh = g_q_hi; dl = g_q_lo; }
        else if (sIdx == 1) { dh = g_k_hi; dl = g_k_lo; }
        else                { dh = g_v_hi; dl = g_v_lo; }
#pragma unroll
        for (int mi = 0; mi < 4; mi++)
#pragma unroll
            for (int half = 0; half < 2; half++) {
                int row = m0 + wm * 64 + mi * 16 + (lane >> 2) + half * 8;
                int b = row >> 10, l = row & 1023;
                size_t rbase = ((size_t)(b * H_ + h) * L_ + l) * HD;
#pragma unroll
                for (int ni = 0; ni < 4; ni++) {
                    int d = dby + ni * 8 + (lane & 3) * 2;
                    float v0 = acc[mi][ni][half * 2], v1 = acc[mi][ni][half * 2 + 1];
                    __nv_bfloat162 hh = __floats2bfloat162_rn(v0, v1);
                    float2 hf = __bfloat1622float2(hh);
                    __nv_bfloat162 ll = __floats2bfloat162_rn(v0 - hf.x, v1 - hf.y);
                    *(__nv_bfloat162*)&dh[rbase + d] = hh;
                    *(__nv_bfloat162*)&dl[rbase + d] = ll;
                }
            }
    } else {
#pragma unroll
        for (int mi = 0; mi < 4; mi++)
#pragma unroll
            for (int half = 0; half < 2; half++) {
                int row = m0 + wm * 64 + mi * 16 + (lane >> 2) + half * 8;
#pragma unroll
                for (int ni = 0; ni < 4; ni++) {
                    int n = wnb + ni * 8 + (lane & 3) * 2;
                    *(float2*)&C[(size_t)row * 1024 + n] =
                        make_float2(acc[mi][ni][half * 2], acc[mi][ni][half * 2 + 1]);
                }
            }
    }
#undef LOAD_STAGE
}

// ---------------------------------------------------------------------------
// Tensor-core attention v2: cp.async bf16 hi/lo staging, double-buffered K/V,
// trans-ldmatrix for V, fp32 softmax.  One block = (b,h) x 64-query tile.
// smem map (bytes):
//   [0      ) QH 8K (Q hi / P hi buf0)   [ 8192) QL 8K (Q lo / P lo buf0)
//   [16384  ) K0H 8K  [24576) K0L 8K  [32768) K1H 8K  [40960) K1L 8K
//   [49152  ) RH 16K (128 rows; P hi/lo buf1 reuses 49152/57344)
//   [65536  ) RL 16K
//   [81920  ) qE fp32 [64][80] 20K
//   [102400 ) S  fp32 [64][328] 82K      total 186368
// ---------------------------------------------------------------------------
#define OFF_QH   0
#define OFF_QL   8192
#define OFF_K0H  16384
#define OFF_K1H  32768
#define OFF_RH   49152
#define OFF_RL   65536
#define OFF_QE   81920
#define OFF_S    102400
#define ATT_SMEM (102400 + 83968)
#define SP 328
#define QEP 80

// issue one 64x64 bf16 tile pair (hi+lo) via cp.async (2 chunks/thread each)
__device__ __forceinline__ void issue_tile(uint32_t dsthi, uint32_t dstlo,
                                           const __nv_bfloat16* ghi,
                                           const __nv_bfloat16* glo,
                                           int rowbase, int t) {
#pragma unroll
    for (int j = 0; j < 2; j++) {
        int c = t + 256 * j;
        int row = c >> 3, ch = c & 7;
        uint32_t so = (uint32_t)(row * 128 + ((ch ^ (row & 7)) << 4));
        const __nv_bfloat16* gh = ghi + (size_t)(rowbase + row) * 64 + ch * 8;
        const __nv_bfloat16* gl = glo + (size_t)(rowbase + row) * 64 + ch * 8;
        CP_ASYNC16(dsthi + so, gh);
        CP_ASYNC16(dstlo + so, gl);
    }
}

__global__ void __launch_bounds__(256, 1) attn_mma(const float* __restrict__ rel_emb) {
    extern __shared__ char smc[];
    uint32_t sb = smem_u32(smc);
    float* Sf  = (float*)(smc + OFF_S);
    float* qEf = (float*)(smc + OFF_QE);

    const int t = threadIdx.x, lane = t & 31, warp = t >> 5;
    const int wm = warp & 1, wn = warp >> 1;
    const int qt0 = blockIdx.x * 64;
    const int bh  = blockIdx.y;
    const __nv_bfloat16* gqh = g_q_hi + (size_t)bh * L_ * HD;
    const __nv_bfloat16* gql = g_q_lo + (size_t)bh * L_ * HD;
    const __nv_bfloat16* gkh = g_k_hi + (size_t)bh * L_ * HD;
    const __nv_bfloat16* gkl = g_k_lo + (size_t)bh * L_ * HD;
    const __nv_bfloat16* gvh = g_v_hi + (size_t)bh * L_ * HD;
    const __nv_bfloat16* gvl = g_v_lo + (size_t)bh * L_ * HD;

    const int a_rb = wm * 32 + (lane & 15);
    const int a_cb = (lane >> 4);
    const int b_rb16 = wn * 16 + ((lane >> 4) * 8) + (lane & 7);
    const int b_cb = (lane >> 3) & 1;

    int first_kb = 4 - (int)blockIdx.x;
    if (first_kb < 0) first_kb = 0;

    // ---------- phase 0: async Q + first K; convert R ----------------------
    issue_tile(sb + OFF_QH, sb + OFF_QL, gqh, gql, qt0, t);
    CP_COMMIT();                                   // group: Q
    issue_tile(sb + OFF_K0H, sb + OFF_K0H + 8192, gkh, gkl,
               qt0 - 256 + first_kb * 64, t);
    CP_COMMIT();                                   // group: K(first)

    // zero R rows 65..127 (disjoint from fill -> no sync needed)
    for (int i = t; i < 63 * 8; i += 256) {        // 63 rows x 8 chunks of 16B
        int row = 65 + (i >> 3), ch = i & 7;
        uint32_t o = (uint32_t)(row * 128 + ch * 16);
        *(uint4*)(smc + OFF_RH + o) = make_uint4(0, 0, 0, 0);
        *(uint4*)(smc + OFF_RL + o) = make_uint4(0, 0, 0, 0);
    }
    // fill R rows 0..64 (fp32 -> hi/lo, swizzled)
    for (int idx = t; idx < 65 * 16; idx += 256) {
        int r = idx >> 4, c4 = idx & 15;
        float4 v = *(const float4*)&rel_emb[r * HD + c4 * 4];
        uint2 h, l;
        split4(v, h, l);
        uint32_t o = sw_off4(r, c4);
        *(uint2*)(smc + OFF_RH + o) = h;
        *(uint2*)(smc + OFF_RL + o) = l;
    }
    CP_WAIT1();          // Q landed (K may still be in flight)
    __syncthreads();

    // ---------- phase 1: qE = Q * R^T  (M=64, N=128 padded, K=64) ----------
    {
        float qa[2][2][2][4];
#pragma unroll
        for (int mi = 0; mi < 2; mi++)
#pragma unroll
            for (int nh = 0; nh < 2; nh++)
#pragma unroll
                for (int q = 0; q < 2; q++)
#pragma unroll
                    for (int e = 0; e < 4; e++) qa[mi][nh][q][e] = 0.f;

#pragma unroll
        for (int kk = 0; kk < 4; kk++) {
            uint32_t ah[2][4], al[2][4];
#pragma unroll
            for (int mi = 0; mi < 2; mi++) {
                int r = a_rb + mi * 16;
                int c = kk * 2 + a_cb;
                uint32_t addr = sb + (uint32_t)(r * 128 + ((c ^ (r & 7)) << 4));
                ldsm_x4(ah[mi][0], ah[mi][1], ah[mi][2], ah[mi][3], addr + OFF_QH);
                ldsm_x4(al[mi][0], al[mi][1], al[mi][2], al[mi][3], addr + OFF_QL);
            }
            uint32_t bh[2][4], bl[2][4];
#pragma unroll
            for (int nh = 0; nh < 2; nh++) {
                int r = wn * 32 + nh * 16 + ((lane >> 4) * 8) + (lane & 7);
                int c = kk * 2 + b_cb;
                uint32_t addr = sb + (uint32_t)(r * 128 + ((c ^ (r & 7)) << 4));
                ldsm_x4(bh[nh][0], bh[nh][1], bh[nh][2], bh[nh][3], addr + OFF_RH);
                ldsm_x4(bl[nh][0], bl[nh][1], bl[nh][2], bl[nh][3], addr + OFF_RL);
            }
#pragma unroll
            for (int mi = 0; mi < 2; mi++)
#pragma unroll
                for (int nh = 0; nh < 2; nh++)
#pragma unroll
                    for (int q = 0; q < 2; q++) {
                        float* d = qa[mi][nh][q];
                        mma_bf16(d, ah[mi], bh[nh][q * 2], bh[nh][q * 2 + 1]);
                        mma_bf16(d, ah[mi], bl[nh][q * 2], bl[nh][q * 2 + 1]);
                        mma_bf16(d, al[mi], bh[nh][q * 2], bh[nh][q * 2 + 1]);
                    }
        }
#pragma unroll
        for (int mi = 0; mi < 2; mi++)
#pragma unroll
            for (int nh = 0; nh < 2; nh++)
#pragma unroll
                for (int q = 0; q < 2; q++)
#pragma unroll
                    for (int half = 0; half < 2; half++) {
                        int row = wm * 32 + mi * 16 + (lane >> 2) + half * 8;
                        int col = wn * 32 + nh * 16 + q * 8 + (lane & 3) * 2;
                        if (col < 72) {
                            qEf[row * QEP + col]     = qa[mi][nh][q][half * 2];
                            qEf[row * QEP + col + 1] = qa[mi][nh][q][half * 2 + 1];
                        }
                    }
    }

    // fill masked (invalid) key blocks of S
    for (int kbk = 0; kbk < first_kb; kbk++)
        for (int e = t; e < 4096; e += 256)
            Sf[(e >> 6) * SP + kbk * 64 + (e & 63)] = -1e30f;

    // ---------- phase 2: scores, double-buffered K -------------------------
    for (int kbk = first_kb; kbk < 5; kbk++) {
        int kb0 = qt0 - 256 + kbk * 64;
        int bufi = (kbk - first_kb) & 1;
        uint32_t kbase = sb + OFF_K0H + bufi * 16384;

        CP_WAIT0();
        __syncthreads();          // K(kbk) visible; prior block's mma done
        if (kbk < 4) {
            issue_tile(sb + OFF_K0H + (1 - bufi) * 16384,
                       sb + OFF_K0H + (1 - bufi) * 16384 + 8192,
                       gkh, gkl, kb0 + 64, t);
            CP_COMMIT();
        }

        float sc[2][2][4];
#pragma unroll
        for (int mi = 0; mi < 2; mi++)
#pragma unroll
            for (int q = 0; q < 2; q++)
#pragma unroll
                for (int e = 0; e < 4; e++) sc[mi][q][e] = 0.f;

#pragma unroll
        for (int kk = 0; kk < 4; kk++) {
            uint32_t ah[2][4], al[2][4];
#pragma unroll
            for (int mi = 0; mi < 2; mi++) {
                int r = a_rb + mi * 16;
                int c = kk * 2 + a_cb;
                uint32_t addr = sb + (uint32_t)(r * 128 + ((c ^ (r & 7)) << 4));
                ldsm_x4(ah[mi][0], ah[mi][1], ah[mi][2], ah[mi][3], addr + OFF_QH);
                ldsm_x4(al[mi][0], al[mi][1], al[mi][2], al[mi][3], addr + OFF_QL);
            }
            uint32_t bh[4], bl[4];
            {
                int r = b_rb16;
                int c = kk * 2 + b_cb;
                uint32_t off = (uint32_t)(r * 128 + ((c ^ (r & 7)) << 4));
                ldsm_x4(bh[0], bh[1], bh[2], bh[3], kbase + off);
                ldsm_x4(bl[0], bl[1], bl[2], bl[3], kbase + 8192 + off);
            }
#pragma unroll
            for (int mi = 0; mi < 2; mi++)
#pragma unroll
                for (int q = 0; q < 2; q++) {
                    float* d = sc[mi][q];
                    mma_bf16(d, ah[mi], bh[q * 2], bh[q * 2 + 1]);
                    mma_bf16(d, ah[mi], bl[q * 2], bl[q * 2 + 1]);
                    mma_bf16(d, al[mi], bh[q * 2], bh[q * 2 + 1]);
                }
        }
        // epilogue: qE gather + mask + scale -> S
#pragma unroll
        for (int mi = 0; mi < 2; mi++)
#pragma unroll
            for (int q = 0; q < 2; q++)
#pragma unroll
                for (int half = 0; half < 2; half++)
#pragma unroll
                    for (int dd = 0; dd < 2; dd++) {
                        int row = wm * 32 + mi * 16 + (lane >> 2) + half * 8;
                        int col = wn * 16 + q * 8 + (lane & 3) * 2 + dd;
                        int i = qt0 + row, j = kb0 + col;
                        float val;
                        if (j > i || (i - j) >= 256) {
                            val = -1e30f;
                        } else {
                            int rel = j - i + 64;
                            if (rel < 0) rel = 0;
                            val = (sc[mi][q][half * 2 + dd] + qEf[row * QEP + rel]) * 0.125f;
                        }
                        Sf[row * SP + kbk * 64 + col] = val;
                    }
    }
    __syncthreads();     // all S written, all K mma done

    // prefetch first V block into buf0
    issue_tile(sb + OFF_K0H, sb + OFF_K0H + 8192, gvh, gvl,
               qt0 - 256 + first_kb * 64, t);
    CP_COMMIT();

    // ---------- phase 3: row softmax (fp32, 320 cols) ----------------------
    {
        for (int r = warp * 8; r < warp * 8 + 8; r++) {
            float mx = -1e30f;
            for (int c = lane; c < 320; c += 32) mx = fmaxf(mx, Sf[r * SP + c]);
#pragma unroll
            for (int o = 16; o > 0; o >>= 1)
                mx = fmaxf(mx, __shfl_xor_sync(0xffffffffu, mx, o));
            float sum = 0.f;
            for (int c = lane; c < 320; c += 32) {
                float p = __expf(Sf[r * SP + c] - mx);
                Sf[r * SP + c] = p;
                sum += p;
            }
#pragma unroll
            for (int o = 16; o > 0; o >>= 1)
                sum += __shfl_xor_sync(0xffffffffu, sum, o);
            float inv = 1.f / sum;
            for (int c = lane; c < 320; c += 32) Sf[r * SP + c] *= inv;
        }
    }
    __syncthreads();

    // ---------- phase 4: out = P * V, double-buffered V, trans-ldmatrix ----
    float oac[2][2][4];
#pragma unroll
    for (int mi = 0; mi < 2; mi++)
#pragma unroll
        for (int q = 0; q < 2; q++)
#pragma unroll
            for (int e = 0; e < 4; e++) oac[mi][q][e] = 0.f;

    for (int kbk = first_kb; kbk < 5; kbk++) {
        int kb0 = qt0 - 256 + kbk * 64;
        int bufi = (kbk - first_kb) & 1;
        uint32_t vbase = sb + OFF_K0H + bufi * 16384;
        int p_off = bufi ? OFF_RH : OFF_QH;      // P hi at p_off, lo at +8192

        CP_WAIT0();
        __syncthreads();          // V(kbk) visible; prior mma done; P buf free
        if (kbk < 4) {
            issue_tile(sb + OFF_K0H + (1 - bufi) * 16384,
                       sb + OFF_K0H + (1 - bufi) * 16384 + 8192,
                       gvh, gvl, kb0 + 64, t);
            CP_COMMIT();
        }

        // split P block (fp32 S -> bf16 hi/lo, swizzled)
        {
            int row = t >> 2;
            int cbq = (t & 3) * 4;
#pragma unroll
            for (int q4 = 0; q4 < 4; q4++) {
                int c4 = cbq + q4;
                float4 v = *(const float4*)&Sf[row * SP + kbk * 64 + c4 * 4];
                uint2 h, l;
                split4(v, h, l);
                uint32_t o = sw_off4(row, c4);
                *(uint2*)(smc + p_off + o) = h;
                *(uint2*)(smc + p_off + 8192 + o) = l;
            }
        }
        __syncthreads();          // P visible to all warps

#pragma unroll
        for (int kk = 0; kk < 4; kk++) {
            uint32_t ah[2][4], al[2][4];
#pragma unroll
            for (int mi = 0; mi < 2; mi++) {
                int r = a_rb + mi * 16;
                int c = kk * 2 + a_cb;
                uint32_t addr = sb + p_off + (uint32_t)(r * 128 + ((c ^ (r & 7)) << 4));
                ldsm_x4(ah[mi][0], ah[mi][1], ah[mi][2], ah[mi][3], addr);
                ldsm_x4(al[mi][0], al[mi][1], al[mi][2], al[mi][3], addr + 8192);
            }
            uint32_t bh[4], bl[4];
            {
                int vrow = kk * 16 + (lane & 7) + ((lane >> 3) & 1) * 8;
                int vch  = wn * 2 + (lane >> 4);
                uint32_t off = (uint32_t)(vrow * 128 + ((vch ^ (vrow & 7)) << 4));
                ldsm_x4_t(bh[0], bh[1], bh[2], bh[3], vbase + off);
                ldsm_x4_t(bl[0], bl[1], bl[2], bl[3], vbase + 8192 + off);
            }
#pragma unroll
            for (int mi = 0; mi < 2; mi++)
#pragma unroll
                for (int q = 0; q < 2; q++) {
                    float* d = oac[mi][q];
                    mma_bf16(d, ah[mi], bh[q * 2], bh[q * 2 + 1]);
                    mma_bf16(d, ah[mi], bl[q * 2], bl[q * 2 + 1]);
                    mma_bf16(d, al[mi], bh[q * 2], bh[q * 2 + 1]);
                }
        }
    }

    // ---------- epilogue: write att hi/lo in [B,L,H*hd] --------------------
    {
        int b = bh >> 4, h = bh & 15;
#pragma unroll
        for (int mi = 0; mi < 2; mi++)
#pragma unroll
            for (int q = 0; q < 2; q++)
#pragma unroll
                for (int half = 0; half < 2; half++) {
                    int row = wm * 32 + mi * 16 + (lane >> 2) + half * 8;
                    int i = qt0 + row;
                    int d = wn * 16 + q * 8 + (lane & 3) * 2;
                    float v0 = oac[mi][q][half * 2], v1 = oac[mi][q][half * 2 + 1];
                    __nv_bfloat162 hh = __floats2bfloat162_rn(v0, v1);
                    float2 hf = __bfloat1622float2(hh);
                    __nv_bfloat162 ll = __floats2bfloat162_rn(v0 - hf.x, v1 - hf.y);
                    size_t off = ((size_t)(b * L_ + i) * H_ + h) * HD + d;
                    *(__nv_bfloat162*)&g_att_hi[off] = hh;
                    *(__nv_bfloat162*)&g_att_lo[off] = ll;
                }
    }
}

// ---------------------------------------------------------------------------
extern "C" void kernel_launch(void* const* d_in, const int* in_sizes, int n_in,
                              void* d_out, int out_size) {
    const float* x       = (const float*)d_in[0];
    const float* w_qkv   = (const float*)d_in[1];
    const float* w_out   = (const float*)d_in[2];
    const float* rel_emb = (const float*)d_in[3];
    float* out = (float*)d_out;

    (void)in_sizes; (void)n_in; (void)out_size;

    cudaFuncSetAttribute(attn_mma,
                         cudaFuncAttributeMaxDynamicSharedMemorySize, ATT_SMEM);
    cudaFuncSetAttribute(tc_gemm<0>,
                         cudaFuncAttributeMaxDynamicSharedMemorySize, TC_SMEM);
    cudaFuncSetAttribute(tc_gemm<1>,
                         cudaFuncAttributeMaxDynamicSharedMemorySize, TC_SMEM);

    cvt_split<0><<<(B_ * L_ * D_ / 4 + 255) / 256, 256>>>(x,    B_ * L_ * D_ / 4);
    cvt_split<1><<<(3 * D_ * D_ / 4 + 255) / 256, 256>>>(w_qkv, 3 * D_ * D_ / 4);
    cvt_split<2><<<(D_ * D_ / 4 + 255) / 256, 256>>>(w_out,     D_ * D_ / 4);

    tc_gemm<0><<<dim3(3072 / 128, 4096 / 128), 256, TC_SMEM>>>(nullptr);

    attn_mma<<<dim3(L_ / 64, NBH), 256, ATT_SMEM>>>(rel_emb);

    tc_gemm<1><<<dim3(1024 / 128, 4096 / 128), 256, TC_SMEM>>>(out);
}

// round 9
// speedup vs baseline: 2.8903x; 1.0237x over previous
#include <cuda_runtime.h>
#include <cuda_bf16.h>
#include <cstdint>

#define B_  4
#define L_  1024
#define D_  1024
#define H_  16
#define HD  64
#define NBH (B_ * H_)   // 64

// ---------------------------------------------------------------------------
// Static device scratch (no allocation allowed)
// ---------------------------------------------------------------------------
__device__ __nv_bfloat16 g_q_hi[NBH * L_ * HD];
__device__ __nv_bfloat16 g_q_lo[NBH * L_ * HD];
__device__ __nv_bfloat16 g_k_hi[NBH * L_ * HD];
__device__ __nv_bfloat16 g_k_lo[NBH * L_ * HD];
__device__ __nv_bfloat16 g_v_hi[NBH * L_ * HD];
__device__ __nv_bfloat16 g_v_lo[NBH * L_ * HD];

__device__ __nv_bfloat16 g_x_hi[B_ * L_ * D_];
__device__ __nv_bfloat16 g_x_lo[B_ * L_ * D_];
__device__ __nv_bfloat16 g_wqkv_hi[3 * D_ * D_];
__device__ __nv_bfloat16 g_wqkv_lo[3 * D_ * D_];
__device__ __nv_bfloat16 g_wout_hi[D_ * D_];
__device__ __nv_bfloat16 g_wout_lo[D_ * D_];
__device__ __nv_bfloat16 g_att_hi[B_ * L_ * D_];
__device__ __nv_bfloat16 g_att_lo[B_ * L_ * D_];

// ---------------------------------------------------------------------------
// PTX helpers (base ISA only)
// ---------------------------------------------------------------------------
__device__ __forceinline__ uint32_t smem_u32(const void* p) {
    uint32_t a;
    asm("{ .reg .u64 t; cvta.to.shared.u64 t, %1; cvt.u32.u64 %0, t; }" : "=r"(a) : "l"(p));
    return a;
}

#define CP_ASYNC16(dst, src) \
    asm volatile("cp.async.cg.shared.global [%0], [%1], 16;" :: "r"(dst), "l"(src))
#define CP_COMMIT() asm volatile("cp.async.commit_group;" ::: "memory")
#define CP_WAIT0()  asm volatile("cp.async.wait_group 0;" ::: "memory")
#define CP_WAIT1()  asm volatile("cp.async.wait_group 1;" ::: "memory")

__device__ __forceinline__ void ldsm_x4(uint32_t& r0, uint32_t& r1, uint32_t& r2,
                                        uint32_t& r3, uint32_t addr) {
    asm volatile("ldmatrix.sync.aligned.m8n8.x4.shared.b16 {%0,%1,%2,%3}, [%4];"
                 : "=r"(r0), "=r"(r1), "=r"(r2), "=r"(r3) : "r"(addr));
}
__device__ __forceinline__ void ldsm_x4_t(uint32_t& r0, uint32_t& r1, uint32_t& r2,
                                          uint32_t& r3, uint32_t addr) {
    asm volatile("ldmatrix.sync.aligned.m8n8.x4.trans.shared.b16 {%0,%1,%2,%3}, [%4];"
                 : "=r"(r0), "=r"(r1), "=r"(r2), "=r"(r3) : "r"(addr));
}

__device__ __forceinline__ void mma_bf16(float* d, const uint32_t* a,
                                         uint32_t b0, uint32_t b1) {
    asm volatile(
        "mma.sync.aligned.m16n8k16.row.col.f32.bf16.bf16.f32 "
        "{%0,%1,%2,%3}, {%4,%5,%6,%7}, {%8,%9}, {%0,%1,%2,%3};"
        : "+f"(d[0]), "+f"(d[1]), "+f"(d[2]), "+f"(d[3])
        : "r"(a[0]), "r"(a[1]), "r"(a[2]), "r"(a[3]), "r"(b0), "r"(b1));
}

// split fp32x4 -> two packed bf16x4 (hi, lo)
__device__ __forceinline__ void split4(float4 v, uint2& h, uint2& l) {
    __nv_bfloat162 h01 = __floats2bfloat162_rn(v.x, v.y);
    __nv_bfloat162 h23 = __floats2bfloat162_rn(v.z, v.w);
    float2 f01 = __bfloat1622float2(h01);
    float2 f23 = __bfloat1622float2(h23);
    __nv_bfloat162 l01 = __floats2bfloat162_rn(v.x - f01.x, v.y - f01.y);
    __nv_bfloat162 l23 = __floats2bfloat162_rn(v.z - f23.x, v.w - f23.y);
    h = make_uint2(*(uint32_t*)&h01, *(uint32_t*)&h23);
    l = make_uint2(*(uint32_t*)&l01, *(uint32_t*)&l23);
}

// swizzled byte offset of float4-chunk c4 in a 128B-row bf16 tile
__device__ __forceinline__ uint32_t sw_off4(int row, int c4) {
    return (uint32_t)(row * 128 + ((((c4 >> 1) ^ (row & 7)) << 4) | ((c4 & 1) << 3)));
}

// ---------------------------------------------------------------------------
// fp32 -> bf16 hi/lo split conversion.  W: 0=x, 1=wqkv, 2=wout
// ---------------------------------------------------------------------------
template <int W>
__global__ void __launch_bounds__(256) cvt_split(const float* __restrict__ src, int n4) {
    __nv_bfloat16* hi = (W == 0) ? g_x_hi : (W == 1) ? g_wqkv_hi : g_wout_hi;
    __nv_bfloat16* lo = (W == 0) ? g_x_lo : (W == 1) ? g_wqkv_lo : g_wout_lo;

    int i = blockIdx.x * 256 + threadIdx.x;
    if (i >= n4) return;
    float4 v = ((const float4*)src)[i];
    uint2 h, l;
    split4(v, h, l);
    ((uint2*)hi)[i] = h;
    ((uint2*)lo)[i] = l;
}

// ---------------------------------------------------------------------------
// Warp-mma split-bf16 GEMM NT v2: CTA tile 128x256, warp tile 64x64 (2m x 4n),
// K staged by 64, 2-stage cp.async, ONE __syncthreads per K-iter.
// MODE 0: A=x, B=w_qkv -> scatter bf16 hi/lo q/k/v.  MODE 1: A=att -> C fp32.
// ---------------------------------------------------------------------------
#define AT_B  16384                 // A tile (128x64 bf16)
#define BT_B  32768                 // B tile (256x64 bf16)
#define STG_B (2 * AT_B + 2 * BT_B) // 98304 per stage (Ah|Al|Bh|Bl)
#define TC_SMEM (2 * STG_B)         // 196608

template <int MODE>
__global__ void __launch_bounds__(256, 1) tc_gemm(float* __restrict__ C) {
    extern __shared__ char smc[];
    uint32_t sb = smem_u32(smc);

    const __nv_bfloat16* Ah  = (MODE == 0) ? g_x_hi : g_att_hi;
    const __nv_bfloat16* Al  = (MODE == 0) ? g_x_lo : g_att_lo;
    const __nv_bfloat16* Bhp = (MODE == 0) ? g_wqkv_hi : g_wout_hi;
    const __nv_bfloat16* Blp = (MODE == 0) ? g_wqkv_lo : g_wout_lo;

    const int t = threadIdx.x, lane = t & 31, warp = t >> 5;
    const int wm = warp & 1, wn = warp >> 1;          // wn in 0..3 (64 cols each)
    const int m0 = blockIdx.y * 128, n0 = blockIdx.x * 256;

    float acc[4][4][2][4];
#pragma unroll
    for (int mi = 0; mi < 4; mi++)
#pragma unroll
        for (int nh = 0; nh < 4; nh++)
#pragma unroll
            for (int q = 0; q < 2; q++)
#pragma unroll
                for (int e = 0; e < 4; e++) acc[mi][nh][q][e] = 0.f;

    const int a_rb = wm * 64 + (lane & 15);
    const int a_cb = (lane >> 4);
    const int b_cb = (lane >> 3) & 1;

#define LOAD_STAGE(it, s) do {                                                   \
    uint32_t base = sb + (s) * STG_B;                                            \
    int k0 = (it) * 64;                                                          \
    _Pragma("unroll")                                                            \
    for (int j = 0; j < 4; j++) {                                                \
        int c = t + 256 * j;                                                     \
        int row = c >> 3, ch = c & 7;                                            \
        uint32_t so = (uint32_t)(row * 128 + ((ch ^ (row & 7)) << 4));           \
        size_t g = (size_t)(m0 + row) * 1024 + ch * 8 + k0;                      \
        CP_ASYNC16(base + so, Ah + g);                                           \
        CP_ASYNC16(base + AT_B + so, Al + g);                                    \
    }                                                                            \
    _Pragma("unroll")                                                            \
    for (int j = 0; j < 8; j++) {                                                \
        int c = t + 256 * j;                                                     \
        int row = c >> 3, ch = c & 7;                                            \
        uint32_t so = (uint32_t)(row * 128 + ((ch ^ (row & 7)) << 4));           \
        size_t g = (size_t)(n0 + row) * 1024 + ch * 8 + k0;                      \
        CP_ASYNC16(base + 2 * AT_B + so, Bhp + g);                               \
        CP_ASYNC16(base + 2 * AT_B + BT_B + so, Blp + g);                        \
    }                                                                            \
    CP_COMMIT();                                                                 \
} while (0)

    LOAD_STAGE(0, 0);

    for (int it = 0; it < 16; it++) {
        int s = it & 1;
        CP_WAIT0();               // own copies of stage s done
        __syncthreads();          // everyone's copies visible; stage s^1 free
        if (it + 1 < 16) LOAD_STAGE(it + 1, s ^ 1);
        uint32_t base = sb + s * STG_B;

#pragma unroll
        for (int kk = 0; kk < 4; kk++) {
            uint32_t ah[4][4], al[4][4];
#pragma unroll
            for (int mi = 0; mi < 4; mi++) {
                int r = a_rb + mi * 16;
                int c2 = kk * 2 + a_cb;
                uint32_t addr = base + (uint32_t)(r * 128 + ((c2 ^ (r & 7)) << 4));
                ldsm_x4(ah[mi][0], ah[mi][1], ah[mi][2], ah[mi][3], addr);
                ldsm_x4(al[mi][0], al[mi][1], al[mi][2], al[mi][3], addr + AT_B);
            }
#pragma unroll
            for (int nh = 0; nh < 4; nh++) {
                int r = wn * 64 + nh * 16 + ((lane >> 4) * 8) + (lane & 7);
                int c2 = kk * 2 + b_cb;
                uint32_t addr = base + 2 * AT_B
                              + (uint32_t)(r * 128 + ((c2 ^ (r & 7)) << 4));
                uint32_t bh[4], bl[4];
                ldsm_x4(bh[0], bh[1], bh[2], bh[3], addr);
                ldsm_x4(bl[0], bl[1], bl[2], bl[3], addr + BT_B);
#pragma unroll
                for (int mi = 0; mi < 4; mi++)
#pragma unroll
                    for (int q = 0; q < 2; q++) {
                        float* d = acc[mi][nh][q];
                        mma_bf16(d, ah[mi], bh[q * 2], bh[q * 2 + 1]);
                        mma_bf16(d, ah[mi], bl[q * 2], bl[q * 2 + 1]);
                        mma_bf16(d, al[mi], bh[q * 2], bh[q * 2 + 1]);
                    }
            }
        }
    }

    // ---------------- epilogue -------------------------------------------
    const int wnb = n0 + wn * 64;                 // multiple of 64
    if (MODE == 0) {
        const int sIdx = wnb >> 10;
        const int h    = (wnb >> 6) & 15;
        __nv_bfloat16 *dh, *dl;
        if (sIdx == 0)      { dh = g_q_hi; dl = g_q_lo; }
        else if (sIdx == 1) { dh = g_k_hi; dl = g_k_lo; }
        else                { dh = g_v_hi; dl = g_v_lo; }
#pragma unroll
        for (int mi = 0; mi < 4; mi++)
#pragma unroll
            for (int half = 0; half < 2; half++) {
                int row = m0 + wm * 64 + mi * 16 + (lane >> 2) + half * 8;
                int b = row >> 10, l = row & 1023;
                size_t rbase = ((size_t)(b * H_ + h) * L_ + l) * HD;
#pragma unroll
                for (int nh = 0; nh < 4; nh++)
#pragma unroll
                    for (int q = 0; q < 2; q++) {
                        int d = nh * 16 + q * 8 + (lane & 3) * 2;
                        float v0 = acc[mi][nh][q][half * 2];
                        float v1 = acc[mi][nh][q][half * 2 + 1];
                        __nv_bfloat162 hh = __floats2bfloat162_rn(v0, v1);
                        float2 hf = __bfloat1622float2(hh);
                        __nv_bfloat162 ll = __floats2bfloat162_rn(v0 - hf.x, v1 - hf.y);
                        *(__nv_bfloat162*)&dh[rbase + d] = hh;
                        *(__nv_bfloat162*)&dl[rbase + d] = ll;
                    }
            }
    } else {
#pragma unroll
        for (int mi = 0; mi < 4; mi++)
#pragma unroll
            for (int half = 0; half < 2; half++) {
                int row = m0 + wm * 64 + mi * 16 + (lane >> 2) + half * 8;
#pragma unroll
                for (int nh = 0; nh < 4; nh++)
#pragma unroll
                    for (int q = 0; q < 2; q++) {
                        int n = wnb + nh * 16 + q * 8 + (lane & 3) * 2;
                        *(float2*)&C[(size_t)row * 1024 + n] =
                            make_float2(acc[mi][nh][q][half * 2],
                                        acc[mi][nh][q][half * 2 + 1]);
                    }
            }
    }
#undef LOAD_STAGE
}

// ---------------------------------------------------------------------------
// Tensor-core attention (R7 layout; phase 4 one sync per key block)
// ---------------------------------------------------------------------------
#define OFF_QH   0
#define OFF_QL   8192
#define OFF_K0H  16384
#define OFF_K1H  32768
#define OFF_RH   49152
#define OFF_RL   65536
#define OFF_QE   81920
#define OFF_S    102400
#define ATT_SMEM (102400 + 83968)
#define SP 328
#define QEP 80

__device__ __forceinline__ void issue_tile(uint32_t dsthi, uint32_t dstlo,
                                           const __nv_bfloat16* ghi,
                                           const __nv_bfloat16* glo,
                                           int rowbase, int t) {
#pragma unroll
    for (int j = 0; j < 2; j++) {
        int c = t + 256 * j;
        int row = c >> 3, ch = c & 7;
        uint32_t so = (uint32_t)(row * 128 + ((ch ^ (row & 7)) << 4));
        const __nv_bfloat16* gh = ghi + (size_t)(rowbase + row) * 64 + ch * 8;
        const __nv_bfloat16* gl = glo + (size_t)(rowbase + row) * 64 + ch * 8;
        CP_ASYNC16(dsthi + so, gh);
        CP_ASYNC16(dstlo + so, gl);
    }
}

__global__ void __launch_bounds__(256, 1) attn_mma(const float* __restrict__ rel_emb) {
    extern __shared__ char smc[];
    uint32_t sb = smem_u32(smc);
    float* Sf  = (float*)(smc + OFF_S);
    float* qEf = (float*)(smc + OFF_QE);

    const int t = threadIdx.x, lane = t & 31, warp = t >> 5;
    const int wm = warp & 1, wn = warp >> 1;
    const int qt0 = blockIdx.x * 64;
    const int bh  = blockIdx.y;
    const __nv_bfloat16* gqh = g_q_hi + (size_t)bh * L_ * HD;
    const __nv_bfloat16* gql = g_q_lo + (size_t)bh * L_ * HD;
    const __nv_bfloat16* gkh = g_k_hi + (size_t)bh * L_ * HD;
    const __nv_bfloat16* gkl = g_k_lo + (size_t)bh * L_ * HD;
    const __nv_bfloat16* gvh = g_v_hi + (size_t)bh * L_ * HD;
    const __nv_bfloat16* gvl = g_v_lo + (size_t)bh * L_ * HD;

    const int a_rb = wm * 32 + (lane & 15);
    const int a_cb = (lane >> 4);
    const int b_rb16 = wn * 16 + ((lane >> 4) * 8) + (lane & 7);
    const int b_cb = (lane >> 3) & 1;

    int first_kb = 4 - (int)blockIdx.x;
    if (first_kb < 0) first_kb = 0;

    // ---------- phase 0: async Q + first K; convert R ----------------------
    issue_tile(sb + OFF_QH, sb + OFF_QL, gqh, gql, qt0, t);
    CP_COMMIT();
    issue_tile(sb + OFF_K0H, sb + OFF_K0H + 8192, gkh, gkl,
               qt0 - 256 + first_kb * 64, t);
    CP_COMMIT();

    for (int i = t; i < 63 * 8; i += 256) {
        int row = 65 + (i >> 3), ch = i & 7;
        uint32_t o = (uint32_t)(row * 128 + ch * 16);
        *(uint4*)(smc + OFF_RH + o) = make_uint4(0, 0, 0, 0);
        *(uint4*)(smc + OFF_RL + o) = make_uint4(0, 0, 0, 0);
    }
    for (int idx = t; idx < 65 * 16; idx += 256) {
        int r = idx >> 4, c4 = idx & 15;
        float4 v = *(const float4*)&rel_emb[r * HD + c4 * 4];
        uint2 h, l;
        split4(v, h, l);
        uint32_t o = sw_off4(r, c4);
        *(uint2*)(smc + OFF_RH + o) = h;
        *(uint2*)(smc + OFF_RL + o) = l;
    }
    CP_WAIT1();
    __syncthreads();

    // ---------- phase 1: qE = Q * R^T --------------------------------------
    {
        float qa[2][2][2][4];
#pragma unroll
        for (int mi = 0; mi < 2; mi++)
#pragma unroll
            for (int nh = 0; nh < 2; nh++)
#pragma unroll
                for (int q = 0; q < 2; q++)
#pragma unroll
                    for (int e = 0; e < 4; e++) qa[mi][nh][q][e] = 0.f;

#pragma unroll
        for (int kk = 0; kk < 4; kk++) {
            uint32_t ah[2][4], al[2][4];
#pragma unroll
            for (int mi = 0; mi < 2; mi++) {
                int r = a_rb + mi * 16;
                int c = kk * 2 + a_cb;
                uint32_t addr = sb + (uint32_t)(r * 128 + ((c ^ (r & 7)) << 4));
                ldsm_x4(ah[mi][0], ah[mi][1], ah[mi][2], ah[mi][3], addr + OFF_QH);
                ldsm_x4(al[mi][0], al[mi][1], al[mi][2], al[mi][3], addr + OFF_QL);
            }
            uint32_t bh[2][4], bl[2][4];
#pragma unroll
            for (int nh = 0; nh < 2; nh++) {
                int r = wn * 32 + nh * 16 + ((lane >> 4) * 8) + (lane & 7);
                int c = kk * 2 + b_cb;
                uint32_t addr = sb + (uint32_t)(r * 128 + ((c ^ (r & 7)) << 4));
                ldsm_x4(bh[nh][0], bh[nh][1], bh[nh][2], bh[nh][3], addr + OFF_RH);
                ldsm_x4(bl[nh][0], bl[nh][1], bl[nh][2], bl[nh][3], addr + OFF_RL);
            }
#pragma unroll
            for (int mi = 0; mi < 2; mi++)
#pragma unroll
                for (int nh = 0; nh < 2; nh++)
#pragma unroll
                    for (int q = 0; q < 2; q++) {
                        float* d = qa[mi][nh][q];
                        mma_bf16(d, ah[mi], bh[nh][q * 2], bh[nh][q * 2 + 1]);
                        mma_bf16(d, ah[mi], bl[nh][q * 2], bl[nh][q * 2 + 1]);
                        mma_bf16(d, al[mi], bh[nh][q * 2], bh[nh][q * 2 + 1]);
                    }
        }
#pragma unroll
        for (int mi = 0; mi < 2; mi++)
#pragma unroll
            for (int nh = 0; nh < 2; nh++)
#pragma unroll
                for (int q = 0; q < 2; q++)
#pragma unroll
                    for (int half = 0; half < 2; half++) {
                        int row = wm * 32 + mi * 16 + (lane >> 2) + half * 8;
                        int col = wn * 32 + nh * 16 + q * 8 + (lane & 3) * 2;
                        if (col < 72) {
                            qEf[row * QEP + col]     = qa[mi][nh][q][half * 2];
                            qEf[row * QEP + col + 1] = qa[mi][nh][q][half * 2 + 1];
                        }
                    }
    }

    for (int kbk = 0; kbk < first_kb; kbk++)
        for (int e = t; e < 4096; e += 256)
            Sf[(e >> 6) * SP + kbk * 64 + (e & 63)] = -1e30f;

    // ---------- phase 2: scores, double-buffered K (1 sync / block) --------
    for (int kbk = first_kb; kbk < 5; kbk++) {
        int kb0 = qt0 - 256 + kbk * 64;
        int bufi = (kbk - first_kb) & 1;
        uint32_t kbase = sb + OFF_K0H + bufi * 16384;

        CP_WAIT0();
        __syncthreads();
        if (kbk < 4) {
            issue_tile(sb + OFF_K0H + (1 - bufi) * 16384,
                       sb + OFF_K0H + (1 - bufi) * 16384 + 8192,
                       gkh, gkl, kb0 + 64, t);
            CP_COMMIT();
        }

        float sc[2][2][4];
#pragma unroll
        for (int mi = 0; mi < 2; mi++)
#pragma unroll
            for (int q = 0; q < 2; q++)
#pragma unroll
                for (int e = 0; e < 4; e++) sc[mi][q][e] = 0.f;

#pragma unroll
        for (int kk = 0; kk < 4; kk++) {
            uint32_t ah[2][4], al[2][4];
#pragma unroll
            for (int mi = 0; mi < 2; mi++) {
                int r = a_rb + mi * 16;
                int c = kk * 2 + a_cb;
                uint32_t addr = sb + (uint32_t)(r * 128 + ((c ^ (r & 7)) << 4));
                ldsm_x4(ah[mi][0], ah[mi][1], ah[mi][2], ah[mi][3], addr + OFF_QH);
                ldsm_x4(al[mi][0], al[mi][1], al[mi][2], al[mi][3], addr + OFF_QL);
            }
            uint32_t bh[4], bl[4];
            {
                int r = b_rb16;
                int c = kk * 2 + b_cb;
                uint32_t off = (uint32_t)(r * 128 + ((c ^ (r & 7)) << 4));
                ldsm_x4(bh[0], bh[1], bh[2], bh[3], kbase + off);
                ldsm_x4(bl[0], bl[1], bl[2], bl[3], kbase + 8192 + off);
            }
#pragma unroll
            for (int mi = 0; mi < 2; mi++)
#pragma unroll
                for (int q = 0; q < 2; q++) {
                    float* d = sc[mi][q];
                    mma_bf16(d, ah[mi], bh[q * 2], bh[q * 2 + 1]);
                    mma_bf16(d, ah[mi], bl[q * 2], bl[q * 2 + 1]);
                    mma_bf16(d, al[mi], bh[q * 2], bh[q * 2 + 1]);
                }
        }
#pragma unroll
        for (int mi = 0; mi < 2; mi++)
#pragma unroll
            for (int q = 0; q < 2; q++)
#pragma unroll
                for (int half = 0; half < 2; half++)
#pragma unroll
                    for (int dd = 0; dd < 2; dd++) {
                        int row = wm * 32 + mi * 16 + (lane >> 2) + half * 8;
                        int col = wn * 16 + q * 8 + (lane & 3) * 2 + dd;
                        int i = qt0 + row, j = kb0 + col;
                        float val;
                        if (j > i || (i - j) >= 256) {
                            val = -1e30f;
                        } else {
                            int rel = j - i + 64;
                            if (rel < 0) rel = 0;
                            val = (sc[mi][q][half * 2 + dd] + qEf[row * QEP + rel]) * 0.125f;
                        }
                        Sf[row * SP + kbk * 64 + col] = val;
                    }
    }
    __syncthreads();

    // prefetch first V block into buf0
    issue_tile(sb + OFF_K0H, sb + OFF_K0H + 8192, gvh, gvl,
               qt0 - 256 + first_kb * 64, t);
    CP_COMMIT();

    // ---------- phase 3: row softmax (fp32, 320 cols) ----------------------
    {
        for (int r = warp * 8; r < warp * 8 + 8; r++) {
            float mx = -1e30f;
            for (int c = lane; c < 320; c += 32) mx = fmaxf(mx, Sf[r * SP + c]);
#pragma unroll
            for (int o = 16; o > 0; o >>= 1)
                mx = fmaxf(mx, __shfl_xor_sync(0xffffffffu, mx, o));
            float sum = 0.f;
            for (int c = lane; c < 320; c += 32) {
                float p = __expf(Sf[r * SP + c] - mx);
                Sf[r * SP + c] = p;
                sum += p;
            }
#pragma unroll
            for (int o = 16; o > 0; o >>= 1)
                sum += __shfl_xor_sync(0xffffffffu, sum, o);
            float inv = 1.f / sum;
            for (int c = lane; c < 320; c += 32) Sf[r * SP + c] *= inv;
        }
    }
    __syncthreads();

    // ---------- phase 4: out = P * V (ONE sync per block) ------------------
    float oac[2][2][4];
#pragma unroll
    for (int mi = 0; mi < 2; mi++)
#pragma unroll
        for (int q = 0; q < 2; q++)
#pragma unroll
            for (int e = 0; e < 4; e++) oac[mi][q][e] = 0.f;

    for (int kbk = first_kb; kbk < 5; kbk++) {
        int kb0 = qt0 - 256 + kbk * 64;
        int bufi = (kbk - first_kb) & 1;
        uint32_t vbase = sb + OFF_K0H + bufi * 16384;
        int p_off = bufi ? OFF_RH : OFF_QH;

        // split P(kbk) first (own buffer free; overlaps V flight)
        {
            int row = t >> 2;
            int cbq = (t & 3) * 4;
#pragma unroll
            for (int q4 = 0; q4 < 4; q4++) {
                int c4 = cbq + q4;
                float4 v = *(const float4*)&Sf[row * SP + kbk * 64 + c4 * 4];
                uint2 h, l;
                split4(v, h, l);
                uint32_t o = sw_off4(row, c4);
                *(uint2*)(smc + p_off + o) = h;
                *(uint2*)(smc + p_off + 8192 + o) = l;
            }
        }
        CP_WAIT0();
        __syncthreads();          // P + V visible; prior mma done
        if (kbk < 4) {
            issue_tile(sb + OFF_K0H + (1 - bufi) * 16384,
                       sb + OFF_K0H + (1 - bufi) * 16384 + 8192,
                       gvh, gvl, kb0 + 64, t);
            CP_COMMIT();
        }

#pragma unroll
        for (int kk = 0; kk < 4; kk++) {
            uint32_t ah[2][4], al[2][4];
#pragma unroll
            for (int mi = 0; mi < 2; mi++) {
                int r = a_rb + mi * 16;
                int c = kk * 2 + a_cb;
                uint32_t addr = sb + p_off + (uint32_t)(r * 128 + ((c ^ (r & 7)) << 4));
                ldsm_x4(ah[mi][0], ah[mi][1], ah[mi][2], ah[mi][3], addr);
                ldsm_x4(al[mi][0], al[mi][1], al[mi][2], al[mi][3], addr + 8192);
            }
            uint32_t bh[4], bl[4];
            {
                int vrow = kk * 16 + (lane & 7) + ((lane >> 3) & 1) * 8;
                int vch  = wn * 2 + (lane >> 4);
                uint32_t off = (uint32_t)(vrow * 128 + ((vch ^ (vrow & 7)) << 4));
                ldsm_x4_t(bh[0], bh[1], bh[2], bh[3], vbase + off);
                ldsm_x4_t(bl[0], bl[1], bl[2], bl[3], vbase + 8192 + off);
            }
#pragma unroll
            for (int mi = 0; mi < 2; mi++)
#pragma unroll
                for (int q = 0; q < 2; q++) {
                    float* d = oac[mi][q];
                    mma_bf16(d, ah[mi], bh[q * 2], bh[q * 2 + 1]);
                    mma_bf16(d, ah[mi], bl[q * 2], bl[q * 2 + 1]);
                    mma_bf16(d, al[mi], bh[q * 2], bh[q * 2 + 1]);
                }
        }
    }

    // ---------- epilogue ---------------------------------------------------
    {
        int b = bh >> 4, h = bh & 15;
#pragma unroll
        for (int mi = 0; mi < 2; mi++)
#pragma unroll
            for (int q = 0; q < 2; q++)
#pragma unroll
                for (int half = 0; half < 2; half++) {
                    int row = wm * 32 + mi * 16 + (lane >> 2) + half * 8;
                    int i = qt0 + row;
                    int d = wn * 16 + q * 8 + (lane & 3) * 2;
                    float v0 = oac[mi][q][half * 2], v1 = oac[mi][q][half * 2 + 1];
                    __nv_bfloat162 hh = __floats2bfloat162_rn(v0, v1);
                    float2 hf = __bfloat1622float2(hh);
                    __nv_bfloat162 ll = __floats2bfloat162_rn(v0 - hf.x, v1 - hf.y);
                    size_t off = ((size_t)(b * L_ + i) * H_ + h) * HD + d;
                    *(__nv_bfloat162*)&g_att_hi[off] = hh;
                    *(__nv_bfloat162*)&g_att_lo[off] = ll;
                }
    }
}

// ---------------------------------------------------------------------------
extern "C" void kernel_launch(void* const* d_in, const int* in_sizes, int n_in,
                              void* d_out, int out_size) {
    const float* x       = (const float*)d_in[0];
    const float* w_qkv   = (const float*)d_in[1];
    const float* w_out   = (const float*)d_in[2];
    const float* rel_emb = (const float*)d_in[3];
    float* out = (float*)d_out;

    (void)in_sizes; (void)n_in; (void)out_size;

    cudaFuncSetAttribute(attn_mma,
                         cudaFuncAttributeMaxDynamicSharedMemorySize, ATT_SMEM);
    cudaFuncSetAttribute(tc_gemm<0>,
                         cudaFuncAttributeMaxDynamicSharedMemorySize, TC_SMEM);
    cudaFuncSetAttribute(tc_gemm<1>,
                         cudaFuncAttributeMaxDynamicSharedMemorySize, TC_SMEM);

    cvt_split<0><<<(B_ * L_ * D_ / 4 + 255) / 256, 256>>>(x,    B_ * L_ * D_ / 4);
    cvt_split<1><<<(3 * D_ * D_ / 4 + 255) / 256, 256>>>(w_qkv, 3 * D_ * D_ / 4);
    cvt_split<2><<<(D_ * D_ / 4 + 255) / 256, 256>>>(w_out,     D_ * D_ / 4);

    tc_gemm<0><<<dim3(3072 / 256, 4096 / 128), 256, TC_SMEM>>>(nullptr);

    attn_mma<<<dim3(L_ / 64, NBH), 256, ATT_SMEM>>>(rel_emb);

    tc_gemm<1><<<dim3(1024 / 256, 4096 / 128), 256, TC_SMEM>>>(out);
}

// round 10
// speedup vs baseline: 2.9008x; 1.0037x over previous
#include <cuda_runtime.h>
#include <cuda_bf16.h>
#include <cstdint>

#define B_  4
#define L_  1024
#define D_  1024
#define H_  16
#define HD  64
#define NBH (B_ * H_)   // 64

// ---------------------------------------------------------------------------
// Static device scratch (no allocation allowed)
// ---------------------------------------------------------------------------
__device__ __nv_bfloat16 g_q_hi[NBH * L_ * HD];
__device__ __nv_bfloat16 g_q_lo[NBH * L_ * HD];
__device__ __nv_bfloat16 g_k_hi[NBH * L_ * HD];
__device__ __nv_bfloat16 g_k_lo[NBH * L_ * HD];
__device__ __nv_bfloat16 g_v_hi[NBH * L_ * HD];
__device__ __nv_bfloat16 g_v_lo[NBH * L_ * HD];

__device__ __nv_bfloat16 g_x_hi[B_ * L_ * D_];
__device__ __nv_bfloat16 g_x_lo[B_ * L_ * D_];
__device__ __nv_bfloat16 g_wqkv_hi[3 * D_ * D_];
__device__ __nv_bfloat16 g_wqkv_lo[3 * D_ * D_];
__device__ __nv_bfloat16 g_wout_hi[D_ * D_];
__device__ __nv_bfloat16 g_wout_lo[D_ * D_];
__device__ __nv_bfloat16 g_att_hi[B_ * L_ * D_];
__device__ __nv_bfloat16 g_att_lo[B_ * L_ * D_];

// ---------------------------------------------------------------------------
// PTX helpers (base ISA only)
// ---------------------------------------------------------------------------
__device__ __forceinline__ uint32_t smem_u32(const void* p) {
    uint32_t a;
    asm("{ .reg .u64 t; cvta.to.shared.u64 t, %1; cvt.u32.u64 %0, t; }" : "=r"(a) : "l"(p));
    return a;
}

#define CP_ASYNC16(dst, src) \
    asm volatile("cp.async.cg.shared.global [%0], [%1], 16;" :: "r"(dst), "l"(src))
#define CP_COMMIT() asm volatile("cp.async.commit_group;" ::: "memory")
#define CP_WAIT0()  asm volatile("cp.async.wait_group 0;" ::: "memory")
#define CP_WAIT1()  asm volatile("cp.async.wait_group 1;" ::: "memory")

__device__ __forceinline__ void ldsm_x4(uint32_t& r0, uint32_t& r1, uint32_t& r2,
                                        uint32_t& r3, uint32_t addr) {
    asm volatile("ldmatrix.sync.aligned.m8n8.x4.shared.b16 {%0,%1,%2,%3}, [%4];"
                 : "=r"(r0), "=r"(r1), "=r"(r2), "=r"(r3) : "r"(addr));
}
__device__ __forceinline__ void ldsm_x4_t(uint32_t& r0, uint32_t& r1, uint32_t& r2,
                                          uint32_t& r3, uint32_t addr) {
    asm volatile("ldmatrix.sync.aligned.m8n8.x4.trans.shared.b16 {%0,%1,%2,%3}, [%4];"
                 : "=r"(r0), "=r"(r1), "=r"(r2), "=r"(r3) : "r"(addr));
}

__device__ __forceinline__ void mma_bf16(float* d, const uint32_t* a,
                                         uint32_t b0, uint32_t b1) {
    asm volatile(
        "mma.sync.aligned.m16n8k16.row.col.f32.bf16.bf16.f32 "
        "{%0,%1,%2,%3}, {%4,%5,%6,%7}, {%8,%9}, {%0,%1,%2,%3};"
        : "+f"(d[0]), "+f"(d[1]), "+f"(d[2]), "+f"(d[3])
        : "r"(a[0]), "r"(a[1]), "r"(a[2]), "r"(a[3]), "r"(b0), "r"(b1));
}

// split fp32x4 -> two packed bf16x4 (hi, lo)
__device__ __forceinline__ void split4(float4 v, uint2& h, uint2& l) {
    __nv_bfloat162 h01 = __floats2bfloat162_rn(v.x, v.y);
    __nv_bfloat162 h23 = __floats2bfloat162_rn(v.z, v.w);
    float2 f01 = __bfloat1622float2(h01);
    float2 f23 = __bfloat1622float2(h23);
    __nv_bfloat162 l01 = __floats2bfloat162_rn(v.x - f01.x, v.y - f01.y);
    __nv_bfloat162 l23 = __floats2bfloat162_rn(v.z - f23.x, v.w - f23.y);
    h = make_uint2(*(uint32_t*)&h01, *(uint32_t*)&h23);
    l = make_uint2(*(uint32_t*)&l01, *(uint32_t*)&l23);
}

// swizzled byte offset of float4-chunk c4 in a 128B-row bf16 tile
__device__ __forceinline__ uint32_t sw_off4(int row, int c4) {
    return (uint32_t)(row * 128 + ((((c4 >> 1) ^ (row & 7)) << 4) | ((c4 & 1) << 3)));
}

// ---------------------------------------------------------------------------
// fp32 -> bf16 hi/lo split conversion.  W: 0=x, 1=wqkv, 2=wout
// ---------------------------------------------------------------------------
template <int W>
__global__ void __launch_bounds__(256) cvt_split(const float* __restrict__ src, int n4) {
    __nv_bfloat16* hi = (W == 0) ? g_x_hi : (W == 1) ? g_wqkv_hi : g_wout_hi;
    __nv_bfloat16* lo = (W == 0) ? g_x_lo : (W == 1) ? g_wqkv_lo : g_wout_lo;

    int i = blockIdx.x * 256 + threadIdx.x;
    if (i >= n4) return;
    float4 v = ((const float4*)src)[i];
    uint2 h, l;
    split4(v, h, l);
    ((uint2*)hi)[i] = h;
    ((uint2*)lo)[i] = l;
}

// ---------------------------------------------------------------------------
// Warp-mma split-bf16 GEMM NT v3: CTA tile 128x256, 512 threads (16 warps,
// 4/SMSP), warp tile 64x32 (2m x 8n), K staged by 64, 2-stage cp.async,
// ONE __syncthreads per K-iter.  regs/thread ~125 (no spill @128 budget).
// MODE 0: A=x, B=w_qkv -> scatter bf16 hi/lo q/k/v.  MODE 1: A=att -> C fp32.
// ---------------------------------------------------------------------------
#define AT_B  16384                 // A tile (128x64 bf16)
#define BT_B  32768                 // B tile (256x64 bf16)
#define STG_B (2 * AT_B + 2 * BT_B) // 98304 per stage (Ah|Al|Bh|Bl)
#define TC_SMEM (2 * STG_B)         // 196608

template <int MODE>
__global__ void __launch_bounds__(512, 1) tc_gemm(float* __restrict__ C) {
    extern __shared__ char smc[];
    uint32_t sb = smem_u32(smc);

    const __nv_bfloat16* Ah  = (MODE == 0) ? g_x_hi : g_att_hi;
    const __nv_bfloat16* Al  = (MODE == 0) ? g_x_lo : g_att_lo;
    const __nv_bfloat16* Bhp = (MODE == 0) ? g_wqkv_hi : g_wout_hi;
    const __nv_bfloat16* Blp = (MODE == 0) ? g_wqkv_lo : g_wout_lo;

    const int t = threadIdx.x, lane = t & 31, warp = t >> 5;
    const int wm = warp & 1, wn = warp >> 1;          // wn 0..7 (32 cols each)
    const int m0 = blockIdx.y * 128, n0 = blockIdx.x * 256;

    // acc[mi][n8][4]: warp tile 64x32 -> 4 m16 x 4 n8
    float acc[4][4][4];
#pragma unroll
    for (int mi = 0; mi < 4; mi++)
#pragma unroll
        for (int ni = 0; ni < 4; ni++)
#pragma unroll
            for (int e = 0; e < 4; e++) acc[mi][ni][e] = 0.f;

    const int a_rb = wm * 64 + (lane & 15);
    const int a_cb = (lane >> 4);
    const int b_rb = wn * 32 + ((lane >> 4) * 8) + (lane & 7);
    const int b_cb = (lane >> 3) & 1;

#define LOAD_STAGE(it, s) do {                                                   \
    uint32_t base = sb + (s) * STG_B;                                            \
    int k0 = (it) * 64;                                                          \
    _Pragma("unroll")                                                            \
    for (int j = 0; j < 2; j++) {                                                \
        int c = t + 512 * j;                                                     \
        int row = c >> 3, ch = c & 7;                                            \
        uint32_t so = (uint32_t)(row * 128 + ((ch ^ (row & 7)) << 4));           \
        size_t g = (size_t)(m0 + row) * 1024 + ch * 8 + k0;                      \
        CP_ASYNC16(base + so, Ah + g);                                           \
        CP_ASYNC16(base + AT_B + so, Al + g);                                    \
    }                                                                            \
    _Pragma("unroll")                                                            \
    for (int j = 0; j < 4; j++) {                                                \
        int c = t + 512 * j;                                                     \
        int row = c >> 3, ch = c & 7;                                            \
        uint32_t so = (uint32_t)(row * 128 + ((ch ^ (row & 7)) << 4));           \
        size_t g = (size_t)(n0 + row) * 1024 + ch * 8 + k0;                      \
        CP_ASYNC16(base + 2 * AT_B + so, Bhp + g);                               \
        CP_ASYNC16(base + 2 * AT_B + BT_B + so, Blp + g);                        \
    }                                                                            \
    CP_COMMIT();                                                                 \
} while (0)

    LOAD_STAGE(0, 0);

    for (int it = 0; it < 16; it++) {
        int s = it & 1;
        CP_WAIT0();               // own copies of stage s done
        __syncthreads();          // all copies visible; stage s^1 free
        if (it + 1 < 16) LOAD_STAGE(it + 1, s ^ 1);
        uint32_t base = sb + s * STG_B;

#pragma unroll
        for (int kk = 0; kk < 4; kk++) {
            uint32_t ah[4][4], al[4][4];
#pragma unroll
            for (int mi = 0; mi < 4; mi++) {
                int r = a_rb + mi * 16;
                int c2 = kk * 2 + a_cb;
                uint32_t addr = base + (uint32_t)(r * 128 + ((c2 ^ (r & 7)) << 4));
                ldsm_x4(ah[mi][0], ah[mi][1], ah[mi][2], ah[mi][3], addr);
                ldsm_x4(al[mi][0], al[mi][1], al[mi][2], al[mi][3], addr + AT_B);
            }
#pragma unroll
            for (int nh = 0; nh < 2; nh++) {
                int r = b_rb + nh * 16;
                int c2 = kk * 2 + b_cb;
                uint32_t addr = base + 2 * AT_B
                              + (uint32_t)(r * 128 + ((c2 ^ (r & 7)) << 4));
                uint32_t bh[4], bl[4];
                ldsm_x4(bh[0], bh[1], bh[2], bh[3], addr);
                ldsm_x4(bl[0], bl[1], bl[2], bl[3], addr + BT_B);
#pragma unroll
                for (int mi = 0; mi < 4; mi++)
#pragma unroll
                    for (int q = 0; q < 2; q++) {
                        float* d = acc[mi][nh * 2 + q];
                        mma_bf16(d, ah[mi], bh[q * 2], bh[q * 2 + 1]);
                        mma_bf16(d, ah[mi], bl[q * 2], bl[q * 2 + 1]);
                        mma_bf16(d, al[mi], bh[q * 2], bh[q * 2 + 1]);
                    }
            }
        }
    }

    // ---------------- epilogue -------------------------------------------
    const int wnb = n0 + wn * 32;                 // multiple of 32
    if (MODE == 0) {
        const int sIdx = wnb >> 10;
        const int h    = (wnb >> 6) & 15;
        const int dby  = (wnb & 63);              // 0 or 32
        __nv_bfloat16 *dh, *dl;
        if (sIdx == 0)      { dh = g_q_hi; dl = g_q_lo; }
        else if (sIdx == 1) { dh = g_k_hi; dl = g_k_lo; }
        else                { dh = g_v_hi; dl = g_v_lo; }
#pragma unroll
        for (int mi = 0; mi < 4; mi++)
#pragma unroll
            for (int half = 0; half < 2; half++) {
                int row = m0 + wm * 64 + mi * 16 + (lane >> 2) + half * 8;
                int b = row >> 10, l = row & 1023;
                size_t rbase = ((size_t)(b * H_ + h) * L_ + l) * HD;
#pragma unroll
                for (int ni = 0; ni < 4; ni++) {
                    int d = dby + ni * 8 + (lane & 3) * 2;
                    float v0 = acc[mi][ni][half * 2];
                    float v1 = acc[mi][ni][half * 2 + 1];
                    __nv_bfloat162 hh = __floats2bfloat162_rn(v0, v1);
                    float2 hf = __bfloat1622float2(hh);
                    __nv_bfloat162 ll = __floats2bfloat162_rn(v0 - hf.x, v1 - hf.y);
                    *(__nv_bfloat162*)&dh[rbase + d] = hh;
                    *(__nv_bfloat162*)&dl[rbase + d] = ll;
                }
            }
    } else {
#pragma unroll
        for (int mi = 0; mi < 4; mi++)
#pragma unroll
            for (int half = 0; half < 2; half++) {
                int row = m0 + wm * 64 + mi * 16 + (lane >> 2) + half * 8;
#pragma unroll
                for (int ni = 0; ni < 4; ni++) {
                    int n = wnb + ni * 8 + (lane & 3) * 2;
                    *(float2*)&C[(size_t)row * 1024 + n] =
                        make_float2(acc[mi][ni][half * 2], acc[mi][ni][half * 2 + 1]);
                }
            }
    }
#undef LOAD_STAGE
}

// ---------------------------------------------------------------------------
// Tensor-core attention (unchanged from R9)
// ---------------------------------------------------------------------------
#define OFF_QH   0
#define OFF_QL   8192
#define OFF_K0H  16384
#define OFF_K1H  32768
#define OFF_RH   49152
#define OFF_RL   65536
#define OFF_QE   81920
#define OFF_S    102400
#define ATT_SMEM (102400 + 83968)
#define SP 328
#define QEP 80

__device__ __forceinline__ void issue_tile(uint32_t dsthi, uint32_t dstlo,
                                           const __nv_bfloat16* ghi,
                                           const __nv_bfloat16* glo,
                                           int rowbase, int t) {
#pragma unroll
    for (int j = 0; j < 2; j++) {
        int c = t + 256 * j;
        int row = c >> 3, ch = c & 7;
        uint32_t so = (uint32_t)(row * 128 + ((ch ^ (row & 7)) << 4));
        const __nv_bfloat16* gh = ghi + (size_t)(rowbase + row) * 64 + ch * 8;
        const __nv_bfloat16* gl = glo + (size_t)(rowbase + row) * 64 + ch * 8;
        CP_ASYNC16(dsthi + so, gh);
        CP_ASYNC16(dstlo + so, gl);
    }
}

__global__ void __launch_bounds__(256, 1) attn_mma(const float* __restrict__ rel_emb) {
    extern __shared__ char smc[];
    uint32_t sb = smem_u32(smc);
    float* Sf  = (float*)(smc + OFF_S);
    float* qEf = (float*)(smc + OFF_QE);

    const int t = threadIdx.x, lane = t & 31, warp = t >> 5;
    const int wm = warp & 1, wn = warp >> 1;
    const int qt0 = blockIdx.x * 64;
    const int bh  = blockIdx.y;
    const __nv_bfloat16* gqh = g_q_hi + (size_t)bh * L_ * HD;
    const __nv_bfloat16* gql = g_q_lo + (size_t)bh * L_ * HD;
    const __nv_bfloat16* gkh = g_k_hi + (size_t)bh * L_ * HD;
    const __nv_bfloat16* gkl = g_k_lo + (size_t)bh * L_ * HD;
    const __nv_bfloat16* gvh = g_v_hi + (size_t)bh * L_ * HD;
    const __nv_bfloat16* gvl = g_v_lo + (size_t)bh * L_ * HD;

    const int a_rb = wm * 32 + (lane & 15);
    const int a_cb = (lane >> 4);
    const int b_rb16 = wn * 16 + ((lane >> 4) * 8) + (lane & 7);
    const int b_cb = (lane >> 3) & 1;

    int first_kb = 4 - (int)blockIdx.x;
    if (first_kb < 0) first_kb = 0;

    // ---------- phase 0: async Q + first K; convert R ----------------------
    issue_tile(sb + OFF_QH, sb + OFF_QL, gqh, gql, qt0, t);
    CP_COMMIT();
    issue_tile(sb + OFF_K0H, sb + OFF_K0H + 8192, gkh, gkl,
               qt0 - 256 + first_kb * 64, t);
    CP_COMMIT();

    for (int i = t; i < 63 * 8; i += 256) {
        int row = 65 + (i >> 3), ch = i & 7;
        uint32_t o = (uint32_t)(row * 128 + ch * 16);
        *(uint4*)(smc + OFF_RH + o) = make_uint4(0, 0, 0, 0);
        *(uint4*)(smc + OFF_RL + o) = make_uint4(0, 0, 0, 0);
    }
    for (int idx = t; idx < 65 * 16; idx += 256) {
        int r = idx >> 4, c4 = idx & 15;
        float4 v = *(const float4*)&rel_emb[r * HD + c4 * 4];
        uint2 h, l;
        split4(v, h, l);
        uint32_t o = sw_off4(r, c4);
        *(uint2*)(smc + OFF_RH + o) = h;
        *(uint2*)(smc + OFF_RL + o) = l;
    }
    CP_WAIT1();
    __syncthreads();

    // ---------- phase 1: qE = Q * R^T --------------------------------------
    {
        float qa[2][2][2][4];
#pragma unroll
        for (int mi = 0; mi < 2; mi++)
#pragma unroll
            for (int nh = 0; nh < 2; nh++)
#pragma unroll
                for (int q = 0; q < 2; q++)
#pragma unroll
                    for (int e = 0; e < 4; e++) qa[mi][nh][q][e] = 0.f;

#pragma unroll
        for (int kk = 0; kk < 4; kk++) {
            uint32_t ah[2][4], al[2][4];
#pragma unroll
            for (int mi = 0; mi < 2; mi++) {
                int r = a_rb + mi * 16;
                int c = kk * 2 + a_cb;
                uint32_t addr = sb + (uint32_t)(r * 128 + ((c ^ (r & 7)) << 4));
                ldsm_x4(ah[mi][0], ah[mi][1], ah[mi][2], ah[mi][3], addr + OFF_QH);
                ldsm_x4(al[mi][0], al[mi][1], al[mi][2], al[mi][3], addr + OFF_QL);
            }
            uint32_t bh[2][4], bl[2][4];
#pragma unroll
            for (int nh = 0; nh < 2; nh++) {
                int r = wn * 32 + nh * 16 + ((lane >> 4) * 8) + (lane & 7);
                int c = kk * 2 + b_cb;
                uint32_t addr = sb + (uint32_t)(r * 128 + ((c ^ (r & 7)) << 4));
                ldsm_x4(bh[nh][0], bh[nh][1], bh[nh][2], bh[nh][3], addr + OFF_RH);
                ldsm_x4(bl[nh][0], bl[nh][1], bl[nh][2], bl[nh][3], addr + OFF_RL);
            }
#pragma unroll
            for (int mi = 0; mi < 2; mi++)
#pragma unroll
                for (int nh = 0; nh < 2; nh++)
#pragma unroll
                    for (int q = 0; q < 2; q++) {
                        float* d = qa[mi][nh][q];
                        mma_bf16(d, ah[mi], bh[nh][q * 2], bh[nh][q * 2 + 1]);
                        mma_bf16(d, ah[mi], bl[nh][q * 2], bl[nh][q * 2 + 1]);
                        mma_bf16(d, al[mi], bh[nh][q * 2], bh[nh][q * 2 + 1]);
                    }
        }
#pragma unroll
        for (int mi = 0; mi < 2; mi++)
#pragma unroll
            for (int nh = 0; nh < 2; nh++)
#pragma unroll
                for (int q = 0; q < 2; q++)
#pragma unroll
                    for (int half = 0; half < 2; half++) {
                        int row = wm * 32 + mi * 16 + (lane >> 2) + half * 8;
                        int col = wn * 32 + nh * 16 + q * 8 + (lane & 3) * 2;
                        if (col < 72) {
                            qEf[row * QEP + col]     = qa[mi][nh][q][half * 2];
                            qEf[row * QEP + col + 1] = qa[mi][nh][q][half * 2 + 1];
                        }
                    }
    }

    for (int kbk = 0; kbk < first_kb; kbk++)
        for (int e = t; e < 4096; e += 256)
            Sf[(e >> 6) * SP + kbk * 64 + (e & 63)] = -1e30f;

    // ---------- phase 2: scores, double-buffered K (1 sync / block) --------
    for (int kbk = first_kb; kbk < 5; kbk++) {
        int kb0 = qt0 - 256 + kbk * 64;
        int bufi = (kbk - first_kb) & 1;
        uint32_t kbase = sb + OFF_K0H + bufi * 16384;

        CP_WAIT0();
        __syncthreads();
        if (kbk < 4) {
            issue_tile(sb + OFF_K0H + (1 - bufi) * 16384,
                       sb + OFF_K0H + (1 - bufi) * 16384 + 8192,
                       gkh, gkl, kb0 + 64, t);
            CP_COMMIT();
        }

        float sc[2][2][4];
#pragma unroll
        for (int mi = 0; mi < 2; mi++)
#pragma unroll
            for (int q = 0; q < 2; q++)
#pragma unroll
                for (int e = 0; e < 4; e++) sc[mi][q][e] = 0.f;

#pragma unroll
        for (int kk = 0; kk < 4; kk++) {
            uint32_t ah[2][4], al[2][4];
#pragma unroll
            for (int mi = 0; mi < 2; mi++) {
                int r = a_rb + mi * 16;
                int c = kk * 2 + a_cb;
                uint32_t addr = sb + (uint32_t)(r * 128 + ((c ^ (r & 7)) << 4));
                ldsm_x4(ah[mi][0], ah[mi][1], ah[mi][2], ah[mi][3], addr + OFF_QH);
                ldsm_x4(al[mi][0], al[mi][1], al[mi][2], al[mi][3], addr + OFF_QL);
            }
            uint32_t bh[4], bl[4];
            {
                int r = b_rb16;
                int c = kk * 2 + b_cb;
                uint32_t off = (uint32_t)(r * 128 + ((c ^ (r & 7)) << 4));
                ldsm_x4(bh[0], bh[1], bh[2], bh[3], kbase + off);
                ldsm_x4(bl[0], bl[1], bl[2], bl[3], kbase + 8192 + off);
            }
#pragma unroll
            for (int mi = 0; mi < 2; mi++)
#pragma unroll
                for (int q = 0; q < 2; q++) {
                    float* d = sc[mi][q];
                    mma_bf16(d, ah[mi], bh[q * 2], bh[q * 2 + 1]);
                    mma_bf16(d, ah[mi], bl[q * 2], bl[q * 2 + 1]);
                    mma_bf16(d, al[mi], bh[q * 2], bh[q * 2 + 1]);
                }
        }
#pragma unroll
        for (int mi = 0; mi < 2; mi++)
#pragma unroll
            for (int q = 0; q < 2; q++)
#pragma unroll
                for (int half = 0; half < 2; half++)
#pragma unroll
                    for (int dd = 0; dd < 2; dd++) {
                        int row = wm * 32 + mi * 16 + (lane >> 2) + half * 8;
                        int col = wn * 16 + q * 8 + (lane & 3) * 2 + dd;
                        int i = qt0 + row, j = kb0 + col;
                        float val;
                        if (j > i || (i - j) >= 256) {
                            val = -1e30f;
                        } else {
                            int rel = j - i + 64;
                            if (rel < 0) rel = 0;
                            val = (sc[mi][q][half * 2 + dd] + qEf[row * QEP + rel]) * 0.125f;
                        }
                        Sf[row * SP + kbk * 64 + col] = val;
                    }
    }
    __syncthreads();

    // prefetch first V block into buf0
    issue_tile(sb + OFF_K0H, sb + OFF_K0H + 8192, gvh, gvl,
               qt0 - 256 + first_kb * 64, t);
    CP_COMMIT();

    // ---------- phase 3: row softmax (fp32, 320 cols) ----------------------
    {
        for (int r = warp * 8; r < warp * 8 + 8; r++) {
            float mx = -1e30f;
            for (int c = lane; c < 320; c += 32) mx = fmaxf(mx, Sf[r * SP + c]);
#pragma unroll
            for (int o = 16; o > 0; o >>= 1)
                mx = fmaxf(mx, __shfl_xor_sync(0xffffffffu, mx, o));
            float sum = 0.f;
            for (int c = lane; c < 320; c += 32) {
                float p = __expf(Sf[r * SP + c] - mx);
                Sf[r * SP + c] = p;
                sum += p;
            }
#pragma unroll
            for (int o = 16; o > 0; o >>= 1)
                sum += __shfl_xor_sync(0xffffffffu, sum, o);
            float inv = 1.f / sum;
            for (int c = lane; c < 320; c += 32) Sf[r * SP + c] *= inv;
        }
    }
    __syncthreads();

    // ---------- phase 4: out = P * V (ONE sync per block) ------------------
    float oac[2][2][4];
#pragma unroll
    for (int mi = 0; mi < 2; mi++)
#pragma unroll
        for (int q = 0; q < 2; q++)
#pragma unroll
            for (int e = 0; e < 4; e++) oac[mi][q][e] = 0.f;

    for (int kbk = first_kb; kbk < 5; kbk++) {
        int kb0 = qt0 - 256 + kbk * 64;
        int bufi = (kbk - first_kb) & 1;
        uint32_t vbase = sb + OFF_K0H + bufi * 16384;
        int p_off = bufi ? OFF_RH : OFF_QH;

        // split P(kbk) first (own buffer free; overlaps V flight)
        {
            int row = t >> 2;
            int cbq = (t & 3) * 4;
#pragma unroll
            for (int q4 = 0; q4 < 4; q4++) {
                int c4 = cbq + q4;
                float4 v = *(const float4*)&Sf[row * SP + kbk * 64 + c4 * 4];
                uint2 h, l;
                split4(v, h, l);
                uint32_t o = sw_off4(row, c4);
                *(uint2*)(smc + p_off + o) = h;
                *(uint2*)(smc + p_off + 8192 + o) = l;
            }
        }
        CP_WAIT0();
        __syncthreads();          // P + V visible; prior mma done
        if (kbk < 4) {
            issue_tile(sb + OFF_K0H + (1 - bufi) * 16384,
                       sb + OFF_K0H + (1 - bufi) * 16384 + 8192,
                       gvh, gvl, kb0 + 64, t);
            CP_COMMIT();
        }

#pragma unroll
        for (int kk = 0; kk < 4; kk++) {
            uint32_t ah[2][4], al[2][4];
#pragma unroll
            for (int mi = 0; mi < 2; mi++) {
                int r = a_rb + mi * 16;
                int c = kk * 2 + a_cb;
                uint32_t addr = sb + p_off + (uint32_t)(r * 128 + ((c ^ (r & 7)) << 4));
                ldsm_x4(ah[mi][0], ah[mi][1], ah[mi][2], ah[mi][3], addr);
                ldsm_x4(al[mi][0], al[mi][1], al[mi][2], al[mi][3], addr + 8192);
            }
            uint32_t bh[4], bl[4];
            {
                int vrow = kk * 16 + (lane & 7) + ((lane >> 3) & 1) * 8;
                int vch  = wn * 2 + (lane >> 4);
                uint32_t off = (uint32_t)(vrow * 128 + ((vch ^ (vrow & 7)) << 4));
                ldsm_x4_t(bh[0], bh[1], bh[2], bh[3], vbase + off);
                ldsm_x4_t(bl[0], bl[1], bl[2], bl[3], vbase + 8192 + off);
            }
#pragma unroll
            for (int mi = 0; mi < 2; mi++)
#pragma unroll
                for (int q = 0; q < 2; q++) {
                    float* d = oac[mi][q];
                    mma_bf16(d, ah[mi], bh[q * 2], bh[q * 2 + 1]);
                    mma_bf16(d, ah[mi], bl[q * 2], bl[q * 2 + 1]);
                    mma_bf16(d, al[mi], bh[q * 2], bh[q * 2 + 1]);
                }
        }
    }

    // ---------- epilogue ---------------------------------------------------
    {
        int b = bh >> 4, h = bh & 15;
#pragma unroll
        for (int mi = 0; mi < 2; mi++)
#pragma unroll
            for (int q = 0; q < 2; q++)
#pragma unroll
                for (int half = 0; half < 2; half++) {
                    int row = wm * 32 + mi * 16 + (lane >> 2) + half * 8;
                    int i = qt0 + row;
                    int d = wn * 16 + q * 8 + (lane & 3) * 2;
                    float v0 = oac[mi][q][half * 2], v1 = oac[mi][q][half * 2 + 1];
                    __nv_bfloat162 hh = __floats2bfloat162_rn(v0, v1);
                    float2 hf = __bfloat1622float2(hh);
                    __nv_bfloat162 ll = __floats2bfloat162_rn(v0 - hf.x, v1 - hf.y);
                    size_t off = ((size_t)(b * L_ + i) * H_ + h) * HD + d;
                    *(__nv_bfloat162*)&g_att_hi[off] = hh;
                    *(__nv_bfloat162*)&g_att_lo[off] = ll;
                }
    }
}

// ---------------------------------------------------------------------------
extern "C" void kernel_launch(void* const* d_in, const int* in_sizes, int n_in,
                              void* d_out, int out_size) {
    const float* x       = (const float*)d_in[0];
    const float* w_qkv   = (const float*)d_in[1];
    const float* w_out   = (const float*)d_in[2];
    const float* rel_emb = (const float*)d_in[3];
    float* out = (float*)d_out;

    (void)in_sizes; (void)n_in; (void)out_size;

    cudaFuncSetAttribute(attn_mma,
                         cudaFuncAttributeMaxDynamicSharedMemorySize, ATT_SMEM);
    cudaFuncSetAttribute(tc_gemm<0>,
                         cudaFuncAttributeMaxDynamicSharedMemorySize, TC_SMEM);
    cudaFuncSetAttribute(tc_gemm<1>,
                         cudaFuncAttributeMaxDynamicSharedMemorySize, TC_SMEM);

    cvt_split<0><<<(B_ * L_ * D_ / 4 + 255) / 256, 256>>>(x,    B_ * L_ * D_ / 4);
    cvt_split<1><<<(3 * D_ * D_ / 4 + 255) / 256, 256>>>(w_qkv, 3 * D_ * D_ / 4);
    cvt_split<2><<<(D_ * D_ / 4 + 255) / 256, 256>>>(w_out,     D_ * D_ / 4);

    tc_gemm<0><<<dim3(3072 / 256, 4096 / 128), 512, TC_SMEM>>>(nullptr);

    attn_mma<<<dim3(L_ / 64, NBH), 256, ATT_SMEM>>>(rel_emb);

    tc_gemm<1><<<dim3(1024 / 256, 4096 / 128), 512, TC_SMEM>>>(out);
}

// round 11
// speedup vs baseline: 5.6428x; 1.9452x over previous
#include <cuda_runtime.h>
#include <cuda_fp16.h>
#include <cstdint>

#define B_  4
#define L_  1024
#define D_  1024
#define H_  16
#define HD  64
#define NBH (B_ * H_)   // 64

// ---------------------------------------------------------------------------
// Static device scratch (no allocation allowed) — single fp16 everywhere
// ---------------------------------------------------------------------------
__device__ __half g_q_h[NBH * L_ * HD];
__device__ __half g_k_h[NBH * L_ * HD];
__device__ __half g_v_h[NBH * L_ * HD];

__device__ __half g_x_h[B_ * L_ * D_];
__device__ __half g_wqkv_h[3 * D_ * D_];
__device__ __half g_wout_h[D_ * D_];
__device__ __half g_att_h[B_ * L_ * D_];

// ---------------------------------------------------------------------------
// PTX helpers (base ISA only)
// ---------------------------------------------------------------------------
__device__ __forceinline__ uint32_t smem_u32(const void* p) {
    uint32_t a;
    asm("{ .reg .u64 t; cvta.to.shared.u64 t, %1; cvt.u32.u64 %0, t; }" : "=r"(a) : "l"(p));
    return a;
}

#define CP_ASYNC16(dst, src) \
    asm volatile("cp.async.cg.shared.global [%0], [%1], 16;" :: "r"(dst), "l"(src))
#define CP_COMMIT() asm volatile("cp.async.commit_group;" ::: "memory")
#define CP_WAIT0()  asm volatile("cp.async.wait_group 0;" ::: "memory")
#define CP_WAIT1()  asm volatile("cp.async.wait_group 1;" ::: "memory")

__device__ __forceinline__ void ldsm_x4(uint32_t& r0, uint32_t& r1, uint32_t& r2,
                                        uint32_t& r3, uint32_t addr) {
    asm volatile("ldmatrix.sync.aligned.m8n8.x4.shared.b16 {%0,%1,%2,%3}, [%4];"
                 : "=r"(r0), "=r"(r1), "=r"(r2), "=r"(r3) : "r"(addr));
}
__device__ __forceinline__ void ldsm_x4_t(uint32_t& r0, uint32_t& r1, uint32_t& r2,
                                          uint32_t& r3, uint32_t addr) {
    asm volatile("ldmatrix.sync.aligned.m8n8.x4.trans.shared.b16 {%0,%1,%2,%3}, [%4];"
                 : "=r"(r0), "=r"(r1), "=r"(r2), "=r"(r3) : "r"(addr));
}

__device__ __forceinline__ void mma_fp16(float* d, const uint32_t* a,
                                         uint32_t b0, uint32_t b1) {
    asm volatile(
        "mma.sync.aligned.m16n8k16.row.col.f32.f16.f16.f32 "
        "{%0,%1,%2,%3}, {%4,%5,%6,%7}, {%8,%9}, {%0,%1,%2,%3};"
        : "+f"(d[0]), "+f"(d[1]), "+f"(d[2]), "+f"(d[3])
        : "r"(a[0]), "r"(a[1]), "r"(a[2]), "r"(a[3]), "r"(b0), "r"(b1));
}

// fp32x4 -> packed fp16x4
__device__ __forceinline__ uint2 f4_to_h4(float4 v) {
    __half2 a = __floats2half2_rn(v.x, v.y);
    __half2 b = __floats2half2_rn(v.z, v.w);
    return make_uint2(*(uint32_t*)&a, *(uint32_t*)&b);
}

// swizzled byte offset of float4-chunk c4 in a 128B-row 16-bit tile
__device__ __forceinline__ uint32_t sw_off4(int row, int c4) {
    return (uint32_t)(row * 128 + ((((c4 >> 1) ^ (row & 7)) << 4) | ((c4 & 1) << 3)));
}

// ---------------------------------------------------------------------------
// fp32 -> fp16 conversion.  W: 0=x, 1=wqkv, 2=wout
// ---------------------------------------------------------------------------
template <int W>
__global__ void __launch_bounds__(256) cvt_h(const float* __restrict__ src, int n4) {
    __half* dst = (W == 0) ? g_x_h : (W == 1) ? g_wqkv_h : g_wout_h;
    int i = blockIdx.x * 256 + threadIdx.x;
    if (i >= n4) return;
    float4 v = ((const float4*)src)[i];
    ((uint2*)dst)[i] = f4_to_h4(v);
}

// ---------------------------------------------------------------------------
// Warp-mma fp16 GEMM NT: CTA tile 128x256, 512 threads (16 warps, 4/SMSP),
// warp tile 64x32 (2m x 8n), K staged by 64, 2-stage cp.async, 1 sync/iter.
// MODE 0: A=x, B=w_qkv -> scatter fp16 q/k/v.  MODE 1: A=att -> C fp32.
// ---------------------------------------------------------------------------
#define AT_B  16384                 // A tile (128x64 fp16)
#define BT_B  32768                 // B tile (256x64 fp16)
#define STG_B (AT_B + BT_B)         // 49152 per stage
#define TC_SMEM (2 * STG_B)         // 98304

template <int MODE>
__global__ void __launch_bounds__(512, 1) tc_gemm(float* __restrict__ C) {
    extern __shared__ char smc[];
    uint32_t sb = smem_u32(smc);

    const __half* A  = (MODE == 0) ? g_x_h : g_att_h;
    const __half* Bp = (MODE == 0) ? g_wqkv_h : g_wout_h;

    const int t = threadIdx.x, lane = t & 31, warp = t >> 5;
    const int wm = warp & 1, wn = warp >> 1;          // wn 0..7 (32 cols each)
    const int m0 = blockIdx.y * 128, n0 = blockIdx.x * 256;

    float acc[4][4][4];
#pragma unroll
    for (int mi = 0; mi < 4; mi++)
#pragma unroll
        for (int ni = 0; ni < 4; ni++)
#pragma unroll
            for (int e = 0; e < 4; e++) acc[mi][ni][e] = 0.f;

    const int a_rb = wm * 64 + (lane & 15);
    const int a_cb = (lane >> 4);
    const int b_rb = wn * 32 + ((lane >> 4) * 8) + (lane & 7);
    const int b_cb = (lane >> 3) & 1;

#define LOAD_STAGE(it, s) do {                                                   \
    uint32_t base = sb + (s) * STG_B;                                            \
    int k0 = (it) * 64;                                                          \
    _Pragma("unroll")                                                            \
    for (int j = 0; j < 2; j++) {                                                \
        int c = t + 512 * j;                                                     \
        int row = c >> 3, ch = c & 7;                                            \
        uint32_t so = (uint32_t)(row * 128 + ((ch ^ (row & 7)) << 4));           \
        CP_ASYNC16(base + so, A + (size_t)(m0 + row) * 1024 + ch * 8 + k0);      \
    }                                                                            \
    _Pragma("unroll")                                                            \
    for (int j = 0; j < 4; j++) {                                                \
        int c = t + 512 * j;                                                     \
        int row = c >> 3, ch = c & 7;                                            \
        uint32_t so = (uint32_t)(row * 128 + ((ch ^ (row & 7)) << 4));           \
        CP_ASYNC16(base + AT_B + so, Bp + (size_t)(n0 + row) * 1024 + ch * 8 + k0); \
    }                                                                            \
    CP_COMMIT();                                                                 \
} while (0)

    LOAD_STAGE(0, 0);

    for (int it = 0; it < 16; it++) {
        int s = it & 1;
        CP_WAIT0();
        __syncthreads();
        if (it + 1 < 16) LOAD_STAGE(it + 1, s ^ 1);
        uint32_t base = sb + s * STG_B;

#pragma unroll
        for (int kk = 0; kk < 4; kk++) {
            uint32_t ah[4][4];
#pragma unroll
            for (int mi = 0; mi < 4; mi++) {
                int r = a_rb + mi * 16;
                int c2 = kk * 2 + a_cb;
                uint32_t addr = base + (uint32_t)(r * 128 + ((c2 ^ (r & 7)) << 4));
                ldsm_x4(ah[mi][0], ah[mi][1], ah[mi][2], ah[mi][3], addr);
            }
#pragma unroll
            for (int nh = 0; nh < 2; nh++) {
                int r = b_rb + nh * 16;
                int c2 = kk * 2 + b_cb;
                uint32_t addr = base + AT_B
                              + (uint32_t)(r * 128 + ((c2 ^ (r & 7)) << 4));
                uint32_t bh[4];
                ldsm_x4(bh[0], bh[1], bh[2], bh[3], addr);
#pragma unroll
                for (int mi = 0; mi < 4; mi++)
#pragma unroll
                    for (int q = 0; q < 2; q++)
                        mma_fp16(acc[mi][nh * 2 + q], ah[mi], bh[q * 2], bh[q * 2 + 1]);
            }
        }
    }

    // ---------------- epilogue -------------------------------------------
    const int wnb = n0 + wn * 32;
    if (MODE == 0) {
        const int sIdx = wnb >> 10;
        const int h    = (wnb >> 6) & 15;
        const int dby  = (wnb & 63);
        __half* dst = (sIdx == 0) ? g_q_h : (sIdx == 1) ? g_k_h : g_v_h;
#pragma unroll
        for (int mi = 0; mi < 4; mi++)
#pragma unroll
            for (int half = 0; half < 2; half++) {
                int row = m0 + wm * 64 + mi * 16 + (lane >> 2) + half * 8;
                int b = row >> 10, l = row & 1023;
                size_t rbase = ((size_t)(b * H_ + h) * L_ + l) * HD;
#pragma unroll
                for (int ni = 0; ni < 4; ni++) {
                    int d = dby + ni * 8 + (lane & 3) * 2;
                    __half2 hv = __floats2half2_rn(acc[mi][ni][half * 2],
                                                   acc[mi][ni][half * 2 + 1]);
                    *(__half2*)&dst[rbase + d] = hv;
                }
            }
    } else {
#pragma unroll
        for (int mi = 0; mi < 4; mi++)
#pragma unroll
            for (int half = 0; half < 2; half++) {
                int row = m0 + wm * 64 + mi * 16 + (lane >> 2) + half * 8;
#pragma unroll
                for (int ni = 0; ni < 4; ni++) {
                    int n = wnb + ni * 8 + (lane & 3) * 2;
                    *(float2*)&C[(size_t)row * 1024 + n] =
                        make_float2(acc[mi][ni][half * 2], acc[mi][ni][half * 2 + 1]);
                }
            }
    }
#undef LOAD_STAGE
}

// ---------------------------------------------------------------------------
// Tensor-core attention, fp16 single precision, fp32 softmax.
// smem map (bytes):
//   [0     ) Q 8K (P buf0 reuse)   [ 8192) K0/V0 8K   [16384) K1/V1 8K
//   [24576 ) R 16K (128 rows; P buf1 reuses first 8K)
//   [40960 ) qE fp32 [64][80] 20K
//   [61440 ) S  fp32 [64][328] 82K     total 145408
// ---------------------------------------------------------------------------
#define OFF_Q    0
#define OFF_K0   8192
#define OFF_K1   16384
#define OFF_R    24576
#define OFF_QE   40960
#define OFF_S    61440
#define ATT_SMEM (61440 + 83968)
#define SP 328
#define QEP 80

// one 64x64 fp16 tile via cp.async (2 chunks/thread, 256 threads)
__device__ __forceinline__ void issue_tile(uint32_t dst, const __half* g,
                                           int rowbase, int t) {
#pragma unroll
    for (int j = 0; j < 2; j++) {
        int c = t + 256 * j;
        int row = c >> 3, ch = c & 7;
        uint32_t so = (uint32_t)(row * 128 + ((ch ^ (row & 7)) << 4));
        CP_ASYNC16(dst + so, g + (size_t)(rowbase + row) * 64 + ch * 8);
    }
}

__global__ void __launch_bounds__(256, 1) attn_mma(const float* __restrict__ rel_emb) {
    extern __shared__ char smc[];
    uint32_t sb = smem_u32(smc);
    float* Sf  = (float*)(smc + OFF_S);
    float* qEf = (float*)(smc + OFF_QE);

    const int t = threadIdx.x, lane = t & 31, warp = t >> 5;
    const int wm = warp & 1, wn = warp >> 1;
    const int qt0 = blockIdx.x * 64;
    const int bh  = blockIdx.y;
    const __half* gq = g_q_h + (size_t)bh * L_ * HD;
    const __half* gk = g_k_h + (size_t)bh * L_ * HD;
    const __half* gv = g_v_h + (size_t)bh * L_ * HD;

    const int a_rb = wm * 32 + (lane & 15);
    const int a_cb = (lane >> 4);
    const int b_rb16 = wn * 16 + ((lane >> 4) * 8) + (lane & 7);
    const int b_cb = (lane >> 3) & 1;

    int first_kb = 4 - (int)blockIdx.x;
    if (first_kb < 0) first_kb = 0;

    // ---------- phase 0: async Q + first K; convert R ----------------------
    issue_tile(sb + OFF_Q, gq, qt0, t);
    CP_COMMIT();
    issue_tile(sb + OFF_K0, gk, qt0 - 256 + first_kb * 64, t);
    CP_COMMIT();

    // zero R rows 65..127 (disjoint from fill)
    for (int i = t; i < 63 * 8; i += 256) {
        int row = 65 + (i >> 3), ch = i & 7;
        *(uint4*)(smc + OFF_R + row * 128 + ch * 16) = make_uint4(0, 0, 0, 0);
    }
    // fill R rows 0..64 (fp32 -> fp16, swizzled)
    for (int idx = t; idx < 65 * 16; idx += 256) {
        int r = idx >> 4, c4 = idx & 15;
        float4 v = *(const float4*)&rel_emb[r * HD + c4 * 4];
        *(uint2*)(smc + OFF_R + sw_off4(r, c4)) = f4_to_h4(v);
    }
    CP_WAIT1();
    __syncthreads();

    // ---------- phase 1: qE = Q * R^T --------------------------------------
    {
        float qa[2][2][2][4];
#pragma unroll
        for (int mi = 0; mi < 2; mi++)
#pragma unroll
            for (int nh = 0; nh < 2; nh++)
#pragma unroll
                for (int q = 0; q < 2; q++)
#pragma unroll
                    for (int e = 0; e < 4; e++) qa[mi][nh][q][e] = 0.f;

#pragma unroll
        for (int kk = 0; kk < 4; kk++) {
            uint32_t ah[2][4];
#pragma unroll
            for (int mi = 0; mi < 2; mi++) {
                int r = a_rb + mi * 16;
                int c = kk * 2 + a_cb;
                uint32_t addr = sb + OFF_Q + (uint32_t)(r * 128 + ((c ^ (r & 7)) << 4));
                ldsm_x4(ah[mi][0], ah[mi][1], ah[mi][2], ah[mi][3], addr);
            }
            uint32_t bh[2][4];
#pragma unroll
            for (int nh = 0; nh < 2; nh++) {
                int r = wn * 32 + nh * 16 + ((lane >> 4) * 8) + (lane & 7);
                int c = kk * 2 + b_cb;
                uint32_t addr = sb + OFF_R + (uint32_t)(r * 128 + ((c ^ (r & 7)) << 4));
                ldsm_x4(bh[nh][0], bh[nh][1], bh[nh][2], bh[nh][3], addr);
            }
#pragma unroll
            for (int mi = 0; mi < 2; mi++)
#pragma unroll
                for (int nh = 0; nh < 2; nh++)
#pragma unroll
                    for (int q = 0; q < 2; q++)
                        mma_fp16(qa[mi][nh][q], ah[mi], bh[nh][q * 2], bh[nh][q * 2 + 1]);
        }
#pragma unroll
        for (int mi = 0; mi < 2; mi++)
#pragma unroll
            for (int nh = 0; nh < 2; nh++)
#pragma unroll
                for (int q = 0; q < 2; q++)
#pragma unroll
                    for (int half = 0; half < 2; half++) {
                        int row = wm * 32 + mi * 16 + (lane >> 2) + half * 8;
                        int col = wn * 32 + nh * 16 + q * 8 + (lane & 3) * 2;
                        if (col < 72) {
                            qEf[row * QEP + col]     = qa[mi][nh][q][half * 2];
                            qEf[row * QEP + col + 1] = qa[mi][nh][q][half * 2 + 1];
                        }
                    }
    }

    for (int kbk = 0; kbk < first_kb; kbk++)
        for (int e = t; e < 4096; e += 256)
            Sf[(e >> 6) * SP + kbk * 64 + (e & 63)] = -1e30f;

    // ---------- phase 2: scores, double-buffered K -------------------------
    for (int kbk = first_kb; kbk < 5; kbk++) {
        int kb0 = qt0 - 256 + kbk * 64;
        int bufi = (kbk - first_kb) & 1;
        uint32_t kbase = sb + OFF_K0 + bufi * 8192;

        CP_WAIT0();
        __syncthreads();
        if (kbk < 4) {
            issue_tile(sb + OFF_K0 + (1 - bufi) * 8192, gk, kb0 + 64, t);
            CP_COMMIT();
        }

        float sc[2][2][4];
#pragma unroll
        for (int mi = 0; mi < 2; mi++)
#pragma unroll
            for (int q = 0; q < 2; q++)
#pragma unroll
                for (int e = 0; e < 4; e++) sc[mi][q][e] = 0.f;

#pragma unroll
        for (int kk = 0; kk < 4; kk++) {
            uint32_t ah[2][4];
#pragma unroll
            for (int mi = 0; mi < 2; mi++) {
                int r = a_rb + mi * 16;
                int c = kk * 2 + a_cb;
                uint32_t addr = sb + OFF_Q + (uint32_t)(r * 128 + ((c ^ (r & 7)) << 4));
                ldsm_x4(ah[mi][0], ah[mi][1], ah[mi][2], ah[mi][3], addr);
            }
            uint32_t bh[4];
            {
                int r = b_rb16;
                int c = kk * 2 + b_cb;
                ldsm_x4(bh[0], bh[1], bh[2], bh[3],
                        kbase + (uint32_t)(r * 128 + ((c ^ (r & 7)) << 4)));
            }
#pragma unroll
            for (int mi = 0; mi < 2; mi++)
#pragma unroll
                for (int q = 0; q < 2; q++)
                    mma_fp16(sc[mi][q], ah[mi], bh[q * 2], bh[q * 2 + 1]);
        }
#pragma unroll
        for (int mi = 0; mi < 2; mi++)
#pragma unroll
            for (int q = 0; q < 2; q++)
#pragma unroll
                for (int half = 0; half < 2; half++)
#pragma unroll
                    for (int dd = 0; dd < 2; dd++) {
                        int row = wm * 32 + mi * 16 + (lane >> 2) + half * 8;
                        int col = wn * 16 + q * 8 + (lane & 3) * 2 + dd;
                        int i = qt0 + row, j = kb0 + col;
                        float val;
                        if (j > i || (i - j) >= 256) {
                            val = -1e30f;
                        } else {
                            int rel = j - i + 64;
                            if (rel < 0) rel = 0;
                            val = (sc[mi][q][half * 2 + dd] + qEf[row * QEP + rel]) * 0.125f;
                        }
                        Sf[row * SP + kbk * 64 + col] = val;
                    }
    }
    __syncthreads();

    // prefetch first V block into buf0
    issue_tile(sb + OFF_K0, gv, qt0 - 256 + first_kb * 64, t);
    CP_COMMIT();

    // ---------- phase 3: row softmax (fp32, 320 cols) ----------------------
    {
        for (int r = warp * 8; r < warp * 8 + 8; r++) {
            float mx = -1e30f;
            for (int c = lane; c < 320; c += 32) mx = fmaxf(mx, Sf[r * SP + c]);
#pragma unroll
            for (int o = 16; o > 0; o >>= 1)
                mx = fmaxf(mx, __shfl_xor_sync(0xffffffffu, mx, o));
            float sum = 0.f;
            for (int c = lane; c < 320; c += 32) {
                float p = __expf(Sf[r * SP + c] - mx);
                Sf[r * SP + c] = p;
                sum += p;
            }
#pragma unroll
            for (int o = 16; o > 0; o >>= 1)
                sum += __shfl_xor_sync(0xffffffffu, sum, o);
            float inv = 1.f / sum;
            for (int c = lane; c < 320; c += 32) Sf[r * SP + c] *= inv;
        }
    }
    __syncthreads();

    // ---------- phase 4: out = P * V (one sync per block) ------------------
    float oac[2][2][4];
#pragma unroll
    for (int mi = 0; mi < 2; mi++)
#pragma unroll
        for (int q = 0; q < 2; q++)
#pragma unroll
            for (int e = 0; e < 4; e++) oac[mi][q][e] = 0.f;

    for (int kbk = first_kb; kbk < 5; kbk++) {
        int kb0 = qt0 - 256 + kbk * 64;
        int bufi = (kbk - first_kb) & 1;
        uint32_t vbase = sb + OFF_K0 + bufi * 8192;
        int p_off = bufi ? OFF_R : OFF_Q;

        // convert P(kbk) to fp16 (own buffer free; overlaps V flight)
        {
            int row = t >> 2;
            int cbq = (t & 3) * 4;
#pragma unroll
            for (int q4 = 0; q4 < 4; q4++) {
                int c4 = cbq + q4;
                float4 v = *(const float4*)&Sf[row * SP + kbk * 64 + c4 * 4];
                *(uint2*)(smc + p_off + sw_off4(row, c4)) = f4_to_h4(v);
            }
        }
        CP_WAIT0();
        __syncthreads();
        if (kbk < 4) {
            issue_tile(sb + OFF_K0 + (1 - bufi) * 8192, gv, kb0 + 64, t);
            CP_COMMIT();
        }

#pragma unroll
        for (int kk = 0; kk < 4; kk++) {
            uint32_t ah[2][4];
#pragma unroll
            for (int mi = 0; mi < 2; mi++) {
                int r = a_rb + mi * 16;
                int c = kk * 2 + a_cb;
                uint32_t addr = sb + p_off + (uint32_t)(r * 128 + ((c ^ (r & 7)) << 4));
                ldsm_x4(ah[mi][0], ah[mi][1], ah[mi][2], ah[mi][3], addr);
            }
            uint32_t bh[4];
            {
                int vrow = kk * 16 + (lane & 7) + ((lane >> 3) & 1) * 8;
                int vch  = wn * 2 + (lane >> 4);
                ldsm_x4_t(bh[0], bh[1], bh[2], bh[3],
                          vbase + (uint32_t)(vrow * 128 + ((vch ^ (vrow & 7)) << 4)));
            }
#pragma unroll
            for (int mi = 0; mi < 2; mi++)
#pragma unroll
                for (int q = 0; q < 2; q++)
                    mma_fp16(oac[mi][q], ah[mi], bh[q * 2], bh[q * 2 + 1]);
        }
    }

    // ---------- epilogue: write att fp16 in [B,L,H*hd] ---------------------
    {
        int b = bh >> 4, h = bh & 15;
#pragma unroll
        for (int mi = 0; mi < 2; mi++)
#pragma unroll
            for (int q = 0; q < 2; q++)
#pragma unroll
                for (int half = 0; half < 2; half++) {
                    int row = wm * 32 + mi * 16 + (lane >> 2) + half * 8;
                    int i = qt0 + row;
                    int d = wn * 16 + q * 8 + (lane & 3) * 2;
                    __half2 hv = __floats2half2_rn(oac[mi][q][half * 2],
                                                   oac[mi][q][half * 2 + 1]);
                    size_t off = ((size_t)(b * L_ + i) * H_ + h) * HD + d;
                    *(__half2*)&g_att_h[off] = hv;
                }
    }
}

// ---------------------------------------------------------------------------
extern "C" void kernel_launch(void* const* d_in, const int* in_sizes, int n_in,
                              void* d_out, int out_size) {
    const float* x       = (const float*)d_in[0];
    const float* w_qkv   = (const float*)d_in[1];
    const float* w_out   = (const float*)d_in[2];
    const float* rel_emb = (const float*)d_in[3];
    float* out = (float*)d_out;

    (void)in_sizes; (void)n_in; (void)out_size;

    cudaFuncSetAttribute(attn_mma,
                         cudaFuncAttributeMaxDynamicSharedMemorySize, ATT_SMEM);
    cudaFuncSetAttribute(tc_gemm<0>,
                         cudaFuncAttributeMaxDynamicSharedMemorySize, TC_SMEM);
    cudaFuncSetAttribute(tc_gemm<1>,
                         cudaFuncAttributeMaxDynamicSharedMemorySize, TC_SMEM);

    cvt_h<0><<<(B_ * L_ * D_ / 4 + 255) / 256, 256>>>(x,    B_ * L_ * D_ / 4);
    cvt_h<1><<<(3 * D_ * D_ / 4 + 255) / 256, 256>>>(w_qkv, 3 * D_ * D_ / 4);
    cvt_h<2><<<(D_ * D_ / 4 + 255) / 256, 256>>>(w_out,     D_ * D_ / 4);

    tc_gemm<0><<<dim3(3072 / 256, 4096 / 128), 512, TC_SMEM>>>(nullptr);

    attn_mma<<<dim3(L_ / 64, NBH), 256, ATT_SMEM>>>(rel_emb);

    tc_gemm<1><<<dim3(1024 / 256, 4096 / 128), 512, TC_SMEM>>>(out);
}

// round 12
// speedup vs baseline: 6.0104x; 1.0651x over previous
#include <cuda_runtime.h>
#include <cuda_fp16.h>
#include <cstdint>

#define B_  4
#define L_  1024
#define D_  1024
#define H_  16
#define HD  64
#define NBH (B_ * H_)   // 64

// ---------------------------------------------------------------------------
// Static device scratch (no allocation allowed) — single fp16 everywhere
// ---------------------------------------------------------------------------
__device__ __half g_q_h[NBH * L_ * HD];
__device__ __half g_k_h[NBH * L_ * HD];
__device__ __half g_v_h[NBH * L_ * HD];

__device__ __half g_x_h[B_ * L_ * D_];
__device__ __half g_wqkv_h[3 * D_ * D_];
__device__ __half g_wout_h[D_ * D_];
__device__ __half g_att_h[B_ * L_ * D_];

// ---------------------------------------------------------------------------
// PTX helpers (base ISA only)
// ---------------------------------------------------------------------------
__device__ __forceinline__ uint32_t smem_u32(const void* p) {
    uint32_t a;
    asm("{ .reg .u64 t; cvta.to.shared.u64 t, %1; cvt.u32.u64 %0, t; }" : "=r"(a) : "l"(p));
    return a;
}

#define CP_ASYNC16(dst, src) \
    asm volatile("cp.async.cg.shared.global [%0], [%1], 16;" :: "r"(dst), "l"(src))
#define CP_COMMIT() asm volatile("cp.async.commit_group;" ::: "memory")
#define CP_WAIT0()  asm volatile("cp.async.wait_group 0;" ::: "memory")
#define CP_WAIT1()  asm volatile("cp.async.wait_group 1;" ::: "memory")

__device__ __forceinline__ void ldsm_x4(uint32_t& r0, uint32_t& r1, uint32_t& r2,
                                        uint32_t& r3, uint32_t addr) {
    asm volatile("ldmatrix.sync.aligned.m8n8.x4.shared.b16 {%0,%1,%2,%3}, [%4];"
                 : "=r"(r0), "=r"(r1), "=r"(r2), "=r"(r3) : "r"(addr));
}
__device__ __forceinline__ void ldsm_x4_t(uint32_t& r0, uint32_t& r1, uint32_t& r2,
                                          uint32_t& r3, uint32_t addr) {
    asm volatile("ldmatrix.sync.aligned.m8n8.x4.trans.shared.b16 {%0,%1,%2,%3}, [%4];"
                 : "=r"(r0), "=r"(r1), "=r"(r2), "=r"(r3) : "r"(addr));
}

__device__ __forceinline__ void mma_fp16(float* d, const uint32_t* a,
                                         uint32_t b0, uint32_t b1) {
    asm volatile(
        "mma.sync.aligned.m16n8k16.row.col.f32.f16.f16.f32 "
        "{%0,%1,%2,%3}, {%4,%5,%6,%7}, {%8,%9}, {%0,%1,%2,%3};"
        : "+f"(d[0]), "+f"(d[1]), "+f"(d[2]), "+f"(d[3])
        : "r"(a[0]), "r"(a[1]), "r"(a[2]), "r"(a[3]), "r"(b0), "r"(b1));
}

// fp32x4 -> packed fp16x4
__device__ __forceinline__ uint2 f4_to_h4(float4 v) {
    __half2 a = __floats2half2_rn(v.x, v.y);
    __half2 b = __floats2half2_rn(v.z, v.w);
    return make_uint2(*(uint32_t*)&a, *(uint32_t*)&b);
}

// swizzled byte offset of float4-chunk c4 in a 128B-row 16-bit tile
__device__ __forceinline__ uint32_t sw_off4(int row, int c4) {
    return (uint32_t)(row * 128 + ((((c4 >> 1) ^ (row & 7)) << 4) | ((c4 & 1) << 3)));
}

// ---------------------------------------------------------------------------
// fp32 -> fp16 conversion.  W: 0=x, 1=wqkv, 2=wout
// ---------------------------------------------------------------------------
template <int W>
__global__ void __launch_bounds__(256) cvt_h(const float* __restrict__ src, int n4) {
    __half* dst = (W == 0) ? g_x_h : (W == 1) ? g_wqkv_h : g_wout_h;
    int i = blockIdx.x * 256 + threadIdx.x;
    if (i >= n4) return;
    float4 v = ((const float4*)src)[i];
    ((uint2*)dst)[i] = f4_to_h4(v);
}

// ---------------------------------------------------------------------------
// Warp-mma fp16 GEMM NT v4: CTA 128x256, 256 threads (8 warps), warp tile
// 64x64 (2m x 4n) — A-fragment reuse over 8 n8 groups cuts smem demand to
// ~64 B/cyc.  K staged by 64, 2-stage cp.async, 1 sync/iter.
// MODE 0: A=x, B=w_qkv -> scatter fp16 q/k/v.  MODE 1: A=att -> C fp32.
// ---------------------------------------------------------------------------
#define AT_B  16384                 // A tile (128x64 fp16)
#define BT_B  32768                 // B tile (256x64 fp16)
#define STG_B (AT_B + BT_B)         // 49152 per stage
#define TC_SMEM (2 * STG_B)         // 98304

template <int MODE>
__global__ void __launch_bounds__(256, 1) tc_gemm(float* __restrict__ C) {
    extern __shared__ char smc[];
    uint32_t sb = smem_u32(smc);

    const __half* A  = (MODE == 0) ? g_x_h : g_att_h;
    const __half* Bp = (MODE == 0) ? g_wqkv_h : g_wout_h;

    const int t = threadIdx.x, lane = t & 31, warp = t >> 5;
    const int wm = warp & 1, wn = warp >> 1;          // wn 0..3 (64 cols each)
    const int m0 = blockIdx.y * 128, n0 = blockIdx.x * 256;

    float acc[4][8][4];                               // mi(4 m16) x 8 n8
#pragma unroll
    for (int mi = 0; mi < 4; mi++)
#pragma unroll
        for (int ni = 0; ni < 8; ni++)
#pragma unroll
            for (int e = 0; e < 4; e++) acc[mi][ni][e] = 0.f;

    const int a_rb = wm * 64 + (lane & 15);
    const int a_cb = (lane >> 4);
    const int b_cb = (lane >> 3) & 1;

#define LOAD_STAGE(it, s) do {                                                   \
    uint32_t base = sb + (s) * STG_B;                                            \
    int k0 = (it) * 64;                                                          \
    _Pragma("unroll")                                                            \
    for (int j = 0; j < 4; j++) {                                                \
        int c = t + 256 * j;                                                     \
        int row = c >> 3, ch = c & 7;                                            \
        uint32_t so = (uint32_t)(row * 128 + ((ch ^ (row & 7)) << 4));           \
        CP_ASYNC16(base + so, A + (size_t)(m0 + row) * 1024 + ch * 8 + k0);      \
    }                                                                            \
    _Pragma("unroll")                                                            \
    for (int j = 0; j < 8; j++) {                                                \
        int c = t + 256 * j;                                                     \
        int row = c >> 3, ch = c & 7;                                            \
        uint32_t so = (uint32_t)(row * 128 + ((ch ^ (row & 7)) << 4));           \
        CP_ASYNC16(base + AT_B + so, Bp + (size_t)(n0 + row) * 1024 + ch * 8 + k0); \
    }                                                                            \
    CP_COMMIT();                                                                 \
} while (0)

    LOAD_STAGE(0, 0);

    for (int it = 0; it < 16; it++) {
        int s = it & 1;
        CP_WAIT0();
        __syncthreads();
        if (it + 1 < 16) LOAD_STAGE(it + 1, s ^ 1);
        uint32_t base = sb + s * STG_B;

#pragma unroll
        for (int kk = 0; kk < 4; kk++) {
            uint32_t ah[4][4];
#pragma unroll
            for (int mi = 0; mi < 4; mi++) {
                int r = a_rb + mi * 16;
                int c2 = kk * 2 + a_cb;
                uint32_t addr = base + (uint32_t)(r * 128 + ((c2 ^ (r & 7)) << 4));
                ldsm_x4(ah[mi][0], ah[mi][1], ah[mi][2], ah[mi][3], addr);
            }
#pragma unroll
            for (int nh = 0; nh < 4; nh++) {
                int r = wn * 64 + nh * 16 + ((lane >> 4) * 8) + (lane & 7);
                int c2 = kk * 2 + b_cb;
                uint32_t addr = base + AT_B
                              + (uint32_t)(r * 128 + ((c2 ^ (r & 7)) << 4));
                uint32_t bh[4];
                ldsm_x4(bh[0], bh[1], bh[2], bh[3], addr);
#pragma unroll
                for (int mi = 0; mi < 4; mi++)
#pragma unroll
                    for (int q = 0; q < 2; q++)
                        mma_fp16(acc[mi][nh * 2 + q], ah[mi], bh[q * 2], bh[q * 2 + 1]);
            }
        }
    }

    // ---------------- epilogue -------------------------------------------
    const int wnb = n0 + wn * 64;                 // multiple of 64
    if (MODE == 0) {
        const int sIdx = wnb >> 10;
        const int h    = (wnb >> 6) & 15;
        __half* dst = (sIdx == 0) ? g_q_h : (sIdx == 1) ? g_k_h : g_v_h;
#pragma unroll
        for (int mi = 0; mi < 4; mi++)
#pragma unroll
            for (int half = 0; half < 2; half++) {
                int row = m0 + wm * 64 + mi * 16 + (lane >> 2) + half * 8;
                int b = row >> 10, l = row & 1023;
                size_t rbase = ((size_t)(b * H_ + h) * L_ + l) * HD;
#pragma unroll
                for (int nh = 0; nh < 4; nh++)
#pragma unroll
                    for (int q = 0; q < 2; q++) {
                        int d = nh * 16 + q * 8 + (lane & 3) * 2;
                        __half2 hv = __floats2half2_rn(acc[mi][nh * 2 + q][half * 2],
                                                       acc[mi][nh * 2 + q][half * 2 + 1]);
                        *(__half2*)&dst[rbase + d] = hv;
                    }
            }
    } else {
#pragma unroll
        for (int mi = 0; mi < 4; mi++)
#pragma unroll
            for (int half = 0; half < 2; half++) {
                int row = m0 + wm * 64 + mi * 16 + (lane >> 2) + half * 8;
#pragma unroll
                for (int nh = 0; nh < 4; nh++)
#pragma unroll
                    for (int q = 0; q < 2; q++) {
                        int n = wnb + nh * 16 + q * 8 + (lane & 3) * 2;
                        *(float2*)&C[(size_t)row * 1024 + n] =
                            make_float2(acc[mi][nh * 2 + q][half * 2],
                                        acc[mi][nh * 2 + q][half * 2 + 1]);
                    }
            }
    }
#undef LOAD_STAGE
}

// ---------------------------------------------------------------------------
// Tensor-core attention v4: 512 threads (16 warps) to halve the per-CTA
// critical path.  Warp (wm = warp&3: 16 rows; wn = warp>>2: 0..3).
// fp16 mma, fp32 softmax.  smem map unchanged from R11.
// ---------------------------------------------------------------------------
#define OFF_Q    0
#define OFF_K0   8192
#define OFF_K1   16384
#define OFF_R    24576
#define OFF_QE   40960
#define OFF_S    61440
#define ATT_SMEM (61440 + 83968)
#define SP 328
#define QEP 80

// one 64x64 fp16 tile via cp.async: 512 threads, 1 chunk each
__device__ __forceinline__ void issue_tile(uint32_t dst, const __half* g,
                                           int rowbase, int t) {
    int row = t >> 3, ch = t & 7;
    uint32_t so = (uint32_t)(row * 128 + ((ch ^ (row & 7)) << 4));
    CP_ASYNC16(dst + so, g + (size_t)(rowbase + row) * 64 + ch * 8);
}

__global__ void __launch_bounds__(512, 1) attn_mma(const float* __restrict__ rel_emb) {
    extern __shared__ char smc[];
    uint32_t sb = smem_u32(smc);
    float* Sf  = (float*)(smc + OFF_S);
    float* qEf = (float*)(smc + OFF_QE);

    const int t = threadIdx.x, lane = t & 31, warp = t >> 5;
    const int wm = warp & 3, wn = warp >> 2;
    const int qt0 = blockIdx.x * 64;
    const int bh  = blockIdx.y;
    const __half* gq = g_q_h + (size_t)bh * L_ * HD;
    const __half* gk = g_k_h + (size_t)bh * L_ * HD;
    const __half* gv = g_v_h + (size_t)bh * L_ * HD;

    const int a_rb = wm * 16 + (lane & 15);                       // m16 per warp
    const int a_cb = (lane >> 4);
    const int b_rb16 = wn * 16 + ((lane >> 4) * 8) + (lane & 7);
    const int b_cb = (lane >> 3) & 1;

    int first_kb = 4 - (int)blockIdx.x;
    if (first_kb < 0) first_kb = 0;

    // ---------- phase 0: async Q + first K; convert R ----------------------
    issue_tile(sb + OFF_Q, gq, qt0, t);
    CP_COMMIT();
    issue_tile(sb + OFF_K0, gk, qt0 - 256 + first_kb * 64, t);
    CP_COMMIT();

    // zero R rows 65..127 (disjoint from fill)
    for (int i = t; i < 63 * 8; i += 512) {
        int row = 65 + (i >> 3), ch = i & 7;
        *(uint4*)(smc + OFF_R + row * 128 + ch * 16) = make_uint4(0, 0, 0, 0);
    }
    // fill R rows 0..64 (fp32 -> fp16, swizzled)
    for (int idx = t; idx < 65 * 16; idx += 512) {
        int r = idx >> 4, c4 = idx & 15;
        float4 v = *(const float4*)&rel_emb[r * HD + c4 * 4];
        *(uint2*)(smc + OFF_R + sw_off4(r, c4)) = f4_to_h4(v);
    }
    CP_WAIT1();
    __syncthreads();

    // ---------- phase 1: qE = Q * R^T  (warp tile m16 x n32) ----------------
    {
        float qa[2][2][4];    // nh, q
#pragma unroll
        for (int nh = 0; nh < 2; nh++)
#pragma unroll
            for (int q = 0; q < 2; q++)
#pragma unroll
                for (int e = 0; e < 4; e++) qa[nh][q][e] = 0.f;

#pragma unroll
        for (int kk = 0; kk < 4; kk++) {
            uint32_t ah[4];
            {
                int r = a_rb;
                int c = kk * 2 + a_cb;
                ldsm_x4(ah[0], ah[1], ah[2], ah[3],
                        sb + OFF_Q + (uint32_t)(r * 128 + ((c ^ (r & 7)) << 4)));
            }
            uint32_t bh[2][4];
#pragma unroll
            for (int nh = 0; nh < 2; nh++) {
                int r = wn * 32 + nh * 16 + ((lane >> 4) * 8) + (lane & 7);
                int c = kk * 2 + b_cb;
                ldsm_x4(bh[nh][0], bh[nh][1], bh[nh][2], bh[nh][3],
                        sb + OFF_R + (uint32_t)(r * 128 + ((c ^ (r & 7)) << 4)));
            }
#pragma unroll
            for (int nh = 0; nh < 2; nh++)
#pragma unroll
                for (int q = 0; q < 2; q++)
                    mma_fp16(qa[nh][q], ah, bh[nh][q * 2], bh[nh][q * 2 + 1]);
        }
#pragma unroll
        for (int nh = 0; nh < 2; nh++)
#pragma unroll
            for (int q = 0; q < 2; q++)
#pragma unroll
                for (int half = 0; half < 2; half++) {
                    int row = wm * 16 + (lane >> 2) + half * 8;
                    int col = wn * 32 + nh * 16 + q * 8 + (lane & 3) * 2;
                    if (col < 72) {
                        qEf[row * QEP + col]     = qa[nh][q][half * 2];
                        qEf[row * QEP + col + 1] = qa[nh][q][half * 2 + 1];
                    }
                }
    }

    for (int kbk = 0; kbk < first_kb; kbk++)
        for (int e = t; e < 4096; e += 512)
            Sf[(e >> 6) * SP + kbk * 64 + (e & 63)] = -1e30f;

    // ---------- phase 2: scores, double-buffered K (warp m16 x n16) --------
    for (int kbk = first_kb; kbk < 5; kbk++) {
        int kb0 = qt0 - 256 + kbk * 64;
        int bufi = (kbk - first_kb) & 1;
        uint32_t kbase = sb + OFF_K0 + bufi * 8192;

        CP_WAIT0();
        __syncthreads();
        if (kbk < 4) {
            issue_tile(sb + OFF_K0 + (1 - bufi) * 8192, gk, kb0 + 64, t);
            CP_COMMIT();
        }

        float sc[2][4];
#pragma unroll
        for (int q = 0; q < 2; q++)
#pragma unroll
            for (int e = 0; e < 4; e++) sc[q][e] = 0.f;

#pragma unroll
        for (int kk = 0; kk < 4; kk++) {
            uint32_t ah[4];
            {
                int r = a_rb;
                int c = kk * 2 + a_cb;
                ldsm_x4(ah[0], ah[1], ah[2], ah[3],
                        sb + OFF_Q + (uint32_t)(r * 128 + ((c ^ (r & 7)) << 4)));
            }
            uint32_t bh[4];
            {
                int r = b_rb16;
                int c = kk * 2 + b_cb;
                ldsm_x4(bh[0], bh[1], bh[2], bh[3],
                        kbase + (uint32_t)(r * 128 + ((c ^ (r & 7)) << 4)));
            }
#pragma unroll
            for (int q = 0; q < 2; q++)
                mma_fp16(sc[q], ah, bh[q * 2], bh[q * 2 + 1]);
        }
#pragma unroll
        for (int q = 0; q < 2; q++)
#pragma unroll
            for (int half = 0; half < 2; half++)
#pragma unroll
                for (int dd = 0; dd < 2; dd++) {
                    int row = wm * 16 + (lane >> 2) + half * 8;
                    int col = wn * 16 + q * 8 + (lane & 3) * 2 + dd;
                    int i = qt0 + row, j = kb0 + col;
                    float val;
                    if (j > i || (i - j) >= 256) {
                        val = -1e30f;
                    } else {
                        int rel = j - i + 64;
                        if (rel < 0) rel = 0;
                        val = (sc[q][half * 2 + dd] + qEf[row * QEP + rel]) * 0.125f;
                    }
                    Sf[row * SP + kbk * 64 + col] = val;
                }
    }
    __syncthreads();

    // prefetch first V block into buf0
    issue_tile(sb + OFF_K0, gv, qt0 - 256 + first_kb * 64, t);
    CP_COMMIT();

    // ---------- phase 3: row softmax (fp32, 320 cols; 4 rows/warp) ---------
    {
        for (int r = warp * 4; r < warp * 4 + 4; r++) {
            float mx = -1e30f;
            for (int c = lane; c < 320; c += 32) mx = fmaxf(mx, Sf[r * SP + c]);
#pragma unroll
            for (int o = 16; o > 0; o >>= 1)
                mx = fmaxf(mx, __shfl_xor_sync(0xffffffffu, mx, o));
            float sum = 0.f;
            for (int c = lane; c < 320; c += 32) {
                float p = __expf(Sf[r * SP + c] - mx);
                Sf[r * SP + c] = p;
                sum += p;
            }
#pragma unroll
            for (int o = 16; o > 0; o >>= 1)
                sum += __shfl_xor_sync(0xffffffffu, sum, o);
            float inv = 1.f / sum;
            for (int c = lane; c < 320; c += 32) Sf[r * SP + c] *= inv;
        }
    }
    __syncthreads();

    // ---------- phase 4: out = P * V (warp m16 x d16) ----------------------
    float oac[2][4];
#pragma unroll
    for (int q = 0; q < 2; q++)
#pragma unroll
        for (int e = 0; e < 4; e++) oac[q][e] = 0.f;

    for (int kbk = first_kb; kbk < 5; kbk++) {
        int kb0 = qt0 - 256 + kbk * 64;
        int bufi = (kbk - first_kb) & 1;
        uint32_t vbase = sb + OFF_K0 + bufi * 8192;
        int p_off = bufi ? OFF_R : OFF_Q;

        // convert P(kbk) to fp16 (own buffer free; overlaps V flight)
        {
            int row = t >> 3;
            int cbq = (t & 7) * 2;
#pragma unroll
            for (int q4 = 0; q4 < 2; q4++) {
                int c4 = cbq + q4;
                float4 v = *(const float4*)&Sf[row * SP + kbk * 64 + c4 * 4];
                *(uint2*)(smc + p_off + sw_off4(row, c4)) = f4_to_h4(v);
            }
        }
        CP_WAIT0();
        __syncthreads();
        if (kbk < 4) {
            issue_tile(sb + OFF_K0 + (1 - bufi) * 8192, gv, kb0 + 64, t);
            CP_COMMIT();
        }

#pragma unroll
        for (int kk = 0; kk < 4; kk++) {
            uint32_t ah[4];
            {
                int r = a_rb;
                int c = kk * 2 + a_cb;
                ldsm_x4(ah[0], ah[1], ah[2], ah[3],
                        sb + p_off + (uint32_t)(r * 128 + ((c ^ (r & 7)) << 4)));
            }
            uint32_t bh[4];
            {
                int vrow = kk * 16 + (lane & 7) + ((lane >> 3) & 1) * 8;
                int vch  = wn * 2 + (lane >> 4);
                ldsm_x4_t(bh[0], bh[1], bh[2], bh[3],
                          vbase + (uint32_t)(vrow * 128 + ((vch ^ (vrow & 7)) << 4)));
            }
#pragma unroll
            for (int q = 0; q < 2; q++)
                mma_fp16(oac[q], ah, bh[q * 2], bh[q * 2 + 1]);
        }
    }

    // ---------- epilogue: write att fp16 in [B,L,H*hd] ---------------------
    {
        int b = bh >> 4, h = bh & 15;
#pragma unroll
        for (int q = 0; q < 2; q++)
#pragma unroll
            for (int half = 0; half < 2; half++) {
                int row = wm * 16 + (lane >> 2) + half * 8;
                int i = qt0 + row;
                int d = wn * 16 + q * 8 + (lane & 3) * 2;
                __half2 hv = __floats2half2_rn(oac[q][half * 2],
                                               oac[q][half * 2 + 1]);
                size_t off = ((size_t)(b * L_ + i) * H_ + h) * HD + d;
                *(__half2*)&g_att_h[off] = hv;
            }
    }
}

// ---------------------------------------------------------------------------
extern "C" void kernel_launch(void* const* d_in, const int* in_sizes, int n_in,
                              void* d_out, int out_size) {
    const float* x       = (const float*)d_in[0];
    const float* w_qkv   = (const float*)d_in[1];
    const float* w_out   = (const float*)d_in[2];
    const float* rel_emb = (const float*)d_in[3];
    float* out = (float*)d_out;

    (void)in_sizes; (void)n_in; (void)out_size;

    cudaFuncSetAttribute(attn_mma,
                         cudaFuncAttributeMaxDynamicSharedMemorySize, ATT_SMEM);
    cudaFuncSetAttribute(tc_gemm<0>,
                         cudaFuncAttributeMaxDynamicSharedMemorySize, TC_SMEM);
    cudaFuncSetAttribute(tc_gemm<1>,
                         cudaFuncAttributeMaxDynamicSharedMemorySize, TC_SMEM);

    cvt_h<0><<<(B_ * L_ * D_ / 4 + 255) / 256, 256>>>(x,    B_ * L_ * D_ / 4);
    cvt_h<1><<<(3 * D_ * D_ / 4 + 255) / 256, 256>>>(w_qkv, 3 * D_ * D_ / 4);
    cvt_h<2><<<(D_ * D_ / 4 + 255) / 256, 256>>>(w_out,     D_ * D_ / 4);

    tc_gemm<0><<<dim3(3072 / 256, 4096 / 128), 256, TC_SMEM>>>(nullptr);

    attn_mma<<<dim3(L_ / 64, NBH), 512, ATT_SMEM>>>(rel_emb);

    tc_gemm<1><<<dim3(1024 / 256, 4096 / 128), 256, TC_SMEM>>>(out);
}

// round 13
// speedup vs baseline: 6.8984x; 1.1478x over previous
#include <cuda_runtime.h>
#include <cuda_fp16.h>
#include <cstdint>

#define B_  4
#define L_  1024
#define D_  1024
#define H_  16
#define HD  64
#define NBH (B_ * H_)   // 64

// ---------------------------------------------------------------------------
// Static device scratch (no allocation allowed) — single fp16 everywhere
// ---------------------------------------------------------------------------
__device__ __half g_q_h[NBH * L_ * HD];
__device__ __half g_k_h[NBH * L_ * HD];
__device__ __half g_v_h[NBH * L_ * HD];

__device__ __half g_x_h[B_ * L_ * D_];
__device__ __half g_wqkv_h[3 * D_ * D_];
__device__ __half g_wout_h[D_ * D_];
__device__ __half g_att_h[B_ * L_ * D_];

// ---------------------------------------------------------------------------
// PTX helpers (base ISA only)
// ---------------------------------------------------------------------------
__device__ __forceinline__ uint32_t smem_u32(const void* p) {
    uint32_t a;
    asm("{ .reg .u64 t; cvta.to.shared.u64 t, %1; cvt.u32.u64 %0, t; }" : "=r"(a) : "l"(p));
    return a;
}

#define CP_ASYNC16(dst, src) \
    asm volatile("cp.async.cg.shared.global [%0], [%1], 16;" :: "r"(dst), "l"(src))
#define CP_COMMIT() asm volatile("cp.async.commit_group;" ::: "memory")
#define CP_WAIT0()  asm volatile("cp.async.wait_group 0;" ::: "memory")
#define CP_WAIT1()  asm volatile("cp.async.wait_group 1;" ::: "memory")

__device__ __forceinline__ void ldsm_x4(uint32_t& r0, uint32_t& r1, uint32_t& r2,
                                        uint32_t& r3, uint32_t addr) {
    asm volatile("ldmatrix.sync.aligned.m8n8.x4.shared.b16 {%0,%1,%2,%3}, [%4];"
                 : "=r"(r0), "=r"(r1), "=r"(r2), "=r"(r3) : "r"(addr));
}
__device__ __forceinline__ void ldsm_x4_t(uint32_t& r0, uint32_t& r1, uint32_t& r2,
                                          uint32_t& r3, uint32_t addr) {
    asm volatile("ldmatrix.sync.aligned.m8n8.x4.trans.shared.b16 {%0,%1,%2,%3}, [%4];"
                 : "=r"(r0), "=r"(r1), "=r"(r2), "=r"(r3) : "r"(addr));
}

__device__ __forceinline__ void mma_fp16(float* d, const uint32_t* a,
                                         uint32_t b0, uint32_t b1) {
    asm volatile(
        "mma.sync.aligned.m16n8k16.row.col.f32.f16.f16.f32 "
        "{%0,%1,%2,%3}, {%4,%5,%6,%7}, {%8,%9}, {%0,%1,%2,%3};"
        : "+f"(d[0]), "+f"(d[1]), "+f"(d[2]), "+f"(d[3])
        : "r"(a[0]), "r"(a[1]), "r"(a[2]), "r"(a[3]), "r"(b0), "r"(b1));
}

// fp32x4 -> packed fp16x4
__device__ __forceinline__ uint2 f4_to_h4(float4 v) {
    __half2 a = __floats2half2_rn(v.x, v.y);
    __half2 b = __floats2half2_rn(v.z, v.w);
    return make_uint2(*(uint32_t*)&a, *(uint32_t*)&b);
}
__device__ __forceinline__ uint32_t f2_to_h2(float a, float b) {
    __half2 h = __floats2half2_rn(a, b);
    return *(uint32_t*)&h;
}

// swizzled byte offset of float4-chunk c4 in a 128B-row 16-bit tile
__device__ __forceinline__ uint32_t sw_off4(int row, int c4) {
    return (uint32_t)(row * 128 + ((((c4 >> 1) ^ (row & 7)) << 4) | ((c4 & 1) << 3)));
}

// ---------------------------------------------------------------------------
// fp32 -> fp16 conversion.  W: 0=x, 1=wqkv, 2=wout
// ---------------------------------------------------------------------------
template <int W>
__global__ void __launch_bounds__(256) cvt_h(const float* __restrict__ src, int n4) {
    __half* dst = (W == 0) ? g_x_h : (W == 1) ? g_wqkv_h : g_wout_h;
    int i = blockIdx.x * 256 + threadIdx.x;
    if (i >= n4) return;
    float4 v = ((const float4*)src)[i];
    ((uint2*)dst)[i] = f4_to_h4(v);
}

// ---------------------------------------------------------------------------
// Warp-mma fp16 GEMM NT (R12, unchanged): CTA 128x256, 8 warps, warp 64x64.
// ---------------------------------------------------------------------------
#define AT_B  16384
#define BT_B  32768
#define STG_B (AT_B + BT_B)
#define TC_SMEM (2 * STG_B)   // 98304

template <int MODE>
__global__ void __launch_bounds__(256, 1) tc_gemm(float* __restrict__ C) {
    extern __shared__ char smc[];
    uint32_t sb = smem_u32(smc);

    const __half* A  = (MODE == 0) ? g_x_h : g_att_h;
    const __half* Bp = (MODE == 0) ? g_wqkv_h : g_wout_h;

    const int t = threadIdx.x, lane = t & 31, warp = t >> 5;
    const int wm = warp & 1, wn = warp >> 1;
    const int m0 = blockIdx.y * 128, n0 = blockIdx.x * 256;

    float acc[4][8][4];
#pragma unroll
    for (int mi = 0; mi < 4; mi++)
#pragma unroll
        for (int ni = 0; ni < 8; ni++)
#pragma unroll
            for (int e = 0; e < 4; e++) acc[mi][ni][e] = 0.f;

    const int a_rb = wm * 64 + (lane & 15);
    const int a_cb = (lane >> 4);
    const int b_cb = (lane >> 3) & 1;

#define LOAD_STAGE(it, s) do {                                                   \
    uint32_t base = sb + (s) * STG_B;                                            \
    int k0 = (it) * 64;                                                          \
    _Pragma("unroll")                                                            \
    for (int j = 0; j < 4; j++) {                                                \
        int c = t + 256 * j;                                                     \
        int row = c >> 3, ch = c & 7;                                            \
        uint32_t so = (uint32_t)(row * 128 + ((ch ^ (row & 7)) << 4));           \
        CP_ASYNC16(base + so, A + (size_t)(m0 + row) * 1024 + ch * 8 + k0);      \
    }                                                                            \
    _Pragma("unroll")                                                            \
    for (int j = 0; j < 8; j++) {                                                \
        int c = t + 256 * j;                                                     \
        int row = c >> 3, ch = c & 7;                                            \
        uint32_t so = (uint32_t)(row * 128 + ((ch ^ (row & 7)) << 4));           \
        CP_ASYNC16(base + AT_B + so, Bp + (size_t)(n0 + row) * 1024 + ch * 8 + k0); \
    }                                                                            \
    CP_COMMIT();                                                                 \
} while (0)

    LOAD_STAGE(0, 0);

    for (int it = 0; it < 16; it++) {
        int s = it & 1;
        CP_WAIT0();
        __syncthreads();
        if (it + 1 < 16) LOAD_STAGE(it + 1, s ^ 1);
        uint32_t base = sb + s * STG_B;

#pragma unroll
        for (int kk = 0; kk < 4; kk++) {
            uint32_t ah[4][4];
#pragma unroll
            for (int mi = 0; mi < 4; mi++) {
                int r = a_rb + mi * 16;
                int c2 = kk * 2 + a_cb;
                uint32_t addr = base + (uint32_t)(r * 128 + ((c2 ^ (r & 7)) << 4));
                ldsm_x4(ah[mi][0], ah[mi][1], ah[mi][2], ah[mi][3], addr);
            }
#pragma unroll
            for (int nh = 0; nh < 4; nh++) {
                int r = wn * 64 + nh * 16 + ((lane >> 4) * 8) + (lane & 7);
                int c2 = kk * 2 + b_cb;
                uint32_t addr = base + AT_B
                              + (uint32_t)(r * 128 + ((c2 ^ (r & 7)) << 4));
                uint32_t bh[4];
                ldsm_x4(bh[0], bh[1], bh[2], bh[3], addr);
#pragma unroll
                for (int mi = 0; mi < 4; mi++)
#pragma unroll
                    for (int q = 0; q < 2; q++)
                        mma_fp16(acc[mi][nh * 2 + q], ah[mi], bh[q * 2], bh[q * 2 + 1]);
            }
        }
    }

    const int wnb = n0 + wn * 64;
    if (MODE == 0) {
        const int sIdx = wnb >> 10;
        const int h    = (wnb >> 6) & 15;
        __half* dst = (sIdx == 0) ? g_q_h : (sIdx == 1) ? g_k_h : g_v_h;
#pragma unroll
        for (int mi = 0; mi < 4; mi++)
#pragma unroll
            for (int half = 0; half < 2; half++) {
                int row = m0 + wm * 64 + mi * 16 + (lane >> 2) + half * 8;
                int b = row >> 10, l = row & 1023;
                size_t rbase = ((size_t)(b * H_ + h) * L_ + l) * HD;
#pragma unroll
                for (int nh = 0; nh < 4; nh++)
#pragma unroll
                    for (int q = 0; q < 2; q++) {
                        int d = nh * 16 + q * 8 + (lane & 3) * 2;
                        __half2 hv = __floats2half2_rn(acc[mi][nh * 2 + q][half * 2],
                                                       acc[mi][nh * 2 + q][half * 2 + 1]);
                        *(__half2*)&dst[rbase + d] = hv;
                    }
            }
    } else {
#pragma unroll
        for (int mi = 0; mi < 4; mi++)
#pragma unroll
            for (int half = 0; half < 2; half++) {
                int row = m0 + wm * 64 + mi * 16 + (lane >> 2) + half * 8;
#pragma unroll
                for (int nh = 0; nh < 4; nh++)
#pragma unroll
                    for (int q = 0; q < 2; q++) {
                        int n = wnb + nh * 16 + q * 8 + (lane & 3) * 2;
                        *(float2*)&C[(size_t)row * 1024 + n] =
                            make_float2(acc[mi][nh * 2 + q][half * 2],
                                        acc[mi][nh * 2 + q][half * 2 + 1]);
                    }
            }
    }
#undef LOAD_STAGE
}

// ---------------------------------------------------------------------------
// Flash attention: CTA = (b,h) x 128-query tile, 256 threads (8 warps).
// Warp owns 16 rows (tile = warp>>2, wr = warp&3).  Streams 6 key blocks of
// 64 with online softmax; P stays in registers (acc->A fragment identity).
// smem: Q 16K | K0 8K | V0 8K | K1 8K | V1 8K | R 16K | qE 40K = 104 KB.
// ---------------------------------------------------------------------------
#define FA_Q    0
#define FA_K0   16384
#define FA_V0   24576
#define FA_K1   32768
#define FA_V1   40960
#define FA_R    49152
#define FA_QE   65536
#define FA_SMEM (65536 + 40960)   // 106496
#define QEP 80

// one 64x64 fp16 tile via cp.async (2 chunks/thread, 256 threads)
__device__ __forceinline__ void fa_tile64(uint32_t dst, const __half* g,
                                          int rowbase, int t) {
#pragma unroll
    for (int j = 0; j < 2; j++) {
        int c = t + 256 * j;
        int row = c >> 3, ch = c & 7;
        uint32_t so = (uint32_t)(row * 128 + ((ch ^ (row & 7)) << 4));
        CP_ASYNC16(dst + so, g + (size_t)(rowbase + row) * 64 + ch * 8);
    }
}

__global__ void __launch_bounds__(256, 2) attn_flash(const float* __restrict__ rel_emb) {
    extern __shared__ char smc[];
    uint32_t sb = smem_u32(smc);
    float* qEf = (float*)(smc + FA_QE);

    const int t = threadIdx.x, lane = t & 31, warp = t >> 5;
    const int qt0 = blockIdx.x * 128;
    const int bh  = blockIdx.y;
    const int rowbase = (warp >> 2) * 64 + (warp & 3) * 16;   // CTA-local row base
    const __half* gq = g_q_h + (size_t)bh * L_ * HD;
    const __half* gk = g_k_h + (size_t)bh * L_ * HD;
    const __half* gv = g_v_h + (size_t)bh * L_ * HD;

    const int a_rb = rowbase + (lane & 15);
    const int a_cb = (lane >> 4);

    int first_kb = 4 - 2 * (int)blockIdx.x;
    if (first_kb < 0) first_kb = 0;

    // ---------- phase 0: Q (cp.async), first K/V, R conversion -------------
    {   // Q: 128x64 fp16, 4 chunks/thread
#pragma unroll
        for (int j = 0; j < 4; j++) {
            int c = t + 256 * j;
            int row = c >> 3, ch = c & 7;
            uint32_t so = (uint32_t)(row * 128 + ((ch ^ (row & 7)) << 4));
            CP_ASYNC16(sb + FA_Q + so, gq + (size_t)(qt0 + row) * 64 + ch * 8);
        }
        CP_COMMIT();
    }
    {
        int kb0 = qt0 - 256 + first_kb * 64;
        fa_tile64(sb + FA_K0, gk, kb0, t);
        fa_tile64(sb + FA_V0, gv, kb0, t);
        CP_COMMIT();
    }
    // zero R rows 65..127, fill 0..64
    for (int i = t; i < 63 * 8; i += 256) {
        int row = 65 + (i >> 3), ch = i & 7;
        *(uint4*)(smc + FA_R + row * 128 + ch * 16) = make_uint4(0, 0, 0, 0);
    }
    for (int idx = t; idx < 65 * 16; idx += 256) {
        int r = idx >> 4, c4 = idx & 15;
        float4 v = *(const float4*)&rel_emb[r * HD + c4 * 4];
        *(uint2*)(smc + FA_R + sw_off4(r, c4)) = f4_to_h4(v);
    }
    CP_WAIT1();          // Q landed
    __syncthreads();

    // ---------- phase 1: qE = Q * R^T (warp m16 x n80), warp-private -------
    {
        float qa[10][4];
#pragma unroll
        for (int ni = 0; ni < 10; ni++)
#pragma unroll
            for (int e = 0; e < 4; e++) qa[ni][e] = 0.f;
#pragma unroll
        for (int kk = 0; kk < 4; kk++) {
            uint32_t ah[4];
            {
                int r = a_rb, c = kk * 2 + a_cb;
                ldsm_x4(ah[0], ah[1], ah[2], ah[3],
                        sb + FA_Q + (uint32_t)(r * 128 + ((c ^ (r & 7)) << 4)));
            }
#pragma unroll
            for (int g = 0; g < 5; g++) {
                int r = g * 16 + ((lane >> 4) * 8) + (lane & 7);
                int c = kk * 2 + ((lane >> 3) & 1);
                uint32_t bhf[4];
                ldsm_x4(bhf[0], bhf[1], bhf[2], bhf[3],
                        sb + FA_R + (uint32_t)(r * 128 + ((c ^ (r & 7)) << 4)));
                mma_fp16(qa[g * 2], ah, bhf[0], bhf[1]);
                mma_fp16(qa[g * 2 + 1], ah, bhf[2], bhf[3]);
            }
        }
#pragma unroll
        for (int ni = 0; ni < 10; ni++)
#pragma unroll
            for (int half = 0; half < 2; half++) {
                int row = rowbase + (lane >> 2) + half * 8;
                int col = ni * 8 + (lane & 3) * 2;
                qEf[row * QEP + col]     = qa[ni][half * 2];
                qEf[row * QEP + col + 1] = qa[ni][half * 2 + 1];
            }
        __syncwarp();   // qE rows are warp-private
    }

    // ---------- main loop: stream key blocks with online softmax ----------
    float oac[8][4];
#pragma unroll
    for (int ni = 0; ni < 8; ni++)
#pragma unroll
        for (int e = 0; e < 4; e++) oac[ni][e] = 0.f;
    float mrow[2] = {-1e30f, -1e30f};
    float srow[2] = {0.f, 0.f};

    const int qb = qt0 + rowbase;            // warp's first global row

    for (int kbk = first_kb; kbk < 6; kbk++) {
        int kb0 = qt0 - 256 + kbk * 64;
        int bufi = (kbk - first_kb) & 1;
        uint32_t kbase = sb + FA_K0 + bufi * 16384;   // K; V at +8192

        CP_WAIT0();
        __syncthreads();
        if (kbk < 5) {
            fa_tile64(sb + FA_K0 + (1 - bufi) * 16384, gk, kb0 + 64, t);
            fa_tile64(sb + FA_V0 + (1 - bufi) * 16384, gv, kb0 + 64, t);
            CP_COMMIT();
        }

        // per-warp block skip (fully future / fully stale)
        if (kb0 > qb + 15 || kb0 + 63 <= qb - 256) continue;

        // --- QK: sc = Q[rows] * K^T, m16 x n64 ---
        float sc[8][4];
#pragma unroll
        for (int ni = 0; ni < 8; ni++)
#pragma unroll
            for (int e = 0; e < 4; e++) sc[ni][e] = 0.f;
#pragma unroll
        for (int kk = 0; kk < 4; kk++) {
            uint32_t ah[4];
            {
                int r = a_rb, c = kk * 2 + a_cb;
                ldsm_x4(ah[0], ah[1], ah[2], ah[3],
                        sb + FA_Q + (uint32_t)(r * 128 + ((c ^ (r & 7)) << 4)));
            }
#pragma unroll
            for (int g = 0; g < 4; g++) {
                int r = g * 16 + ((lane >> 4) * 8) + (lane & 7);
                int c = kk * 2 + ((lane >> 3) & 1);
                uint32_t bhf[4];
                ldsm_x4(bhf[0], bhf[1], bhf[2], bhf[3],
                        kbase + (uint32_t)(r * 128 + ((c ^ (r & 7)) << 4)));
                mma_fp16(sc[g * 2], ah, bhf[0], bhf[1]);
                mma_fp16(sc[g * 2 + 1], ah, bhf[2], bhf[3]);
            }
        }

        // --- mask + qE + scale; online softmax update (per row half) ------
        uint32_t pa[4][4];      // P as A-fragments per k16 chunk
#pragma unroll
        for (int h = 0; h < 2; h++) {
            int rl = rowbase + (lane >> 2) + h * 8;   // CTA-local row
            int i  = qt0 + rl;                        // global row
            float mx = -1e30f;
#pragma unroll
            for (int ni = 0; ni < 8; ni++)
#pragma unroll
                for (int dd = 0; dd < 2; dd++) {
                    int j = kb0 + ni * 8 + (lane & 3) * 2 + dd;
                    float v;
                    if (j > i || i - j >= 256) {
                        v = -1e30f;
                    } else {
                        int rel = j - i + 64;
                        if (rel < 0) rel = 0;
                        v = (sc[ni][h * 2 + dd] + qEf[rl * QEP + rel]) * 0.125f;
                    }
                    sc[ni][h * 2 + dd] = v;
                    mx = fmaxf(mx, v);
                }
            mx = fmaxf(mx, __shfl_xor_sync(0xffffffffu, mx, 1));
            mx = fmaxf(mx, __shfl_xor_sync(0xffffffffu, mx, 2));
            bool valid = mx > -0.5e30f;
            float mn = valid ? fmaxf(mrow[h], mx) : mrow[h];
            float corr = valid ? __expf(mrow[h] - mn) : 1.f;
            float rs = 0.f;
#pragma unroll
            for (int ni = 0; ni < 8; ni++)
#pragma unroll
                for (int dd = 0; dd < 2; dd++) {
                    float p = __expf(sc[ni][h * 2 + dd] - mn);
                    p = valid ? p : 0.f;
                    sc[ni][h * 2 + dd] = p;
                    rs += p;
                }
            rs += __shfl_xor_sync(0xffffffffu, rs, 1);
            rs += __shfl_xor_sync(0xffffffffu, rs, 2);
            srow[h] = srow[h] * corr + rs;
            mrow[h] = mn;
#pragma unroll
            for (int ni = 0; ni < 8; ni++) {
                oac[ni][h * 2]     *= corr;
                oac[ni][h * 2 + 1] *= corr;
            }
        }

        // pack P (acc layout -> A fragment layout, exact lane identity)
#pragma unroll
        for (int kk = 0; kk < 4; kk++) {
            pa[kk][0] = f2_to_h2(sc[2 * kk][0],     sc[2 * kk][1]);
            pa[kk][1] = f2_to_h2(sc[2 * kk][2],     sc[2 * kk][3]);
            pa[kk][2] = f2_to_h2(sc[2 * kk + 1][0], sc[2 * kk + 1][1]);
            pa[kk][3] = f2_to_h2(sc[2 * kk + 1][2], sc[2 * kk + 1][3]);
        }

        // --- PV: oac += P * V  (V via trans-ldmatrix, validated path) -----
#pragma unroll
        for (int kk = 0; kk < 4; kk++) {
#pragma unroll
            for (int dch = 0; dch < 4; dch++) {
                int vrow = kk * 16 + (lane & 7) + ((lane >> 3) & 1) * 8;
                int vch  = dch * 2 + (lane >> 4);
                uint32_t bhf[4];
                ldsm_x4_t(bhf[0], bhf[1], bhf[2], bhf[3],
                          kbase + 8192 +
                          (uint32_t)(vrow * 128 + ((vch ^ (vrow & 7)) << 4)));
                mma_fp16(oac[dch * 2],     pa[kk], bhf[0], bhf[1]);
                mma_fp16(oac[dch * 2 + 1], pa[kk], bhf[2], bhf[3]);
            }
        }
    }

    // ---------- epilogue: out = oac / srow, write fp16 to g_att -----------
    {
        int b = bh >> 4, hh = bh & 15;
#pragma unroll
        for (int h = 0; h < 2; h++) {
            float inv = 1.f / srow[h];
            int i = qt0 + rowbase + (lane >> 2) + h * 8;
#pragma unroll
            for (int ni = 0; ni < 8; ni++) {
                int d = ni * 8 + (lane & 3) * 2;
                __half2 hv = __floats2half2_rn(oac[ni][h * 2] * inv,
                                               oac[ni][h * 2 + 1] * inv);
                size_t off = ((size_t)(b * L_ + i) * H_ + hh) * HD + d;
                *(__half2*)&g_att_h[off] = hv;
            }
        }
    }
}

// ---------------------------------------------------------------------------
extern "C" void kernel_launch(void* const* d_in, const int* in_sizes, int n_in,
                              void* d_out, int out_size) {
    const float* x       = (const float*)d_in[0];
    const float* w_qkv   = (const float*)d_in[1];
    const float* w_out   = (const float*)d_in[2];
    const float* rel_emb = (const float*)d_in[3];
    float* out = (float*)d_out;

    (void)in_sizes; (void)n_in; (void)out_size;

    cudaFuncSetAttribute(attn_flash,
                         cudaFuncAttributeMaxDynamicSharedMemorySize, FA_SMEM);
    cudaFuncSetAttribute(tc_gemm<0>,
                         cudaFuncAttributeMaxDynamicSharedMemorySize, TC_SMEM);
    cudaFuncSetAttribute(tc_gemm<1>,
                         cudaFuncAttributeMaxDynamicSharedMemorySize, TC_SMEM);

    cvt_h<0><<<(B_ * L_ * D_ / 4 + 255) / 256, 256>>>(x,    B_ * L_ * D_ / 4);
    cvt_h<1><<<(3 * D_ * D_ / 4 + 255) / 256, 256>>>(w_qkv, 3 * D_ * D_ / 4);
    cvt_h<2><<<(D_ * D_ / 4 + 255) / 256, 256>>>(w_out,     D_ * D_ / 4);

    tc_gemm<0><<<dim3(3072 / 256, 4096 / 128), 256, TC_SMEM>>>(nullptr);

    attn_flash<<<dim3(L_ / 128, NBH), 256, FA_SMEM>>>(rel_emb);

    tc_gemm<1><<<dim3(1024 / 256, 4096 / 128), 256, TC_SMEM>>>(out);
}

// round 14
// speedup vs baseline: 7.0589x; 1.0233x over previous
#include <cuda_runtime.h>
#include <cuda_fp16.h>
#include <cstdint>

#define B_  4
#define L_  1024
#define D_  1024
#define H_  16
#define HD  64
#define NBH (B_ * H_)   // 64

// ---------------------------------------------------------------------------
// Static device scratch (no allocation allowed) — single fp16 everywhere
// ---------------------------------------------------------------------------
__device__ __half g_q_h[NBH * L_ * HD];
__device__ __half g_k_h[NBH * L_ * HD];
__device__ __half g_v_h[NBH * L_ * HD];

__device__ __half g_x_h[B_ * L_ * D_];
__device__ __half g_wqkv_h[3 * D_ * D_];
__device__ __half g_wout_h[D_ * D_];
__device__ __half g_att_h[B_ * L_ * D_];

// ---------------------------------------------------------------------------
// PTX helpers (base ISA only)
// ---------------------------------------------------------------------------
__device__ __forceinline__ uint32_t smem_u32(const void* p) {
    uint32_t a;
    asm("{ .reg .u64 t; cvta.to.shared.u64 t, %1; cvt.u32.u64 %0, t; }" : "=r"(a) : "l"(p));
    return a;
}

#define CP_ASYNC16(dst, src) \
    asm volatile("cp.async.cg.shared.global [%0], [%1], 16;" :: "r"(dst), "l"(src))
#define CP_COMMIT() asm volatile("cp.async.commit_group;" ::: "memory")
#define CP_WAIT0()  asm volatile("cp.async.wait_group 0;" ::: "memory")
#define CP_WAIT1()  asm volatile("cp.async.wait_group 1;" ::: "memory")

__device__ __forceinline__ void ldsm_x4(uint32_t& r0, uint32_t& r1, uint32_t& r2,
                                        uint32_t& r3, uint32_t addr) {
    asm volatile("ldmatrix.sync.aligned.m8n8.x4.shared.b16 {%0,%1,%2,%3}, [%4];"
                 : "=r"(r0), "=r"(r1), "=r"(r2), "=r"(r3) : "r"(addr));
}
__device__ __forceinline__ void ldsm_x4_t(uint32_t& r0, uint32_t& r1, uint32_t& r2,
                                          uint32_t& r3, uint32_t addr) {
    asm volatile("ldmatrix.sync.aligned.m8n8.x4.trans.shared.b16 {%0,%1,%2,%3}, [%4];"
                 : "=r"(r0), "=r"(r1), "=r"(r2), "=r"(r3) : "r"(addr));
}

__device__ __forceinline__ void mma_fp16(float* d, const uint32_t* a,
                                         uint32_t b0, uint32_t b1) {
    asm volatile(
        "mma.sync.aligned.m16n8k16.row.col.f32.f16.f16.f32 "
        "{%0,%1,%2,%3}, {%4,%5,%6,%7}, {%8,%9}, {%0,%1,%2,%3};"
        : "+f"(d[0]), "+f"(d[1]), "+f"(d[2]), "+f"(d[3])
        : "r"(a[0]), "r"(a[1]), "r"(a[2]), "r"(a[3]), "r"(b0), "r"(b1));
}

// fp32x4 -> packed fp16x4
__device__ __forceinline__ uint2 f4_to_h4(float4 v) {
    __half2 a = __floats2half2_rn(v.x, v.y);
    __half2 b = __floats2half2_rn(v.z, v.w);
    return make_uint2(*(uint32_t*)&a, *(uint32_t*)&b);
}
__device__ __forceinline__ uint32_t f2_to_h2(float a, float b) {
    __half2 h = __floats2half2_rn(a, b);
    return *(uint32_t*)&h;
}

// swizzled byte offset of float4-chunk c4 in a 128B-row 16-bit tile
__device__ __forceinline__ uint32_t sw_off4(int row, int c4) {
    return (uint32_t)(row * 128 + ((((c4 >> 1) ^ (row & 7)) << 4) | ((c4 & 1) << 3)));
}

// ---------------------------------------------------------------------------
// fp32 -> fp16 conversion.  W: 0=x, 1=wqkv, 2=wout
// ---------------------------------------------------------------------------
template <int W>
__global__ void __launch_bounds__(256) cvt_h(const float* __restrict__ src, int n4) {
    __half* dst = (W == 0) ? g_x_h : (W == 1) ? g_wqkv_h : g_wout_h;
    int i = blockIdx.x * 256 + threadIdx.x;
    if (i >= n4) return;
    float4 v = ((const float4*)src)[i];
    ((uint2*)dst)[i] = f4_to_h4(v);
}

// ---------------------------------------------------------------------------
// Warp-mma fp16 GEMM NT v5: CTA tile 128x128, 256 threads, warp 64x32
// (acc = 64 regs -> <=128 regs/thread -> 2 CTAs/SM; desynchronized CTAs
// fill each other's ldsm/sync gaps).  2-stage cp.async, 1 sync/iter.
// MODE 0: A=x, B=w_qkv -> scatter fp16 q/k/v.  MODE 1: A=att -> C fp32.
// ---------------------------------------------------------------------------
#define AT_B  16384                 // A tile (128x64 fp16)
#define GBT_B 16384                 // B tile (128x64 fp16)
#define STG_B (AT_B + GBT_B)        // 32768 per stage
#define TC_SMEM (2 * STG_B)         // 65536

template <int MODE>
__global__ void __launch_bounds__(256, 2) tc_gemm(float* __restrict__ C) {
    extern __shared__ char smc[];
    uint32_t sb = smem_u32(smc);

    const __half* A  = (MODE == 0) ? g_x_h : g_att_h;
    const __half* Bp = (MODE == 0) ? g_wqkv_h : g_wout_h;

    const int t = threadIdx.x, lane = t & 31, warp = t >> 5;
    const int wm = warp & 1, wn = warp >> 1;          // wn 0..3 (32 cols each)
    const int m0 = blockIdx.y * 128, n0 = blockIdx.x * 128;

    float acc[4][4][4];                               // 4 m16 x 4 n8
#pragma unroll
    for (int mi = 0; mi < 4; mi++)
#pragma unroll
        for (int ni = 0; ni < 4; ni++)
#pragma unroll
            for (int e = 0; e < 4; e++) acc[mi][ni][e] = 0.f;

    const int a_rb = wm * 64 + (lane & 15);
    const int a_cb = (lane >> 4);
    const int b_rb = wn * 32 + ((lane >> 4) * 8) + (lane & 7);
    const int b_cb = (lane >> 3) & 1;

#define LOAD_STAGE(it, s) do {                                                   \
    uint32_t base = sb + (s) * STG_B;                                            \
    int k0 = (it) * 64;                                                          \
    _Pragma("unroll")                                                            \
    for (int j = 0; j < 4; j++) {                                                \
        int c = t + 256 * j;                                                     \
        int row = c >> 3, ch = c & 7;                                            \
        uint32_t so = (uint32_t)(row * 128 + ((ch ^ (row & 7)) << 4));           \
        CP_ASYNC16(base + so, A + (size_t)(m0 + row) * 1024 + ch * 8 + k0);      \
        CP_ASYNC16(base + AT_B + so, Bp + (size_t)(n0 + row) * 1024 + ch * 8 + k0); \
    }                                                                            \
    CP_COMMIT();                                                                 \
} while (0)

    LOAD_STAGE(0, 0);

    for (int it = 0; it < 16; it++) {
        int s = it & 1;
        CP_WAIT0();
        __syncthreads();
        if (it + 1 < 16) LOAD_STAGE(it + 1, s ^ 1);
        uint32_t base = sb + s * STG_B;

#pragma unroll
        for (int kk = 0; kk < 4; kk++) {
            uint32_t ah[4][4];
#pragma unroll
            for (int mi = 0; mi < 4; mi++) {
                int r = a_rb + mi * 16;
                int c2 = kk * 2 + a_cb;
                uint32_t addr = base + (uint32_t)(r * 128 + ((c2 ^ (r & 7)) << 4));
                ldsm_x4(ah[mi][0], ah[mi][1], ah[mi][2], ah[mi][3], addr);
            }
#pragma unroll
            for (int nh = 0; nh < 2; nh++) {
                int r = b_rb + nh * 16;
                int c2 = kk * 2 + b_cb;
                uint32_t addr = base + AT_B
                              + (uint32_t)(r * 128 + ((c2 ^ (r & 7)) << 4));
                uint32_t bh[4];
                ldsm_x4(bh[0], bh[1], bh[2], bh[3], addr);
#pragma unroll
                for (int mi = 0; mi < 4; mi++)
#pragma unroll
                    for (int q = 0; q < 2; q++)
                        mma_fp16(acc[mi][nh * 2 + q], ah[mi], bh[q * 2], bh[q * 2 + 1]);
            }
        }
    }

    // ---------------- epilogue -------------------------------------------
    const int wnb = n0 + wn * 32;
    if (MODE == 0) {
        const int sIdx = wnb >> 10;
        const int h    = (wnb >> 6) & 15;
        const int dby  = (wnb & 63);                  // 0 or 32
        __half* dst = (sIdx == 0) ? g_q_h : (sIdx == 1) ? g_k_h : g_v_h;
#pragma unroll
        for (int mi = 0; mi < 4; mi++)
#pragma unroll
            for (int half = 0; half < 2; half++) {
                int row = m0 + wm * 64 + mi * 16 + (lane >> 2) + half * 8;
                int b = row >> 10, l = row & 1023;
                size_t rbase = ((size_t)(b * H_ + h) * L_ + l) * HD;
#pragma unroll
                for (int ni = 0; ni < 4; ni++) {
                    int d = dby + ni * 8 + (lane & 3) * 2;
                    __half2 hv = __floats2half2_rn(acc[mi][ni][half * 2],
                                                   acc[mi][ni][half * 2 + 1]);
                    *(__half2*)&dst[rbase + d] = hv;
                }
            }
    } else {
#pragma unroll
        for (int mi = 0; mi < 4; mi++)
#pragma unroll
            for (int half = 0; half < 2; half++) {
                int row = m0 + wm * 64 + mi * 16 + (lane >> 2) + half * 8;
#pragma unroll
                for (int ni = 0; ni < 4; ni++) {
                    int n = wnb + ni * 8 + (lane & 3) * 2;
                    *(float2*)&C[(size_t)row * 1024 + n] =
                        make_float2(acc[mi][ni][half * 2], acc[mi][ni][half * 2 + 1]);
                }
            }
    }
#undef LOAD_STAGE
}

// ---------------------------------------------------------------------------
// Flash attention (R13, unchanged): CTA = (b,h) x 128-query tile, 8 warps,
// warp owns 16 rows end-to-end, online softmax, P in registers.
// ---------------------------------------------------------------------------
#define FA_Q    0
#define FA_K0   16384
#define FA_V0   24576
#define FA_K1   32768
#define FA_V1   40960
#define FA_R    49152
#define FA_QE   65536
#define FA_SMEM (65536 + 40960)   // 106496
#define QEP 80

__device__ __forceinline__ void fa_tile64(uint32_t dst, const __half* g,
                                          int rowbase, int t) {
#pragma unroll
    for (int j = 0; j < 2; j++) {
        int c = t + 256 * j;
        int row = c >> 3, ch = c & 7;
        uint32_t so = (uint32_t)(row * 128 + ((ch ^ (row & 7)) << 4));
        CP_ASYNC16(dst + so, g + (size_t)(rowbase + row) * 64 + ch * 8);
    }
}

__global__ void __launch_bounds__(256, 2) attn_flash(const float* __restrict__ rel_emb) {
    extern __shared__ char smc[];
    uint32_t sb = smem_u32(smc);
    float* qEf = (float*)(smc + FA_QE);

    const int t = threadIdx.x, lane = t & 31, warp = t >> 5;
    const int qt0 = blockIdx.x * 128;
    const int bh  = blockIdx.y;
    const int rowbase = (warp >> 2) * 64 + (warp & 3) * 16;
    const __half* gq = g_q_h + (size_t)bh * L_ * HD;
    const __half* gk = g_k_h + (size_t)bh * L_ * HD;
    const __half* gv = g_v_h + (size_t)bh * L_ * HD;

    const int a_rb = rowbase + (lane & 15);
    const int a_cb = (lane >> 4);

    int first_kb = 4 - 2 * (int)blockIdx.x;
    if (first_kb < 0) first_kb = 0;

    // ---------- phase 0 ----------------------------------------------------
    {
#pragma unroll
        for (int j = 0; j < 4; j++) {
            int c = t + 256 * j;
            int row = c >> 3, ch = c & 7;
            uint32_t so = (uint32_t)(row * 128 + ((ch ^ (row & 7)) << 4));
            CP_ASYNC16(sb + FA_Q + so, gq + (size_t)(qt0 + row) * 64 + ch * 8);
        }
        CP_COMMIT();
    }
    {
        int kb0 = qt0 - 256 + first_kb * 64;
        fa_tile64(sb + FA_K0, gk, kb0, t);
        fa_tile64(sb + FA_V0, gv, kb0, t);
        CP_COMMIT();
    }
    for (int i = t; i < 63 * 8; i += 256) {
        int row = 65 + (i >> 3), ch = i & 7;
        *(uint4*)(smc + FA_R + row * 128 + ch * 16) = make_uint4(0, 0, 0, 0);
    }
    for (int idx = t; idx < 65 * 16; idx += 256) {
        int r = idx >> 4, c4 = idx & 15;
        float4 v = *(const float4*)&rel_emb[r * HD + c4 * 4];
        *(uint2*)(smc + FA_R + sw_off4(r, c4)) = f4_to_h4(v);
    }
    CP_WAIT1();
    __syncthreads();

    // ---------- phase 1: qE = Q * R^T (warp m16 x n80) ---------------------
    {
        float qa[10][4];
#pragma unroll
        for (int ni = 0; ni < 10; ni++)
#pragma unroll
            for (int e = 0; e < 4; e++) qa[ni][e] = 0.f;
#pragma unroll
        for (int kk = 0; kk < 4; kk++) {
            uint32_t ah[4];
            {
                int r = a_rb, c = kk * 2 + a_cb;
                ldsm_x4(ah[0], ah[1], ah[2], ah[3],
                        sb + FA_Q + (uint32_t)(r * 128 + ((c ^ (r & 7)) << 4)));
            }
#pragma unroll
            for (int g = 0; g < 5; g++) {
                int r = g * 16 + ((lane >> 4) * 8) + (lane & 7);
                int c = kk * 2 + ((lane >> 3) & 1);
                uint32_t bhf[4];
                ldsm_x4(bhf[0], bhf[1], bhf[2], bhf[3],
                        sb + FA_R + (uint32_t)(r * 128 + ((c ^ (r & 7)) << 4)));
                mma_fp16(qa[g * 2], ah, bhf[0], bhf[1]);
                mma_fp16(qa[g * 2 + 1], ah, bhf[2], bhf[3]);
            }
        }
#pragma unroll
        for (int ni = 0; ni < 10; ni++)
#pragma unroll
            for (int half = 0; half < 2; half++) {
                int row = rowbase + (lane >> 2) + half * 8;
                int col = ni * 8 + (lane & 3) * 2;
                qEf[row * QEP + col]     = qa[ni][half * 2];
                qEf[row * QEP + col + 1] = qa[ni][half * 2 + 1];
            }
        __syncwarp();
    }

    // ---------- main loop --------------------------------------------------
    float oac[8][4];
#pragma unroll
    for (int ni = 0; ni < 8; ni++)
#pragma unroll
        for (int e = 0; e < 4; e++) oac[ni][e] = 0.f;
    float mrow[2] = {-1e30f, -1e30f};
    float srow[2] = {0.f, 0.f};

    const int qb = qt0 + rowbase;

    for (int kbk = first_kb; kbk < 6; kbk++) {
        int kb0 = qt0 - 256 + kbk * 64;
        int bufi = (kbk - first_kb) & 1;
        uint32_t kbase = sb + FA_K0 + bufi * 16384;

        CP_WAIT0();
        __syncthreads();
        if (kbk < 5) {
            fa_tile64(sb + FA_K0 + (1 - bufi) * 16384, gk, kb0 + 64, t);
            fa_tile64(sb + FA_V0 + (1 - bufi) * 16384, gv, kb0 + 64, t);
            CP_COMMIT();
        }

        if (kb0 > qb + 15 || kb0 + 63 <= qb - 256) continue;

        float sc[8][4];
#pragma unroll
        for (int ni = 0; ni < 8; ni++)
#pragma unroll
            for (int e = 0; e < 4; e++) sc[ni][e] = 0.f;
#pragma unroll
        for (int kk = 0; kk < 4; kk++) {
            uint32_t ah[4];
            {
                int r = a_rb, c = kk * 2 + a_cb;
                ldsm_x4(ah[0], ah[1], ah[2], ah[3],
                        sb + FA_Q + (uint32_t)(r * 128 + ((c ^ (r & 7)) << 4)));
            }
#pragma unroll
            for (int g = 0; g < 4; g++) {
                int r = g * 16 + ((lane >> 4) * 8) + (lane & 7);
                int c = kk * 2 + ((lane >> 3) & 1);
                uint32_t bhf[4];
                ldsm_x4(bhf[0], bhf[1], bhf[2], bhf[3],
                        kbase + (uint32_t)(r * 128 + ((c ^ (r & 7)) << 4)));
                mma_fp16(sc[g * 2], ah, bhf[0], bhf[1]);
                mma_fp16(sc[g * 2 + 1], ah, bhf[2], bhf[3]);
            }
        }

        uint32_t pa[4][4];
#pragma unroll
        for (int h = 0; h < 2; h++) {
            int rl = rowbase + (lane >> 2) + h * 8;
            int i  = qt0 + rl;
            float mx = -1e30f;
#pragma unroll
            for (int ni = 0; ni < 8; ni++)
#pragma unroll
                for (int dd = 0; dd < 2; dd++) {
                    int j = kb0 + ni * 8 + (lane & 3) * 2 + dd;
                    float v;
                    if (j > i || i - j >= 256) {
                        v = -1e30f;
                    } else {
                        int rel = j - i + 64;
                        if (rel < 0) rel = 0;
                        v = (sc[ni][h * 2 + dd] + qEf[rl * QEP + rel]) * 0.125f;
                    }
                    sc[ni][h * 2 + dd] = v;
                    mx = fmaxf(mx, v);
                }
            mx = fmaxf(mx, __shfl_xor_sync(0xffffffffu, mx, 1));
            mx = fmaxf(mx, __shfl_xor_sync(0xffffffffu, mx, 2));
            bool valid = mx > -0.5e30f;
            float mn = valid ? fmaxf(mrow[h], mx) : mrow[h];
            float corr = valid ? __expf(mrow[h] - mn) : 1.f;
            float rs = 0.f;
#pragma unroll
            for (int ni = 0; ni < 8; ni++)
#pragma unroll
                for (int dd = 0; dd < 2; dd++) {
                    float p = __expf(sc[ni][h * 2 + dd] - mn);
                    p = valid ? p : 0.f;
                    sc[ni][h * 2 + dd] = p;
                    rs += p;
                }
            rs += __shfl_xor_sync(0xffffffffu, rs, 1);
            rs += __shfl_xor_sync(0xffffffffu, rs, 2);
            srow[h] = srow[h] * corr + rs;
            mrow[h] = mn;
#pragma unroll
            for (int ni = 0; ni < 8; ni++) {
                oac[ni][h * 2]     *= corr;
                oac[ni][h * 2 + 1] *= corr;
            }
        }

#pragma unroll
        for (int kk = 0; kk < 4; kk++) {
            pa[kk][0] = f2_to_h2(sc[2 * kk][0],     sc[2 * kk][1]);
            pa[kk][1] = f2_to_h2(sc[2 * kk][2],     sc[2 * kk][3]);
            pa[kk][2] = f2_to_h2(sc[2 * kk + 1][0], sc[2 * kk + 1][1]);
            pa[kk][3] = f2_to_h2(sc[2 * kk + 1][2], sc[2 * kk + 1][3]);
        }

#pragma unroll
        for (int kk = 0; kk < 4; kk++) {
#pragma unroll
            for (int dch = 0; dch < 4; dch++) {
                int vrow = kk * 16 + (lane & 7) + ((lane >> 3) & 1) * 8;
                int vch  = dch * 2 + (lane >> 4);
                uint32_t bhf[4];
                ldsm_x4_t(bhf[0], bhf[1], bhf[2], bhf[3],
                          kbase + 8192 +
                          (uint32_t)(vrow * 128 + ((vch ^ (vrow & 7)) << 4)));
                mma_fp16(oac[dch * 2],     pa[kk], bhf[0], bhf[1]);
                mma_fp16(oac[dch * 2 + 1], pa[kk], bhf[2], bhf[3]);
            }
        }
    }

    // ---------- epilogue ---------------------------------------------------
    {
        int b = bh >> 4, hh = bh & 15;
#pragma unroll
        for (int h = 0; h < 2; h++) {
            float inv = 1.f / srow[h];
            int i = qt0 + rowbase + (lane >> 2) + h * 8;
#pragma unroll
            for (int ni = 0; ni < 8; ni++) {
                int d = ni * 8 + (lane & 3) * 2;
                __half2 hv = __floats2half2_rn(oac[ni][h * 2] * inv,
                                               oac[ni][h * 2 + 1] * inv);
                size_t off = ((size_t)(b * L_ + i) * H_ + hh) * HD + d;
                *(__half2*)&g_att_h[off] = hv;
            }
        }
    }
}

// ---------------------------------------------------------------------------
extern "C" void kernel_launch(void* const* d_in, const int* in_sizes, int n_in,
                              void* d_out, int out_size) {
    const float* x       = (const float*)d_in[0];
    const float* w_qkv   = (const float*)d_in[1];
    const float* w_out   = (const float*)d_in[2];
    const float* rel_emb = (const float*)d_in[3];
    float* out = (float*)d_out;

    (void)in_sizes; (void)n_in; (void)out_size;

    cudaFuncSetAttribute(attn_flash,
                         cudaFuncAttributeMaxDynamicSharedMemorySize, FA_SMEM);
    cudaFuncSetAttribute(tc_gemm<0>,
                         cudaFuncAttributeMaxDynamicSharedMemorySize, TC_SMEM);
    cudaFuncSetAttribute(tc_gemm<1>,
                         cudaFuncAttributeMaxDynamicSharedMemorySize, TC_SMEM);

    cvt_h<0><<<(B_ * L_ * D_ / 4 + 255) / 256, 256>>>(x,    B_ * L_ * D_ / 4);
    cvt_h<1><<<(3 * D_ * D_ / 4 + 255) / 256, 256>>>(w_qkv, 3 * D_ * D_ / 4);
    cvt_h<2><<<(D_ * D_ / 4 + 255) / 256, 256>>>(w_out,     D_ * D_ / 4);

    tc_gemm<0><<<dim3(3072 / 128, 4096 / 128), 256, TC_SMEM>>>(nullptr);

    attn_flash<<<dim3(L_ / 128, NBH), 256, FA_SMEM>>>(rel_emb);

    tc_gemm<1><<<dim3(1024 / 128, 4096 / 128), 256, TC_SMEM>>>(out);
}

// round 15
// speedup vs baseline: 7.6845x; 1.0886x over previous
#include <cuda_runtime.h>
#include <cuda_fp16.h>
#include <cstdint>

#define B_  4
#define L_  1024
#define D_  1024
#define H_  16
#define HD  64
#define NBH (B_ * H_)   // 64

// ---------------------------------------------------------------------------
// Static device scratch (no allocation allowed) — single fp16 everywhere
// ---------------------------------------------------------------------------
__device__ __half g_q_h[NBH * L_ * HD];
__device__ __half g_k_h[NBH * L_ * HD];
__device__ __half g_v_h[NBH * L_ * HD];

__device__ __half g_x_h[B_ * L_ * D_];
__device__ __half g_wqkv_h[3 * D_ * D_];
__device__ __half g_wout_h[D_ * D_];
__device__ __half g_att_h[B_ * L_ * D_];

// ---------------------------------------------------------------------------
// PTX helpers (base ISA only)
// ---------------------------------------------------------------------------
__device__ __forceinline__ uint32_t smem_u32(const void* p) {
    uint32_t a;
    asm("{ .reg .u64 t; cvta.to.shared.u64 t, %1; cvt.u32.u64 %0, t; }" : "=r"(a) : "l"(p));
    return a;
}

#define CP_ASYNC16(dst, src) \
    asm volatile("cp.async.cg.shared.global [%0], [%1], 16;" :: "r"(dst), "l"(src))
#define CP_COMMIT() asm volatile("cp.async.commit_group;" ::: "memory")
#define CP_WAIT0()  asm volatile("cp.async.wait_group 0;" ::: "memory")
#define CP_WAIT1()  asm volatile("cp.async.wait_group 1;" ::: "memory")

__device__ __forceinline__ void ldsm_x4(uint32_t& r0, uint32_t& r1, uint32_t& r2,
                                        uint32_t& r3, uint32_t addr) {
    asm volatile("ldmatrix.sync.aligned.m8n8.x4.shared.b16 {%0,%1,%2,%3}, [%4];"
                 : "=r"(r0), "=r"(r1), "=r"(r2), "=r"(r3) : "r"(addr));
}
__device__ __forceinline__ void ldsm_x4_t(uint32_t& r0, uint32_t& r1, uint32_t& r2,
                                          uint32_t& r3, uint32_t addr) {
    asm volatile("ldmatrix.sync.aligned.m8n8.x4.trans.shared.b16 {%0,%1,%2,%3}, [%4];"
                 : "=r"(r0), "=r"(r1), "=r"(r2), "=r"(r3) : "r"(addr));
}

__device__ __forceinline__ void mma_fp16(float* d, const uint32_t* a,
                                         uint32_t b0, uint32_t b1) {
    asm volatile(
        "mma.sync.aligned.m16n8k16.row.col.f32.f16.f16.f32 "
        "{%0,%1,%2,%3}, {%4,%5,%6,%7}, {%8,%9}, {%0,%1,%2,%3};"
        : "+f"(d[0]), "+f"(d[1]), "+f"(d[2]), "+f"(d[3])
        : "r"(a[0]), "r"(a[1]), "r"(a[2]), "r"(a[3]), "r"(b0), "r"(b1));
}

// fp32x4 -> packed fp16x4
__device__ __forceinline__ uint2 f4_to_h4(float4 v) {
    __half2 a = __floats2half2_rn(v.x, v.y);
    __half2 b = __floats2half2_rn(v.z, v.w);
    return make_uint2(*(uint32_t*)&a, *(uint32_t*)&b);
}
__device__ __forceinline__ uint32_t f2_to_h2(float a, float b) {
    __half2 h = __floats2half2_rn(a, b);
    return *(uint32_t*)&h;
}

// swizzled byte offset of float4-chunk c4 in a 128B-row 16-bit tile
__device__ __forceinline__ uint32_t sw_off4(int row, int c4) {
    return (uint32_t)(row * 128 + ((((c4 >> 1) ^ (row & 7)) << 4) | ((c4 & 1) << 3)));
}

// ---------------------------------------------------------------------------
// Merged fp32 -> fp16 conversion for x | w_qkv | w_out (one launch)
// ---------------------------------------------------------------------------
#define NX_CH (B_ * L_ * D_ / 4)      // 1048576
#define NW_CH (3 * D_ * D_ / 4)       //  786432
#define NO_CH (D_ * D_ / 4)           //  262144
#define CVT_CH (NX_CH + NW_CH + NO_CH)

__global__ void __launch_bounds__(256) cvt_all(const float* __restrict__ x,
                                               const float* __restrict__ wqkv,
                                               const float* __restrict__ wout) {
    int i = blockIdx.x * 256 + threadIdx.x;
    if (i < NX_CH) {
        ((uint2*)g_x_h)[i] = f4_to_h4(((const float4*)x)[i]);
    } else if (i < NX_CH + NW_CH) {
        int j = i - NX_CH;
        ((uint2*)g_wqkv_h)[j] = f4_to_h4(((const float4*)wqkv)[j]);
    } else if (i < CVT_CH) {
        int j = i - NX_CH - NW_CH;
        ((uint2*)g_wout_h)[j] = f4_to_h4(((const float4*)wout)[j]);
    }
}

// ---------------------------------------------------------------------------
// Warp-mma fp16 GEMM NT v6: CTA 128x128, 256 thr, warp 64x32, 2 CTAs/SM,
// THREE-stage cp.async pipeline (loads get 2 compute iters of slack).
// MODE 0: A=x, B=w_qkv -> scatter fp16 q/k/v.  MODE 1: A=att -> C fp32.
// ---------------------------------------------------------------------------
#define AT_B  16384
#define GBT_B 16384
#define STG_B (AT_B + GBT_B)        // 32768 per stage
#define TC_SMEM (3 * STG_B)         // 98304; 2 CTAs = 192K <= 227K

template <int MODE>
__global__ void __launch_bounds__(256, 2) tc_gemm(float* __restrict__ C) {
    extern __shared__ char smc[];
    uint32_t sb = smem_u32(smc);

    const __half* A  = (MODE == 0) ? g_x_h : g_att_h;
    const __half* Bp = (MODE == 0) ? g_wqkv_h : g_wout_h;

    const int t = threadIdx.x, lane = t & 31, warp = t >> 5;
    const int wm = warp & 1, wn = warp >> 1;
    const int m0 = blockIdx.y * 128, n0 = blockIdx.x * 128;

    float acc[4][4][4];
#pragma unroll
    for (int mi = 0; mi < 4; mi++)
#pragma unroll
        for (int ni = 0; ni < 4; ni++)
#pragma unroll
            for (int e = 0; e < 4; e++) acc[mi][ni][e] = 0.f;

    const int a_rb = wm * 64 + (lane & 15);
    const int a_cb = (lane >> 4);
    const int b_rb = wn * 32 + ((lane >> 4) * 8) + (lane & 7);
    const int b_cb = (lane >> 3) & 1;

#define LOAD_STAGE(it, s) do {                                                   \
    uint32_t base = sb + (s) * STG_B;                                            \
    int k0 = (it) * 64;                                                          \
    _Pragma("unroll")                                                            \
    for (int j = 0; j < 4; j++) {                                                \
        int c = t + 256 * j;                                                     \
        int row = c >> 3, ch = c & 7;                                            \
        uint32_t so = (uint32_t)(row * 128 + ((ch ^ (row & 7)) << 4));           \
        CP_ASYNC16(base + so, A + (size_t)(m0 + row) * 1024 + ch * 8 + k0);      \
        CP_ASYNC16(base + AT_B + so, Bp + (size_t)(n0 + row) * 1024 + ch * 8 + k0); \
    }                                                                            \
    CP_COMMIT();                                                                 \
} while (0)

    LOAD_STAGE(0, 0);
    LOAD_STAGE(1, 1);

    for (int it = 0; it < 16; it++) {
        int s = it % 3;
        if (it == 15) CP_WAIT0(); else CP_WAIT1();   // stage `it` complete
        __syncthreads();                             // visible; buf (it+2)%3 free
        if (it + 2 < 16) LOAD_STAGE(it + 2, (it + 2) % 3);
        uint32_t base = sb + s * STG_B;

#pragma unroll
        for (int kk = 0; kk < 4; kk++) {
            uint32_t ah[4][4];
#pragma unroll
            for (int mi = 0; mi < 4; mi++) {
                int r = a_rb + mi * 16;
                int c2 = kk * 2 + a_cb;
                uint32_t addr = base + (uint32_t)(r * 128 + ((c2 ^ (r & 7)) << 4));
                ldsm_x4(ah[mi][0], ah[mi][1], ah[mi][2], ah[mi][3], addr);
            }
#pragma unroll
            for (int nh = 0; nh < 2; nh++) {
                int r = b_rb + nh * 16;
                int c2 = kk * 2 + b_cb;
                uint32_t addr = base + AT_B
                              + (uint32_t)(r * 128 + ((c2 ^ (r & 7)) << 4));
                uint32_t bh[4];
                ldsm_x4(bh[0], bh[1], bh[2], bh[3], addr);
#pragma unroll
                for (int mi = 0; mi < 4; mi++)
#pragma unroll
                    for (int q = 0; q < 2; q++)
                        mma_fp16(acc[mi][nh * 2 + q], ah[mi], bh[q * 2], bh[q * 2 + 1]);
            }
        }
    }

    // ---------------- epilogue -------------------------------------------
    const int wnb = n0 + wn * 32;
    if (MODE == 0) {
        const int sIdx = wnb >> 10;
        const int h    = (wnb >> 6) & 15;
        const int dby  = (wnb & 63);
        __half* dst = (sIdx == 0) ? g_q_h : (sIdx == 1) ? g_k_h : g_v_h;
#pragma unroll
        for (int mi = 0; mi < 4; mi++)
#pragma unroll
            for (int half = 0; half < 2; half++) {
                int row = m0 + wm * 64 + mi * 16 + (lane >> 2) + half * 8;
                int b = row >> 10, l = row & 1023;
                size_t rbase = ((size_t)(b * H_ + h) * L_ + l) * HD;
#pragma unroll
                for (int ni = 0; ni < 4; ni++) {
                    int d = dby + ni * 8 + (lane & 3) * 2;
                    __half2 hv = __floats2half2_rn(acc[mi][ni][half * 2],
                                                   acc[mi][ni][half * 2 + 1]);
                    *(__half2*)&dst[rbase + d] = hv;
                }
            }
    } else {
#pragma unroll
        for (int mi = 0; mi < 4; mi++)
#pragma unroll
            for (int half = 0; half < 2; half++) {
                int row = m0 + wm * 64 + mi * 16 + (lane >> 2) + half * 8;
#pragma unroll
                for (int ni = 0; ni < 4; ni++) {
                    int n = wnb + ni * 8 + (lane & 3) * 2;
                    *(float2*)&C[(size_t)row * 1024 + n] =
                        make_float2(acc[mi][ni][half * 2], acc[mi][ni][half * 2 + 1]);
                }
            }
    }
#undef LOAD_STAGE
}

// ---------------------------------------------------------------------------
// Flash attention (R13 core + interior-block fast path)
// ---------------------------------------------------------------------------
#define FA_Q    0
#define FA_K0   16384
#define FA_V0   24576
#define FA_K1   32768
#define FA_V1   40960
#define FA_R    49152
#define FA_QE   65536
#define FA_SMEM (65536 + 40960)   // 106496
#define QEP 80

__device__ __forceinline__ void fa_tile64(uint32_t dst, const __half* g,
                                          int rowbase, int t) {
#pragma unroll
    for (int j = 0; j < 2; j++) {
        int c = t + 256 * j;
        int row = c >> 3, ch = c & 7;
        uint32_t so = (uint32_t)(row * 128 + ((ch ^ (row & 7)) << 4));
        CP_ASYNC16(dst + so, g + (size_t)(rowbase + row) * 64 + ch * 8);
    }
}

__global__ void __launch_bounds__(256, 2) attn_flash(const float* __restrict__ rel_emb) {
    extern __shared__ char smc[];
    uint32_t sb = smem_u32(smc);
    float* qEf = (float*)(smc + FA_QE);

    const int t = threadIdx.x, lane = t & 31, warp = t >> 5;
    const int qt0 = blockIdx.x * 128;
    const int bh  = blockIdx.y;
    const int rowbase = (warp >> 2) * 64 + (warp & 3) * 16;
    const __half* gq = g_q_h + (size_t)bh * L_ * HD;
    const __half* gk = g_k_h + (size_t)bh * L_ * HD;
    const __half* gv = g_v_h + (size_t)bh * L_ * HD;

    const int a_rb = rowbase + (lane & 15);
    const int a_cb = (lane >> 4);

    int first_kb = 4 - 2 * (int)blockIdx.x;
    if (first_kb < 0) first_kb = 0;

    // ---------- phase 0 ----------------------------------------------------
    {
#pragma unroll
        for (int j = 0; j < 4; j++) {
            int c = t + 256 * j;
            int row = c >> 3, ch = c & 7;
            uint32_t so = (uint32_t)(row * 128 + ((ch ^ (row & 7)) << 4));
            CP_ASYNC16(sb + FA_Q + so, gq + (size_t)(qt0 + row) * 64 + ch * 8);
        }
        CP_COMMIT();
    }
    {
        int kb0 = qt0 - 256 + first_kb * 64;
        fa_tile64(sb + FA_K0, gk, kb0, t);
        fa_tile64(sb + FA_V0, gv, kb0, t);
        CP_COMMIT();
    }
    for (int i = t; i < 63 * 8; i += 256) {
        int row = 65 + (i >> 3), ch = i & 7;
        *(uint4*)(smc + FA_R + row * 128 + ch * 16) = make_uint4(0, 0, 0, 0);
    }
    for (int idx = t; idx < 65 * 16; idx += 256) {
        int r = idx >> 4, c4 = idx & 15;
        float4 v = *(const float4*)&rel_emb[r * HD + c4 * 4];
        *(uint2*)(smc + FA_R + sw_off4(r, c4)) = f4_to_h4(v);
    }
    CP_WAIT1();
    __syncthreads();

    // ---------- phase 1: qE = Q * R^T (warp m16 x n80) ---------------------
    {
        float qa[10][4];
#pragma unroll
        for (int ni = 0; ni < 10; ni++)
#pragma unroll
            for (int e = 0; e < 4; e++) qa[ni][e] = 0.f;
#pragma unroll
        for (int kk = 0; kk < 4; kk++) {
            uint32_t ah[4];
            {
                int r = a_rb, c = kk * 2 + a_cb;
                ldsm_x4(ah[0], ah[1], ah[2], ah[3],
                        sb + FA_Q + (uint32_t)(r * 128 + ((c ^ (r & 7)) << 4)));
            }
#pragma unroll
            for (int g = 0; g < 5; g++) {
                int r = g * 16 + ((lane >> 4) * 8) + (lane & 7);
                int c = kk * 2 + ((lane >> 3) & 1);
                uint32_t bhf[4];
                ldsm_x4(bhf[0], bhf[1], bhf[2], bhf[3],
                        sb + FA_R + (uint32_t)(r * 128 + ((c ^ (r & 7)) << 4)));
                mma_fp16(qa[g * 2], ah, bhf[0], bhf[1]);
                mma_fp16(qa[g * 2 + 1], ah, bhf[2], bhf[3]);
            }
        }
#pragma unroll
        for (int ni = 0; ni < 10; ni++)
#pragma unroll
            for (int half = 0; half < 2; half++) {
                int row = rowbase + (lane >> 2) + half * 8;
                int col = ni * 8 + (lane & 3) * 2;
                qEf[row * QEP + col]     = qa[ni][half * 2];
                qEf[row * QEP + col + 1] = qa[ni][half * 2 + 1];
            }
        __syncwarp();
    }

    // ---------- main loop --------------------------------------------------
    float oac[8][4];
#pragma unroll
    for (int ni = 0; ni < 8; ni++)
#pragma unroll
        for (int e = 0; e < 4; e++) oac[ni][e] = 0.f;
    float mrow[2] = {-1e30f, -1e30f};
    float srow[2] = {0.f, 0.f};

    const int qb = qt0 + rowbase;

    for (int kbk = first_kb; kbk < 6; kbk++) {
        int kb0 = qt0 - 256 + kbk * 64;
        int bufi = (kbk - first_kb) & 1;
        uint32_t kbase = sb + FA_K0 + bufi * 16384;

        CP_WAIT0();
        __syncthreads();
        if (kbk < 5) {
            fa_tile64(sb + FA_K0 + (1 - bufi) * 16384, gk, kb0 + 64, t);
            fa_tile64(sb + FA_V0 + (1 - bufi) * 16384, gv, kb0 + 64, t);
            CP_COMMIT();
        }

        if (kb0 > qb + 15 || kb0 + 63 <= qb - 256) continue;

        float sc[8][4];
#pragma unroll
        for (int ni = 0; ni < 8; ni++)
#pragma unroll
            for (int e = 0; e < 4; e++) sc[ni][e] = 0.f;
#pragma unroll
        for (int kk = 0; kk < 4; kk++) {
            uint32_t ah[4];
            {
                int r = a_rb, c = kk * 2 + a_cb;
                ldsm_x4(ah[0], ah[1], ah[2], ah[3],
                        sb + FA_Q + (uint32_t)(r * 128 + ((c ^ (r & 7)) << 4)));
            }
#pragma unroll
            for (int g = 0; g < 4; g++) {
                int r = g * 16 + ((lane >> 4) * 8) + (lane & 7);
                int c = kk * 2 + ((lane >> 3) & 1);
                uint32_t bhf[4];
                ldsm_x4(bhf[0], bhf[1], bhf[2], bhf[3],
                        kbase + (uint32_t)(r * 128 + ((c ^ (r & 7)) << 4)));
                mma_fp16(sc[g * 2], ah, bhf[0], bhf[1]);
                mma_fp16(sc[g * 2 + 1], ah, bhf[2], bhf[3]);
            }
        }

        // interior block for this warp: no masking possible for any of its rows
        const bool interior = (kb0 + 63 <= qb) && (qb + 15 - kb0 < 256);

        uint32_t pa[4][4];
#pragma unroll
        for (int h = 0; h < 2; h++) {
            int rl = rowbase + (lane >> 2) + h * 8;
            int i  = qt0 + rl;
            float mx = -1e30f;
            if (interior) {
#pragma unroll
                for (int ni = 0; ni < 8; ni++)
#pragma unroll
                    for (int dd = 0; dd < 2; dd++) {
                        int j = kb0 + ni * 8 + (lane & 3) * 2 + dd;
                        int rel = j - i + 64;
                        if (rel < 0) rel = 0;
                        float v = (sc[ni][h * 2 + dd] + qEf[rl * QEP + rel]) * 0.125f;
                        sc[ni][h * 2 + dd] = v;
                        mx = fmaxf(mx, v);
                    }
                mx = fmaxf(mx, __shfl_xor_sync(0xffffffffu, mx, 1));
                mx = fmaxf(mx, __shfl_xor_sync(0xffffffffu, mx, 2));
                float mn = fmaxf(mrow[h], mx);
                float corr = __expf(mrow[h] - mn);
                float rs = 0.f;
#pragma unroll
                for (int ni = 0; ni < 8; ni++)
#pragma unroll
                    for (int dd = 0; dd < 2; dd++) {
                        float p = __expf(sc[ni][h * 2 + dd] - mn);
                        sc[ni][h * 2 + dd] = p;
                        rs += p;
                    }
                rs += __shfl_xor_sync(0xffffffffu, rs, 1);
                rs += __shfl_xor_sync(0xffffffffu, rs, 2);
                srow[h] = srow[h] * corr + rs;
                mrow[h] = mn;
#pragma unroll
                for (int ni = 0; ni < 8; ni++) {
                    oac[ni][h * 2]     *= corr;
                    oac[ni][h * 2 + 1] *= corr;
                }
            } else {
#pragma unroll
                for (int ni = 0; ni < 8; ni++)
#pragma unroll
                    for (int dd = 0; dd < 2; dd++) {
                        int j = kb0 + ni * 8 + (lane & 3) * 2 + dd;
                        float v;
                        if (j > i || i - j >= 256) {
                            v = -1e30f;
                        } else {
                            int rel = j - i + 64;
                            if (rel < 0) rel = 0;
                            v = (sc[ni][h * 2 + dd] + qEf[rl * QEP + rel]) * 0.125f;
                        }
                        sc[ni][h * 2 + dd] = v;
                        mx = fmaxf(mx, v);
                    }
                mx = fmaxf(mx, __shfl_xor_sync(0xffffffffu, mx, 1));
                mx = fmaxf(mx, __shfl_xor_sync(0xffffffffu, mx, 2));
                bool valid = mx > -0.5e30f;
                float mn = valid ? fmaxf(mrow[h], mx) : mrow[h];
                float corr = valid ? __expf(mrow[h] - mn) : 1.f;
                float rs = 0.f;
#pragma unroll
                for (int ni = 0; ni < 8; ni++)
#pragma unroll
                    for (int dd = 0; dd < 2; dd++) {
                        float p = __expf(sc[ni][h * 2 + dd] - mn);
                        p = valid ? p : 0.f;
                        sc[ni][h * 2 + dd] = p;
                        rs += p;
                    }
                rs += __shfl_xor_sync(0xffffffffu, rs, 1);
                rs += __shfl_xor_sync(0xffffffffu, rs, 2);
                srow[h] = srow[h] * corr + rs;
                mrow[h] = mn;
#pragma unroll
                for (int ni = 0; ni < 8; ni++) {
                    oac[ni][h * 2]     *= corr;
                    oac[ni][h * 2 + 1] *= corr;
                }
            }
        }

#pragma unroll
        for (int kk = 0; kk < 4; kk++) {
            pa[kk][0] = f2_to_h2(sc[2 * kk][0],     sc[2 * kk][1]);
            pa[kk][1] = f2_to_h2(sc[2 * kk][2],     sc[2 * kk][3]);
            pa[kk][2] = f2_to_h2(sc[2 * kk + 1][0], sc[2 * kk + 1][1]);
            pa[kk][3] = f2_to_h2(sc[2 * kk + 1][2], sc[2 * kk + 1][3]);
        }

#pragma unroll
        for (int kk = 0; kk < 4; kk++) {
#pragma unroll
            for (int dch = 0; dch < 4; dch++) {
                int vrow = kk * 16 + (lane & 7) + ((lane >> 3) & 1) * 8;
                int vch  = dch * 2 + (lane >> 4);
                uint32_t bhf[4];
                ldsm_x4_t(bhf[0], bhf[1], bhf[2], bhf[3],
                          kbase + 8192 +
                          (uint32_t)(vrow * 128 + ((vch ^ (vrow & 7)) << 4)));
                mma_fp16(oac[dch * 2],     pa[kk], bhf[0], bhf[1]);
                mma_fp16(oac[dch * 2 + 1], pa[kk], bhf[2], bhf[3]);
            }
        }
    }

    // ---------- epilogue ---------------------------------------------------
    {
        int b = bh >> 4, hh = bh & 15;
#pragma unroll
        for (int h = 0; h < 2; h++) {
            float inv = 1.f / srow[h];
            int i = qt0 + rowbase + (lane >> 2) + h * 8;
#pragma unroll
            for (int ni = 0; ni < 8; ni++) {
                int d = ni * 8 + (lane & 3) * 2;
                __half2 hv = __floats2half2_rn(oac[ni][h * 2] * inv,
                                               oac[ni][h * 2 + 1] * inv);
                size_t off = ((size_t)(b * L_ + i) * H_ + hh) * HD + d;
                *(__half2*)&g_att_h[off] = hv;
            }
        }
    }
}

// ---------------------------------------------------------------------------
extern "C" void kernel_launch(void* const* d_in, const int* in_sizes, int n_in,
                              void* d_out, int out_size) {
    const float* x       = (const float*)d_in[0];
    const float* w_qkv   = (const float*)d_in[1];
    const float* w_out   = (const float*)d_in[2];
    const float* rel_emb = (const float*)d_in[3];
    float* out = (float*)d_out;

    (void)in_sizes; (void)n_in; (void)out_size;

    cudaFuncSetAttribute(attn_flash,
                         cudaFuncAttributeMaxDynamicSharedMemorySize, FA_SMEM);
    cudaFuncSetAttribute(tc_gemm<0>,
                         cudaFuncAttributeMaxDynamicSharedMemorySize, TC_SMEM);
    cudaFuncSetAttribute(tc_gemm<1>,
                         cudaFuncAttributeMaxDynamicSharedMemorySize, TC_SMEM);

    cvt_all<<<CVT_CH / 256, 256>>>(x, w_qkv, w_out);

    tc_gemm<0><<<dim3(3072 / 128, 4096 / 128), 256, TC_SMEM>>>(nullptr);

    attn_flash<<<dim3(L_ / 128, NBH), 256, FA_SMEM>>>(rel_emb);

    tc_gemm<1><<<dim3(1024 / 128, 4096 / 128), 256, TC_SMEM>>>(out);
}